// round 1
// baseline (speedup 1.0000x reference)
#include <cuda_runtime.h>
#include <math.h>

#define Bn 32
#define Hh 56
#define Wd 56
#define Cc 192
#define WSZ 7
#define SSH 3
#define NHEAD 6
#define HDIM 32
#define NT 49            // tokens per window
#define HIDDEN 768
#define SCALE 0.17677669529663687f

// scratch for x + attention residual (allocation-free rule: static device array)
__device__ float g_x2[(size_t)Bn * Hh * Wd * Cc];

// ---------------------------------------------------------------------------
// Kernel 1: per-window  LN1 -> QKV -> attention -> proj -> residual scatter
// grid = 32*64 = 2048 blocks, 256 threads
// smem: xw[49][196] | qkv[49][577] | stage[32*196] | psm[8*64]
// ---------------------------------------------------------------------------
#define ATTN_SMEM_FLOATS (44664)

__global__ __launch_bounds__(256) void swin_attn_kernel(
    const float* __restrict__ x, const float* __restrict__ mask,
    const float* __restrict__ rel_table, const float* __restrict__ qkv_w,
    const float* __restrict__ qkv_b, const float* __restrict__ proj_w,
    const float* __restrict__ proj_b, const float* __restrict__ n1w,
    const float* __restrict__ n1b)
{
    extern __shared__ float sm[];
    float* xw    = sm;              // 49*196 floats, later reused as attn-out
    float* qkv   = sm + 9604;       // 49*577 floats, later reused as proj-out (49*196)
    float* stage = sm + 37880;      // 32*196 = 6272 floats (weight stage / mask)
    float* psm   = sm + 44152;      // 8*64 floats

    const int bid  = blockIdx.x;
    const int b    = bid >> 6;
    const int w    = bid & 63;
    const int wh   = w >> 3;
    const int ww   = w & 7;
    const int tid  = threadIdx.x;
    const int warp = tid >> 5;
    const int lane = tid & 31;

    // ---- Phase 1: gather (shifted window) + LayerNorm1 ----
    for (int n = warp; n < NT; n += 8) {
        int r  = wh * WSZ + n / WSZ;
        int c  = ww * WSZ + n % WSZ;
        int gr = r + SSH; if (gr >= Hh) gr -= Hh;
        int gc = c + SSH; if (gc >= Wd) gc -= Wd;
        const float* xr = x + ((size_t)b * 3136 + gr * 56 + gc) * Cc;
        float v[6]; float s = 0.f, ss = 0.f;
#pragma unroll
        for (int j = 0; j < 6; j++) { v[j] = xr[lane + 32 * j]; s += v[j]; ss += v[j] * v[j]; }
#pragma unroll
        for (int o = 16; o > 0; o >>= 1) {
            s  += __shfl_xor_sync(0xffffffffu, s,  o);
            ss += __shfl_xor_sync(0xffffffffu, ss, o);
        }
        float mean = s * (1.f / 192.f);
        float rinv = rsqrtf(ss * (1.f / 192.f) - mean * mean + 1e-5f);
#pragma unroll
        for (int j = 0; j < 6; j++) {
            int k = lane + 32 * j;
            xw[n * 196 + k] = (v[j] - mean) * rinv * n1w[k] + n1b[k];
        }
    }
    __syncthreads();

    // ---- Phase 2: QKV GEMM  (49x576 = xw(49x192) @ qkv_w(192x576)) ----
    // warp handles rows {warp, warp+8, ...}; lane handles 6 cols (3 x float2)
    for (int pass = 0; pass < 3; pass++) {
        float acc[7][6];
#pragma unroll
        for (int i = 0; i < 7; i++)
#pragma unroll
            for (int g = 0; g < 6; g++) acc[i][g] = 0.f;

        for (int kc = 0; kc < 192; kc += 16) {
            __syncthreads();
            for (int idx = tid; idx < 768; idx += 256) {   // 16 x 48 float4
                int kk = idx / 48, cv = idx % 48;
                *(float4*)(stage + kk * 196 + 4 * cv) =
                    *(const float4*)(qkv_w + (size_t)(kc + kk) * 576 + pass * 192 + 4 * cv);
            }
            __syncthreads();
#pragma unroll 4
            for (int kk = 0; kk < 16; kk++) {
                float xv[7];
#pragma unroll
                for (int i = 0; i < 7; i++) {
                    int n = warp + 8 * i; if (n > 48) n = 48;
                    xv[i] = xw[n * 196 + kc + kk];
                }
                float2 wv[3];
#pragma unroll
                for (int g = 0; g < 3; g++)
                    wv[g] = *(float2*)(stage + kk * 196 + 2 * lane + 64 * g);
#pragma unroll
                for (int i = 0; i < 7; i++) {
#pragma unroll
                    for (int g = 0; g < 3; g++) {
                        acc[i][2 * g]     += xv[i] * wv[g].x;
                        acc[i][2 * g + 1] += xv[i] * wv[g].y;
                    }
                }
            }
        }
#pragma unroll
        for (int i = 0; i < 7; i++) {
            int n = warp + 8 * i;
            if (n < NT) {
#pragma unroll
                for (int g = 0; g < 3; g++) {
                    int j0 = pass * 192 + 2 * lane + 64 * g;
                    float o0 = acc[i][2 * g]     + qkv_b[j0];
                    float o1 = acc[i][2 * g + 1] + qkv_b[j0 + 1];
                    if (pass == 0) { o0 *= SCALE; o1 *= SCALE; }  // fold q scale
                    qkv[n * 577 + j0]     = o0;
                    qkv[n * 577 + j0 + 1] = o1;
                }
            }
        }
    }
    __syncthreads();

    // ---- stage this window's mask (shared by all heads) ----
    {
        const float* mrow = mask + (size_t)w * 2401;
        for (int idx = tid; idx < 2401; idx += 256) stage[idx] = mrow[idx];
    }
    __syncthreads();

    // ---- Phase 3: attention, warp = head ----
    if (warp < NHEAD) {
        const int h = warp;
        const float* qb = qkv + h * HDIM;          // q[n][d] at qb[n*577+d]
        const float* kb = qkv + 192 + h * HDIM;
        const float* vb = qkv + 384 + h * HDIM;
        float* prow = psm + warp * 64;
        const bool has2 = (lane + 32) < NT;
        const int m1 = lane;
        const int m2 = has2 ? lane + 32 : 48;
        const int rm1 = m1 / 7, cm1 = m1 % 7;
        const int rm2 = m2 / 7, cm2 = m2 % 7;

        for (int n = 0; n < NT; n++) {
            const int rn = n / 7, cn = n % 7;
            float a1 = 0.f, a2 = 0.f;
#pragma unroll
            for (int d = 0; d < HDIM; d++) {
                float qv = qb[n * 577 + d];
                a1 += qv * kb[m1 * 577 + d];
                a2 += qv * kb[m2 * 577 + d];
            }
            float s1 = a1 + __ldg(rel_table + ((rn - rm1 + 6) * 13 + (cn - cm1 + 6)) * NHEAD + h)
                          + stage[n * 49 + m1];
            float s2 = has2
                ? a2 + __ldg(rel_table + ((rn - rm2 + 6) * 13 + (cn - cm2 + 6)) * NHEAD + h)
                     + stage[n * 49 + m2]
                : -1e30f;
            float mx = fmaxf(s1, s2);
#pragma unroll
            for (int o = 16; o > 0; o >>= 1)
                mx = fmaxf(mx, __shfl_xor_sync(0xffffffffu, mx, o));
            float e1 = __expf(s1 - mx);
            float e2 = has2 ? __expf(s2 - mx) : 0.f;
            float sum = e1 + e2;
#pragma unroll
            for (int o = 16; o > 0; o >>= 1)
                sum += __shfl_xor_sync(0xffffffffu, sum, o);
            prow[lane]      = e1;
            prow[lane + 32] = e2;
            __syncwarp();
            float acco = 0.f;
#pragma unroll 7
            for (int m = 0; m < NT; m++) acco += prow[m] * vb[m * 577 + lane];
            xw[n * 196 + h * HDIM + lane] = acco * (1.f / sum);  // out reuses xw
            __syncwarp();
        }
    }
    __syncthreads();

    // ---- Phase 4: proj GEMM (49x192 = out(49x192) @ proj_w(192x192)) ----
    {
        float acc[7][6];
#pragma unroll
        for (int i = 0; i < 7; i++)
#pragma unroll
            for (int g = 0; g < 6; g++) acc[i][g] = 0.f;

        for (int kc = 0; kc < 192; kc += 32) {
            __syncthreads();
            for (int idx = tid; idx < 1536; idx += 256) {   // 32 x 48 float4
                int kk = idx / 48, cv = idx % 48;
                *(float4*)(stage + kk * 196 + 4 * cv) =
                    *(const float4*)(proj_w + (size_t)(kc + kk) * 192 + 4 * cv);
            }
            __syncthreads();
#pragma unroll 4
            for (int kk = 0; kk < 32; kk++) {
                float xv[7];
#pragma unroll
                for (int i = 0; i < 7; i++) {
                    int n = warp + 8 * i; if (n > 48) n = 48;
                    xv[i] = xw[n * 196 + kc + kk];
                }
                float2 wv[3];
#pragma unroll
                for (int g = 0; g < 3; g++)
                    wv[g] = *(float2*)(stage + kk * 196 + 2 * lane + 64 * g);
#pragma unroll
                for (int i = 0; i < 7; i++) {
#pragma unroll
                    for (int g = 0; g < 3; g++) {
                        acc[i][2 * g]     += xv[i] * wv[g].x;
                        acc[i][2 * g + 1] += xv[i] * wv[g].y;
                    }
                }
            }
        }
        // proj result (+bias) into qkv region as [49][196]
#pragma unroll
        for (int i = 0; i < 7; i++) {
            int n = warp + 8 * i;
            if (n < NT) {
#pragma unroll
                for (int g = 0; g < 3; g++) {
                    int j0 = 2 * lane + 64 * g;
                    qkv[n * 196 + j0]     = acc[i][2 * g]     + proj_b[j0];
                    qkv[n * 196 + j0 + 1] = acc[i][2 * g + 1] + proj_b[j0 + 1];
                }
            }
        }
    }
    __syncthreads();

    // ---- Phase 5: residual add + scatter (inverse map == forward map) ----
    for (int n = warp; n < NT; n += 8) {
        int r  = wh * WSZ + n / WSZ;
        int c  = ww * WSZ + n % WSZ;
        int gr = r + SSH; if (gr >= Hh) gr -= Hh;
        int gc = c + SSH; if (gc >= Wd) gc -= Wd;
        size_t base = ((size_t)b * 3136 + gr * 56 + gc) * Cc;
        const float* xr = x + base;
        float* orow = g_x2 + base;
#pragma unroll
        for (int j = 0; j < 6; j++) {
            int k = lane + 32 * j;
            orow[k] = xr[k] + qkv[n * 196 + k];
        }
    }
}

// ---------------------------------------------------------------------------
// Kernel 2: LN2 + MLP (fc1 -> gelu -> fc2) + residual, 64 tokens per block
// grid = 100352/64 = 1568 blocks, 256 threads (16x16)
// ---------------------------------------------------------------------------
#define MLP_SMEM_FLOATS (55040)

__device__ __forceinline__ float gelu_exact(float v) {
    return 0.5f * v * (1.0f + erff(v * 0.70710678118654752f));
}

__global__ __launch_bounds__(256) void swin_mlp_kernel(
    const float* __restrict__ n2w, const float* __restrict__ n2b,
    const float* __restrict__ fc1w, const float* __restrict__ fc1b,
    const float* __restrict__ fc2w, const float* __restrict__ fc2b,
    float* __restrict__ out)
{
    extern __shared__ float sm[];
    float* raw = sm;             // 64*196
    float* xn  = sm + 12544;     // 64*196
    float* f1s = sm + 25088;     // 192*68
    float* hs  = sm + 38144;     // 64*68
    float* f2s = sm + 42496;     // 64*196

    const int tid  = threadIdx.x;
    const int warp = tid >> 5;
    const int lane = tid & 31;
    const int ty   = tid >> 4;   // 0..15 -> rows 4*ty..4*ty+3
    const int tx   = tid & 15;   // 0..15 -> cols 4*tx (+64*jj)
    const size_t t0 = (size_t)blockIdx.x * 64;

    // ---- LN2 ----
    for (int n = warp; n < 64; n += 8) {
        const float* xr = g_x2 + (t0 + n) * Cc;
        float v[6]; float s = 0.f, ss = 0.f;
#pragma unroll
        for (int j = 0; j < 6; j++) { v[j] = xr[lane + 32 * j]; s += v[j]; ss += v[j] * v[j]; }
#pragma unroll
        for (int o = 16; o > 0; o >>= 1) {
            s  += __shfl_xor_sync(0xffffffffu, s,  o);
            ss += __shfl_xor_sync(0xffffffffu, ss, o);
        }
        float mean = s * (1.f / 192.f);
        float rinv = rsqrtf(ss * (1.f / 192.f) - mean * mean + 1e-5f);
#pragma unroll
        for (int j = 0; j < 6; j++) {
            int k = lane + 32 * j;
            raw[n * 196 + k] = v[j];
            xn[n * 196 + k]  = (v[j] - mean) * rinv * n2w[k] + n2b[k];
        }
    }
    __syncthreads();

    float yacc[4][12];
#pragma unroll
    for (int i = 0; i < 4; i++)
#pragma unroll
        for (int g = 0; g < 12; g++) yacc[i][g] = 0.f;

    for (int hc = 0; hc < HIDDEN; hc += 64) {
        __syncthreads();
        // stage fc1 chunk (192x64) and fc2 chunk (64x192)
        for (int idx = tid; idx < 3072; idx += 256) {
            int k = idx >> 4, cv = idx & 15;
            *(float4*)(f1s + k * 68 + 4 * cv) =
                *(const float4*)(fc1w + (size_t)k * 768 + hc + 4 * cv);
        }
        for (int idx = tid; idx < 3072; idx += 256) {
            int k = idx / 48, cv = idx % 48;
            *(float4*)(f2s + k * 196 + 4 * cv) =
                *(const float4*)(fc2w + (size_t)(hc + k) * 192 + 4 * cv);
        }
        __syncthreads();

        // H = gelu(xn @ fc1_chunk + b1), 64x64, 4x4 micro-tile per thread
        float hacc[4][4];
#pragma unroll
        for (int i = 0; i < 4; i++)
#pragma unroll
            for (int q = 0; q < 4; q++) hacc[i][q] = 0.f;
#pragma unroll 2
        for (int k = 0; k < 192; k++) {
            float a[4];
#pragma unroll
            for (int i = 0; i < 4; i++) a[i] = xn[(4 * ty + i) * 196 + k];
            float4 bv = *(float4*)(f1s + k * 68 + 4 * tx);
#pragma unroll
            for (int i = 0; i < 4; i++) {
                hacc[i][0] += a[i] * bv.x;
                hacc[i][1] += a[i] * bv.y;
                hacc[i][2] += a[i] * bv.z;
                hacc[i][3] += a[i] * bv.w;
            }
        }
        {
            float4 b1 = *(const float4*)(fc1b + hc + 4 * tx);
#pragma unroll
            for (int i = 0; i < 4; i++) {
                float* hrow = hs + (4 * ty + i) * 68 + 4 * tx;
                hrow[0] = gelu_exact(hacc[i][0] + b1.x);
                hrow[1] = gelu_exact(hacc[i][1] + b1.y);
                hrow[2] = gelu_exact(hacc[i][2] + b1.z);
                hrow[3] = gelu_exact(hacc[i][3] + b1.w);
            }
        }
        __syncthreads();

        // Y += H @ fc2_chunk, 64x192, 4x12 micro-tile per thread
#pragma unroll 2
        for (int k = 0; k < 64; k++) {
            float a[4];
#pragma unroll
            for (int i = 0; i < 4; i++) a[i] = hs[(4 * ty + i) * 68 + k];
            float4 w0 = *(float4*)(f2s + k * 196 + 4 * tx);
            float4 w1 = *(float4*)(f2s + k * 196 + 4 * tx + 64);
            float4 w2 = *(float4*)(f2s + k * 196 + 4 * tx + 128);
#pragma unroll
            for (int i = 0; i < 4; i++) {
                yacc[i][0]  += a[i] * w0.x;  yacc[i][1]  += a[i] * w0.y;
                yacc[i][2]  += a[i] * w0.z;  yacc[i][3]  += a[i] * w0.w;
                yacc[i][4]  += a[i] * w1.x;  yacc[i][5]  += a[i] * w1.y;
                yacc[i][6]  += a[i] * w1.z;  yacc[i][7]  += a[i] * w1.w;
                yacc[i][8]  += a[i] * w2.x;  yacc[i][9]  += a[i] * w2.y;
                yacc[i][10] += a[i] * w2.z;  yacc[i][11] += a[i] * w2.w;
            }
        }
    }

    // ---- epilogue: out = raw + Y + fc2_b ----
#pragma unroll
    for (int i = 0; i < 4; i++) {
        int row = 4 * ty + i;
        float* orow = out + (t0 + row) * Cc;
        const float* rrow = raw + row * 196;
#pragma unroll
        for (int jj = 0; jj < 3; jj++) {
            int c0 = 4 * tx + 64 * jj;
            float4 bb = *(const float4*)(fc2b + c0);
            float4 r;
            r.x = rrow[c0 + 0] + yacc[i][4 * jj + 0] + bb.x;
            r.y = rrow[c0 + 1] + yacc[i][4 * jj + 1] + bb.y;
            r.z = rrow[c0 + 2] + yacc[i][4 * jj + 2] + bb.z;
            r.w = rrow[c0 + 3] + yacc[i][4 * jj + 3] + bb.w;
            *(float4*)(orow + c0) = r;
        }
    }
}

// ---------------------------------------------------------------------------
extern "C" void kernel_launch(void* const* d_in, const int* in_sizes, int n_in,
                              void* d_out, int out_size)
{
    const float* x      = (const float*)d_in[0];
    const float* mask   = (const float*)d_in[1];
    const float* rel    = (const float*)d_in[2];
    const float* qkv_w  = (const float*)d_in[3];
    const float* qkv_b  = (const float*)d_in[4];
    const float* proj_w = (const float*)d_in[5];
    const float* proj_b = (const float*)d_in[6];
    const float* n1w    = (const float*)d_in[7];
    const float* n1b    = (const float*)d_in[8];
    const float* n2w    = (const float*)d_in[9];
    const float* n2b    = (const float*)d_in[10];
    const float* fc1w   = (const float*)d_in[11];
    const float* fc1b   = (const float*)d_in[12];
    const float* fc2w   = (const float*)d_in[13];
    const float* fc2b   = (const float*)d_in[14];
    float* out = (float*)d_out;

    cudaFuncSetAttribute(swin_attn_kernel, cudaFuncAttributeMaxDynamicSharedMemorySize,
                         ATTN_SMEM_FLOATS * (int)sizeof(float));
    cudaFuncSetAttribute(swin_mlp_kernel, cudaFuncAttributeMaxDynamicSharedMemorySize,
                         MLP_SMEM_FLOATS * (int)sizeof(float));

    swin_attn_kernel<<<Bn * 64, 256, ATTN_SMEM_FLOATS * sizeof(float)>>>(
        x, mask, rel, qkv_w, qkv_b, proj_w, proj_b, n1w, n1b);
    swin_mlp_kernel<<<1568, 256, MLP_SMEM_FLOATS * sizeof(float)>>>(
        n2w, n2b, fc1w, fc1b, fc2w, fc2b, out);
}

// round 3
// speedup vs baseline: 1.4849x; 1.4849x over previous
#include <cuda_runtime.h>
#include <math.h>
#include <stdint.h>

#define Bn 32
#define Cc 192
#define WSZ 7
#define NHEAD 6
#define NT 49
#define HIDDEN 768
#define SCALE 0.17677669529663687f

// scratch for x + attention residual
__device__ float g_x2[(size_t)Bn * 56 * 56 * Cc];

// tf32 round: destination must be a b32 register per PTX spec
__device__ __forceinline__ uint32_t tf32r(float x) {
    uint32_t y;
    asm("cvt.rna.tf32.f32 %0, %1;" : "=r"(y) : "f"(x));
    return y;
}

__device__ __forceinline__ void mma8(float4& c, uint32_t a0, uint32_t a1, uint32_t a2,
                                     uint32_t a3, uint32_t b0, uint32_t b1) {
    asm volatile(
        "mma.sync.aligned.m16n8k8.row.col.f32.tf32.tf32.f32 "
        "{%0,%1,%2,%3},{%4,%5,%6,%7},{%8,%9},{%0,%1,%2,%3};"
        : "+f"(c.x), "+f"(c.y), "+f"(c.z), "+f"(c.w)
        : "r"(a0), "r"(a1), "r"(a2), "r"(a3), "r"(b0), "r"(b1));
}

__device__ __forceinline__ float gelu_exact(float v) {
    return 0.5f * v * (1.0f + erff(v * 0.70710678118654752f));
}

// ---------------------------------------------------------------------------
// Kernel 1: per-window  LN1 -> QKV(mma) -> attention -> proj(mma) -> scatter
// grid = 2048 blocks, 256 threads
// ---------------------------------------------------------------------------
#define XW_STR 204
#define QK_STR 577
#define WST_STR 200
#define OFF_QKV 13056          // 64*204
#define OFF_WST 41329          // + 49*577
#define OFF_PSM 44529          // + 3200
#define ATTN_SM_BYTES (45041 * 4)

__global__ __launch_bounds__(256) void swin_attn_kernel(
    const float* __restrict__ x, const float* __restrict__ mask,
    const float* __restrict__ rel_table, const float* __restrict__ qkv_w,
    const float* __restrict__ qkv_b, const float* __restrict__ proj_w,
    const float* __restrict__ proj_b, const float* __restrict__ n1w,
    const float* __restrict__ n1b)
{
    extern __shared__ float sm[];
    float* xw   = sm;               // [64][204]  LN1 out / attn out (tf32 bits)
    float* qkvs = sm + OFF_QKV;     // [49][577]  fp32
    float* wst  = sm + OFF_WST;     // [16][200]  weight stage (tf32 bits) / mask
    float* psm  = sm + OFF_PSM;     // [8][64]
    uint32_t* xwu  = (uint32_t*)xw;
    uint32_t* wstu = (uint32_t*)wst;

    const int bid  = blockIdx.x;
    const int b    = bid >> 6;
    const int w    = bid & 63;
    const int wh   = w >> 3;
    const int ww   = w & 7;
    const int tid  = threadIdx.x;
    const int warp = tid >> 5;
    const int lane = tid & 31;
    const int g    = lane >> 2;     // fragment group (row)
    const int q    = lane & 3;      // thread in group (k / col)
    const int wm   = warp & 3;      // m-tile id (16 rows each)
    const int wn   = warp >> 2;     // n-half id (96 cols each)
    const int rowA = 16 * wm + g;   // fragment row this thread owns

    // ---- Phase 1: gather (shifted window) + LayerNorm1 (rows>=49 zeroed) ----
    for (int n = warp; n < 64; n += 8) {
        if (n < NT) {
            int r  = wh * WSZ + n / WSZ;
            int c  = ww * WSZ + n % WSZ;
            int gr = r + 3; if (gr >= 56) gr -= 56;
            int gc = c + 3; if (gc >= 56) gc -= 56;
            const float* xr = x + ((size_t)b * 3136 + gr * 56 + gc) * Cc;
            float v[6]; float s = 0.f, ss = 0.f;
#pragma unroll
            for (int j = 0; j < 6; j++) { v[j] = xr[lane + 32 * j]; s += v[j]; ss += v[j] * v[j]; }
#pragma unroll
            for (int o = 16; o > 0; o >>= 1) {
                s  += __shfl_xor_sync(0xffffffffu, s,  o);
                ss += __shfl_xor_sync(0xffffffffu, ss, o);
            }
            float mean = s * (1.f / 192.f);
            float rinv = rsqrtf(ss * (1.f / 192.f) - mean * mean + 1e-5f);
#pragma unroll
            for (int j = 0; j < 6; j++) {
                int k = lane + 32 * j;
                xwu[n * XW_STR + k] = tf32r((v[j] - mean) * rinv * n1w[k] + n1b[k]);
            }
        } else {
#pragma unroll
            for (int j = 0; j < 6; j++) xwu[n * XW_STR + lane + 32 * j] = 0u;
        }
    }

    // ---- Phase 2: QKV via tf32 mma : out(64x192) per pass, K=192 ----
    const bool v0 = rowA < NT, v1 = (rowA + 8) < NT;
    for (int p = 0; p < 3; p++) {
        float4 acc[12];
#pragma unroll
        for (int t = 0; t < 12; t++) acc[t] = make_float4(0.f, 0.f, 0.f, 0.f);

        for (int kc = 0; kc < 192; kc += 16) {
            __syncthreads();
            for (int idx = tid; idx < 768; idx += 256) {   // 16 x 48 float4
                int kk = idx / 48, cv = idx % 48;
                float4 v = *(const float4*)(qkv_w + (size_t)(kc + kk) * 576 + p * 192 + 4 * cv);
                uint32_t* d = wstu + kk * WST_STR + 4 * cv;
                d[0] = tf32r(v.x); d[1] = tf32r(v.y); d[2] = tf32r(v.z); d[3] = tf32r(v.w);
            }
            __syncthreads();
#pragma unroll
            for (int k0 = 0; k0 < 16; k0 += 8) {
                int kg = kc + k0;
                uint32_t a0 = xwu[rowA * XW_STR + kg + q];
                uint32_t a1 = xwu[(rowA + 8) * XW_STR + kg + q];
                uint32_t a2 = xwu[rowA * XW_STR + kg + q + 4];
                uint32_t a3 = xwu[(rowA + 8) * XW_STR + kg + q + 4];
#pragma unroll
                for (int t = 0; t < 12; t++) {
                    uint32_t b0 = wstu[(k0 + q) * WST_STR + 96 * wn + 8 * t + g];
                    uint32_t b1 = wstu[(k0 + q + 4) * WST_STR + 96 * wn + 8 * t + g];
                    mma8(acc[t], a0, a1, a2, a3, b0, b1);
                }
            }
        }
        // epilogue: + bias, fold q-scale, store rows<49
#pragma unroll
        for (int t = 0; t < 12; t++) {
            int col = 96 * wn + 8 * t + 2 * q;
            int j   = 192 * p + col;
            float b0v = __ldg(qkv_b + j), b1v = __ldg(qkv_b + j + 1);
            float o00 = acc[t].x + b0v, o01 = acc[t].y + b1v;
            float o10 = acc[t].z + b0v, o11 = acc[t].w + b1v;
            if (p == 0) { o00 *= SCALE; o01 *= SCALE; o10 *= SCALE; o11 *= SCALE; }
            if (v0) { qkvs[rowA * QK_STR + j] = o00; qkvs[rowA * QK_STR + j + 1] = o01; }
            if (v1) { qkvs[(rowA + 8) * QK_STR + j] = o10; qkvs[(rowA + 8) * QK_STR + j + 1] = o11; }
        }
    }
    __syncthreads();

    // ---- stage this window's mask ----
    {
        const float* mrow = mask + (size_t)w * 2401;
        for (int idx = tid; idx < 2401; idx += 256) wst[idx] = mrow[idx];
    }
    __syncthreads();

    // ---- Phase 3: attention (FFMA), warp = head ----
    if (warp < NHEAD) {
        const int h = warp;
        const float* qb = qkvs + h * 32;
        const float* kb = qkvs + 192 + h * 32;
        const float* vb = qkvs + 384 + h * 32;
        float* prow = psm + warp * 64;
        const bool has2 = (lane + 32) < NT;
        const int m1 = lane;
        const int m2 = has2 ? lane + 32 : 48;
        const int rm1 = m1 / 7, cm1 = m1 % 7;
        const int rm2 = m2 / 7, cm2 = m2 % 7;

        for (int n = 0; n < NT; n++) {
            const int rn = n / 7, cn = n % 7;
            float a1 = 0.f, a2 = 0.f;
#pragma unroll
            for (int d = 0; d < 32; d++) {
                float qv = qb[n * QK_STR + d];
                a1 += qv * kb[m1 * QK_STR + d];
                a2 += qv * kb[m2 * QK_STR + d];
            }
            float s1 = a1 + __ldg(rel_table + ((rn - rm1 + 6) * 13 + (cn - cm1 + 6)) * NHEAD + h)
                          + wst[n * 49 + m1];
            float s2 = has2
                ? a2 + __ldg(rel_table + ((rn - rm2 + 6) * 13 + (cn - cm2 + 6)) * NHEAD + h)
                     + wst[n * 49 + m2]
                : -1e30f;
            float mx = fmaxf(s1, s2);
#pragma unroll
            for (int o = 16; o > 0; o >>= 1)
                mx = fmaxf(mx, __shfl_xor_sync(0xffffffffu, mx, o));
            float e1 = __expf(s1 - mx);
            float e2 = has2 ? __expf(s2 - mx) : 0.f;
            float sum = e1 + e2;
#pragma unroll
            for (int o = 16; o > 0; o >>= 1)
                sum += __shfl_xor_sync(0xffffffffu, sum, o);
            prow[lane]      = e1;
            prow[lane + 32] = e2;
            __syncwarp();
            float acco = 0.f;
#pragma unroll 7
            for (int m = 0; m < NT; m++) acco += prow[m] * vb[m * QK_STR + lane];
            xwu[n * XW_STR + h * 32 + lane] = tf32r(acco * (1.f / sum));
            __syncwarp();
        }
    }

    // ---- Phase 4: proj via tf32 mma, fused residual scatter ----
    {
        float4 acc[12];
#pragma unroll
        for (int t = 0; t < 12; t++) acc[t] = make_float4(0.f, 0.f, 0.f, 0.f);

        for (int kc = 0; kc < 192; kc += 16) {
            __syncthreads();
            for (int idx = tid; idx < 768; idx += 256) {
                int kk = idx / 48, cv = idx % 48;
                float4 v = *(const float4*)(proj_w + (size_t)(kc + kk) * 192 + 4 * cv);
                uint32_t* d = wstu + kk * WST_STR + 4 * cv;
                d[0] = tf32r(v.x); d[1] = tf32r(v.y); d[2] = tf32r(v.z); d[3] = tf32r(v.w);
            }
            __syncthreads();
#pragma unroll
            for (int k0 = 0; k0 < 16; k0 += 8) {
                int kg = kc + k0;
                uint32_t a0 = xwu[rowA * XW_STR + kg + q];
                uint32_t a1 = xwu[(rowA + 8) * XW_STR + kg + q];
                uint32_t a2 = xwu[rowA * XW_STR + kg + q + 4];
                uint32_t a3 = xwu[(rowA + 8) * XW_STR + kg + q + 4];
#pragma unroll
                for (int t = 0; t < 12; t++) {
                    uint32_t b0 = wstu[(k0 + q) * WST_STR + 96 * wn + 8 * t + g];
                    uint32_t b1 = wstu[(k0 + q + 4) * WST_STR + 96 * wn + 8 * t + g];
                    mma8(acc[t], a0, a1, a2, a3, b0, b1);
                }
            }
        }

        // scatter with residual: rows rowA / rowA+8 map to image positions
        size_t base0 = 0, base1 = 0;
        if (v0) {
            int gr = wh * 7 + rowA / 7 + 3; if (gr >= 56) gr -= 56;
            int gc = ww * 7 + rowA % 7 + 3; if (gc >= 56) gc -= 56;
            base0 = ((size_t)b * 3136 + gr * 56 + gc) * Cc;
        }
        if (v1) {
            int r1i = rowA + 8;
            int gr = wh * 7 + r1i / 7 + 3; if (gr >= 56) gr -= 56;
            int gc = ww * 7 + r1i % 7 + 3; if (gc >= 56) gc -= 56;
            base1 = ((size_t)b * 3136 + gr * 56 + gc) * Cc;
        }
#pragma unroll
        for (int t = 0; t < 12; t++) {
            int col = 96 * wn + 8 * t + 2 * q;
            float pb0 = __ldg(proj_b + col), pb1 = __ldg(proj_b + col + 1);
            if (v0) {
                float2 xv = *(const float2*)(x + base0 + col);
                float2 r; r.x = xv.x + acc[t].x + pb0; r.y = xv.y + acc[t].y + pb1;
                *(float2*)(g_x2 + base0 + col) = r;
            }
            if (v1) {
                float2 xv = *(const float2*)(x + base1 + col);
                float2 r; r.x = xv.x + acc[t].z + pb0; r.y = xv.y + acc[t].w + pb1;
                *(float2*)(g_x2 + base1 + col) = r;
            }
        }
    }
}

// ---------------------------------------------------------------------------
// Kernel 2: LN2 + MLP via tf32 mma + residual; 64 tokens/block, 1568 blocks
// ---------------------------------------------------------------------------
#define XN_STR 204
#define F1_STR 72
#define HS_STR 68
#define F2_STR 204
#define OFF_F1 13056          // 64*204
#define OFF_HS 26880          // + 192*72
#define OFF_F2 31232          // + 64*68
#define MLP_SM_BYTES (44288 * 4)

__global__ __launch_bounds__(256) void swin_mlp_kernel(
    const float* __restrict__ n2w, const float* __restrict__ n2b,
    const float* __restrict__ fc1w, const float* __restrict__ fc1b,
    const float* __restrict__ fc2w, const float* __restrict__ fc2b,
    float* __restrict__ out)
{
    extern __shared__ float sm[];
    float* xn  = sm;             // [64][204] tf32 bits
    float* f1s = sm + OFF_F1;    // [192][72]
    float* hs  = sm + OFF_HS;    // [64][68]
    float* f2s = sm + OFF_F2;    // [64][204]
    uint32_t* xnu  = (uint32_t*)xn;
    uint32_t* f1u  = (uint32_t*)f1s;
    uint32_t* hsu  = (uint32_t*)hs;
    uint32_t* f2u  = (uint32_t*)f2s;

    const int tid  = threadIdx.x;
    const int warp = tid >> 5;
    const int lane = tid & 31;
    const int g    = lane >> 2;
    const int q    = lane & 3;
    const int wm   = warp & 3;
    const int wn   = warp >> 2;
    const int rowA = 16 * wm + g;
    const size_t t0 = (size_t)blockIdx.x * 64;

    // ---- LN2 ----
    for (int n = warp; n < 64; n += 8) {
        const float* xr = g_x2 + (t0 + n) * Cc;
        float v[6]; float s = 0.f, ss = 0.f;
#pragma unroll
        for (int j = 0; j < 6; j++) { v[j] = xr[lane + 32 * j]; s += v[j]; ss += v[j] * v[j]; }
#pragma unroll
        for (int o = 16; o > 0; o >>= 1) {
            s  += __shfl_xor_sync(0xffffffffu, s,  o);
            ss += __shfl_xor_sync(0xffffffffu, ss, o);
        }
        float mean = s * (1.f / 192.f);
        float rinv = rsqrtf(ss * (1.f / 192.f) - mean * mean + 1e-5f);
#pragma unroll
        for (int j = 0; j < 6; j++) {
            int k = lane + 32 * j;
            xnu[n * XN_STR + k] = tf32r((v[j] - mean) * rinv * n2w[k] + n2b[k]);
        }
    }

    float4 yacc[12];
#pragma unroll
    for (int t = 0; t < 12; t++) yacc[t] = make_float4(0.f, 0.f, 0.f, 0.f);

    for (int hc = 0; hc < HIDDEN; hc += 64) {
        __syncthreads();
        // stage fc1 chunk [192][64] and fc2 chunk [64][192] (tf32-rounded)
        for (int idx = tid; idx < 3072; idx += 256) {
            int k = idx >> 4, cv = idx & 15;
            float4 v = *(const float4*)(fc1w + (size_t)k * HIDDEN + hc + 4 * cv);
            uint32_t* d = f1u + k * F1_STR + 4 * cv;
            d[0] = tf32r(v.x); d[1] = tf32r(v.y); d[2] = tf32r(v.z); d[3] = tf32r(v.w);
        }
        for (int idx = tid; idx < 3072; idx += 256) {
            int k = idx / 48, cv = idx % 48;
            float4 v = *(const float4*)(fc2w + (size_t)(hc + k) * Cc + 4 * cv);
            uint32_t* d = f2u + k * F2_STR + 4 * cv;
            d[0] = tf32r(v.x); d[1] = tf32r(v.y); d[2] = tf32r(v.z); d[3] = tf32r(v.w);
        }
        __syncthreads();

        // fc1: H(64x64) = xn(64x192) @ w1chunk ; warp tile m16 x n32
        float4 acc1[4];
#pragma unroll
        for (int t = 0; t < 4; t++) acc1[t] = make_float4(0.f, 0.f, 0.f, 0.f);
#pragma unroll 4
        for (int ks = 0; ks < 24; ks++) {
            int kg = 8 * ks;
            uint32_t a0 = xnu[rowA * XN_STR + kg + q];
            uint32_t a1 = xnu[(rowA + 8) * XN_STR + kg + q];
            uint32_t a2 = xnu[rowA * XN_STR + kg + q + 4];
            uint32_t a3 = xnu[(rowA + 8) * XN_STR + kg + q + 4];
#pragma unroll
            for (int t = 0; t < 4; t++) {
                uint32_t b0 = f1u[(kg + q) * F1_STR + 32 * wn + 8 * t + g];
                uint32_t b1 = f1u[(kg + q + 4) * F1_STR + 32 * wn + 8 * t + g];
                mma8(acc1[t], a0, a1, a2, a3, b0, b1);
            }
        }
        // bias + gelu -> hs (tf32 bits)
#pragma unroll
        for (int t = 0; t < 4; t++) {
            int col = 32 * wn + 8 * t + 2 * q;
            float b0v = __ldg(fc1b + hc + col), b1v = __ldg(fc1b + hc + col + 1);
            hsu[rowA * HS_STR + col]           = tf32r(gelu_exact(acc1[t].x + b0v));
            hsu[rowA * HS_STR + col + 1]       = tf32r(gelu_exact(acc1[t].y + b1v));
            hsu[(rowA + 8) * HS_STR + col]     = tf32r(gelu_exact(acc1[t].z + b0v));
            hsu[(rowA + 8) * HS_STR + col + 1] = tf32r(gelu_exact(acc1[t].w + b1v));
        }
        __syncthreads();

        // fc2: Y(64x192) += H(64x64) @ w2chunk ; warp tile m16 x n96
#pragma unroll
        for (int ks = 0; ks < 8; ks++) {
            int kg = 8 * ks;
            uint32_t a0 = hsu[rowA * HS_STR + kg + q];
            uint32_t a1 = hsu[(rowA + 8) * HS_STR + kg + q];
            uint32_t a2 = hsu[rowA * HS_STR + kg + q + 4];
            uint32_t a3 = hsu[(rowA + 8) * HS_STR + kg + q + 4];
#pragma unroll
            for (int t = 0; t < 12; t++) {
                uint32_t b0 = f2u[(kg + q) * F2_STR + 96 * wn + 8 * t + g];
                uint32_t b1 = f2u[(kg + q + 4) * F2_STR + 96 * wn + 8 * t + g];
                mma8(yacc[t], a0, a1, a2, a3, b0, b1);
            }
        }
    }

    // ---- epilogue: out = g_x2 + Y + fc2_b ----
#pragma unroll
    for (int t = 0; t < 12; t++) {
        int col = 96 * wn + 8 * t + 2 * q;
        float b0v = __ldg(fc2b + col), b1v = __ldg(fc2b + col + 1);
        {
            size_t base = (t0 + rowA) * Cc + col;
            float2 xv = *(const float2*)(g_x2 + base);
            float2 r; r.x = xv.x + yacc[t].x + b0v; r.y = xv.y + yacc[t].y + b1v;
            *(float2*)(out + base) = r;
        }
        {
            size_t base = (t0 + rowA + 8) * Cc + col;
            float2 xv = *(const float2*)(g_x2 + base);
            float2 r; r.x = xv.x + yacc[t].z + b0v; r.y = xv.y + yacc[t].w + b1v;
            *(float2*)(out + base) = r;
        }
    }
}

// ---------------------------------------------------------------------------
extern "C" void kernel_launch(void* const* d_in, const int* in_sizes, int n_in,
                              void* d_out, int out_size)
{
    const float* x      = (const float*)d_in[0];
    const float* mask   = (const float*)d_in[1];
    const float* rel    = (const float*)d_in[2];
    const float* qkv_w  = (const float*)d_in[3];
    const float* qkv_b  = (const float*)d_in[4];
    const float* proj_w = (const float*)d_in[5];
    const float* proj_b = (const float*)d_in[6];
    const float* n1w    = (const float*)d_in[7];
    const float* n1b    = (const float*)d_in[8];
    const float* n2w    = (const float*)d_in[9];
    const float* n2b    = (const float*)d_in[10];
    const float* fc1w   = (const float*)d_in[11];
    const float* fc1b   = (const float*)d_in[12];
    const float* fc2w   = (const float*)d_in[13];
    const float* fc2b   = (const float*)d_in[14];
    float* out = (float*)d_out;

    cudaFuncSetAttribute(swin_attn_kernel, cudaFuncAttributeMaxDynamicSharedMemorySize,
                         ATTN_SM_BYTES);
    cudaFuncSetAttribute(swin_mlp_kernel, cudaFuncAttributeMaxDynamicSharedMemorySize,
                         MLP_SM_BYTES);

    swin_attn_kernel<<<Bn * 64, 256, ATTN_SM_BYTES>>>(
        x, mask, rel, qkv_w, qkv_b, proj_w, proj_b, n1w, n1b);
    swin_mlp_kernel<<<1568, 256, MLP_SM_BYTES>>>(
        n2w, n2b, fc1w, fc1b, fc2w, fc2b, out);
}

// round 4
// speedup vs baseline: 2.9872x; 2.0118x over previous
#include <cuda_runtime.h>
#include <cuda_fp16.h>
#include <math.h>
#include <stdint.h>

#define Bn 32
#define Cc 192
#define WSZ 7
#define NHEAD 6
#define NT 49
#define HIDDEN 768
#define SCALE 0.17677669529663687f

// scratch for x + attention residual
__device__ float g_x2[(size_t)Bn * 56 * 56 * Cc];

// pre-transposed fp16 weights, [n][k] layout
__device__ __align__(16) __half g_qkvT[576 * 192];
__device__ __align__(16) __half g_projT[192 * 192];
__device__ __align__(16) __half g_fc1T[768 * 192];
__device__ __align__(16) __half g_fc2T[192 * 768];

__global__ void convert_w(const float* __restrict__ qkv_w, const float* __restrict__ proj_w,
                          const float* __restrict__ fc1w, const float* __restrict__ fc2w)
{
    int tid = blockIdx.x * blockDim.x + threadIdx.x;
    int stride = gridDim.x * blockDim.x;
    for (int j = tid; j < 192 * 576; j += stride) {
        int k = j / 576, n = j % 576;
        g_qkvT[n * 192 + k] = __float2half(qkv_w[j]);
    }
    for (int j = tid; j < 192 * 192; j += stride) {
        int k = j / 192, n = j % 192;
        g_projT[n * 192 + k] = __float2half(proj_w[j]);
    }
    for (int j = tid; j < 192 * 768; j += stride) {
        int k = j / 768, n = j % 768;
        g_fc1T[n * 192 + k] = __float2half(fc1w[j]);
    }
    for (int j = tid; j < 768 * 192; j += stride) {
        int k = j / 192, n = j % 192;
        g_fc2T[n * 768 + k] = __float2half(fc2w[j]);
    }
}

// D = A(16x16 f16, row) x B(16x8 f16, col) + D, fp32 accum
__device__ __forceinline__ void mma16(float4& c, uint32_t a0, uint32_t a1, uint32_t a2,
                                      uint32_t a3, uint32_t b0, uint32_t b1) {
    asm volatile(
        "mma.sync.aligned.m16n8k16.row.col.f32.f16.f16.f32 "
        "{%0,%1,%2,%3},{%4,%5,%6,%7},{%8,%9},{%0,%1,%2,%3};"
        : "+f"(c.x), "+f"(c.y), "+f"(c.z), "+f"(c.w)
        : "r"(a0), "r"(a1), "r"(a2), "r"(a3), "r"(b0), "r"(b1));
}

__device__ __forceinline__ float gelu_exact(float v) {
    return 0.5f * v * (1.0f + erff(v * 0.70710678118654752f));
}

// ---------------------------------------------------------------------------
// Kernel 1: per-window LN1 -> QKV(f16 mma) -> attention -> proj(f16 mma)
// smem (halves): xw[64][200] | qkvs[49][578] | wst[192][40] | psm
// ---------------------------------------------------------------------------
#define XW_STRH 200           // halves; 100 u32 (100%32=4 -> conflict-free)
#define QKS 578               // halves; 289 u32 (odd -> conflict-free)
#define OFF_QKV_H 12800
#define OFF_WST_H 41124
#define OFF_PSM_H 48804
#define ATTN_SM_BYTES (49572 * 2)

__global__ __launch_bounds__(256, 2) void swin_attn_kernel(
    const float* __restrict__ x, const float* __restrict__ mask,
    const float* __restrict__ rel_table,
    const float* __restrict__ qkv_b, const float* __restrict__ proj_b,
    const float* __restrict__ n1w, const float* __restrict__ n1b)
{
    extern __shared__ __half smh[];
    __half* xwh   = smh;                 // [64][200]  LN1 out / attn out
    __half* qkvsh = smh + OFF_QKV_H;     // [49][578]
    uint32_t* xwu  = (uint32_t*)xwh;
    uint32_t* wstu = (uint32_t*)(smh + OFF_WST_H);   // [192][20] u32
    float*    wstf = (float*)(smh + OFF_WST_H);      // mask view (2401 f)
    float*    psm  = (float*)(smh + OFF_PSM_H);      // [6][64]
    const uint32_t* qkvT_u  = (const uint32_t*)g_qkvT;
    const uint32_t* projT_u = (const uint32_t*)g_projT;

    const int bid  = blockIdx.x;
    const int b    = bid >> 6;
    const int w    = bid & 63;
    const int wh   = w >> 3;
    const int ww   = w & 7;
    const int tid  = threadIdx.x;
    const int warp = tid >> 5;
    const int lane = tid & 31;
    const int g    = lane >> 2;
    const int q    = lane & 3;
    const int wm   = warp & 3;
    const int wn   = warp >> 2;
    const int rowA = 16 * wm + g;

    // ---- Phase 1: gather (shifted window) + LN1 (rows>=49 zeroed) ----
    for (int n = warp; n < 64; n += 8) {
        if (n < NT) {
            int r  = wh * WSZ + n / WSZ;
            int c  = ww * WSZ + n % WSZ;
            int gr = r + 3; if (gr >= 56) gr -= 56;
            int gc = c + 3; if (gc >= 56) gc -= 56;
            const float* xr = x + ((size_t)b * 3136 + gr * 56 + gc) * Cc;
            float v[6]; float s = 0.f, ss = 0.f;
#pragma unroll
            for (int j = 0; j < 6; j++) { v[j] = xr[lane + 32 * j]; s += v[j]; ss += v[j] * v[j]; }
#pragma unroll
            for (int o = 16; o > 0; o >>= 1) {
                s  += __shfl_xor_sync(0xffffffffu, s,  o);
                ss += __shfl_xor_sync(0xffffffffu, ss, o);
            }
            float mean = s * (1.f / 192.f);
            float rinv = rsqrtf(ss * (1.f / 192.f) - mean * mean + 1e-5f);
#pragma unroll
            for (int j = 0; j < 6; j++) {
                int k = lane + 32 * j;
                xwh[n * XW_STRH + k] = __float2half((v[j] - mean) * rinv * n1w[k] + n1b[k]);
            }
        } else {
#pragma unroll
            for (int j = 0; j < 3; j++) xwu[n * 100 + lane + 32 * j] = 0u;
        }
    }

    // ---- Phase 2: QKV via f16 mma : out(64x192) per pass, K=192 ----
    const bool v0 = rowA < NT, v1 = (rowA + 8) < NT;
    for (int p = 0; p < 3; p++) {
        float4 acc[12];
#pragma unroll
        for (int t = 0; t < 12; t++) acc[t] = make_float4(0.f, 0.f, 0.f, 0.f);

        for (int kc = 0; kc < 192; kc += 32) {
            __syncthreads();
            for (int idx = tid; idx < 3072; idx += 256) {   // 192 rows x 16 u32
                int n = idx >> 4, kk = idx & 15;
                wstu[n * 20 + kk] = qkvT_u[(p * 192 + n) * 96 + (kc >> 1) + kk];
            }
            __syncthreads();
#pragma unroll
            for (int k0 = 0; k0 < 32; k0 += 16) {
                int kw = (kc + k0) >> 1;
                uint32_t a0 = xwu[rowA * 100 + kw + q];
                uint32_t a1 = xwu[(rowA + 8) * 100 + kw + q];
                uint32_t a2 = xwu[rowA * 100 + kw + q + 4];
                uint32_t a3 = xwu[(rowA + 8) * 100 + kw + q + 4];
#pragma unroll
                for (int t = 0; t < 12; t++) {
                    int col = 96 * wn + 8 * t + g;
                    uint32_t b0 = wstu[col * 20 + (k0 >> 1) + q];
                    uint32_t b1 = wstu[col * 20 + (k0 >> 1) + q + 4];
                    mma16(acc[t], a0, a1, a2, a3, b0, b1);
                }
            }
        }
#pragma unroll
        for (int t = 0; t < 12; t++) {
            int col = 96 * wn + 8 * t + 2 * q;
            int j   = 192 * p + col;
            float b0v = __ldg(qkv_b + j), b1v = __ldg(qkv_b + j + 1);
            float o00 = acc[t].x + b0v, o01 = acc[t].y + b1v;
            float o10 = acc[t].z + b0v, o11 = acc[t].w + b1v;
            if (p == 0) { o00 *= SCALE; o01 *= SCALE; o10 *= SCALE; o11 *= SCALE; }
            if (v0) *(__half2*)(qkvsh + rowA * QKS + j)       = __floats2half2_rn(o00, o01);
            if (v1) *(__half2*)(qkvsh + (rowA + 8) * QKS + j) = __floats2half2_rn(o10, o11);
        }
    }
    __syncthreads();

    // ---- stage this window's mask (wst region is free now) ----
    {
        const float* mrow = mask + (size_t)w * 2401;
        for (int idx = tid; idx < 2401; idx += 256) wstf[idx] = mrow[idx];
    }
    __syncthreads();

    // ---- Phase 3: attention (FFMA fp32 over fp16 operands), warp = head ----
    if (warp < NHEAD) {
        const int h = warp;
        float* prow = psm + warp * 64;
        const bool has2 = (lane + 32) < NT;
        const int m1 = lane;
        const int m2 = has2 ? lane + 32 : 48;
        const int rm1 = m1 / 7, cm1 = m1 % 7;
        const int rm2 = m2 / 7, cm2 = m2 % 7;
        const __half2* k1 = (const __half2*)(qkvsh + m1 * QKS + 192 + h * 32);
        const __half2* k2 = (const __half2*)(qkvsh + m2 * QKS + 192 + h * 32);

        for (int n = 0; n < NT; n++) {
            const int rn = n / 7, cn = n % 7;
            const __half2* qn = (const __half2*)(qkvsh + n * QKS + h * 32);
            float a1 = 0.f, a2 = 0.f;
#pragma unroll
            for (int d = 0; d < 16; d++) {
                float2 qv = __half22float2(qn[d]);
                float2 kv1 = __half22float2(k1[d]);
                float2 kv2 = __half22float2(k2[d]);
                a1 += qv.x * kv1.x + qv.y * kv1.y;
                a2 += qv.x * kv2.x + qv.y * kv2.y;
            }
            float s1 = a1 + __ldg(rel_table + ((rn - rm1 + 6) * 13 + (cn - cm1 + 6)) * NHEAD + h)
                          + wstf[n * 49 + m1];
            float s2 = has2
                ? a2 + __ldg(rel_table + ((rn - rm2 + 6) * 13 + (cn - cm2 + 6)) * NHEAD + h)
                     + wstf[n * 49 + m2]
                : -1e30f;
            float mx = fmaxf(s1, s2);
#pragma unroll
            for (int o = 16; o > 0; o >>= 1)
                mx = fmaxf(mx, __shfl_xor_sync(0xffffffffu, mx, o));
            float e1 = __expf(s1 - mx);
            float e2 = has2 ? __expf(s2 - mx) : 0.f;
            float sum = e1 + e2;
#pragma unroll
            for (int o = 16; o > 0; o >>= 1)
                sum += __shfl_xor_sync(0xffffffffu, sum, o);
            prow[lane]      = e1;
            prow[lane + 32] = e2;
            __syncwarp();
            float acco = 0.f;
#pragma unroll 7
            for (int m = 0; m < NT; m++)
                acco += prow[m] * __half2float(qkvsh[m * QKS + 384 + h * 32 + lane]);
            xwh[n * XW_STRH + h * 32 + lane] = __float2half(acco * (1.f / sum));
            __syncwarp();
        }
    }

    // ---- Phase 4: proj via f16 mma, fused residual scatter ----
    {
        float4 acc[12];
#pragma unroll
        for (int t = 0; t < 12; t++) acc[t] = make_float4(0.f, 0.f, 0.f, 0.f);

        for (int kc = 0; kc < 192; kc += 32) {
            __syncthreads();
            for (int idx = tid; idx < 3072; idx += 256) {
                int n = idx >> 4, kk = idx & 15;
                wstu[n * 20 + kk] = projT_u[n * 96 + (kc >> 1) + kk];
            }
            __syncthreads();
#pragma unroll
            for (int k0 = 0; k0 < 32; k0 += 16) {
                int kw = (kc + k0) >> 1;
                uint32_t a0 = xwu[rowA * 100 + kw + q];
                uint32_t a1 = xwu[(rowA + 8) * 100 + kw + q];
                uint32_t a2 = xwu[rowA * 100 + kw + q + 4];
                uint32_t a3 = xwu[(rowA + 8) * 100 + kw + q + 4];
#pragma unroll
                for (int t = 0; t < 12; t++) {
                    int col = 96 * wn + 8 * t + g;
                    uint32_t b0 = wstu[col * 20 + (k0 >> 1) + q];
                    uint32_t b1 = wstu[col * 20 + (k0 >> 1) + q + 4];
                    mma16(acc[t], a0, a1, a2, a3, b0, b1);
                }
            }
        }

        size_t base0 = 0, base1 = 0;
        if (v0) {
            int gr = wh * 7 + rowA / 7 + 3; if (gr >= 56) gr -= 56;
            int gc = ww * 7 + rowA % 7 + 3; if (gc >= 56) gc -= 56;
            base0 = ((size_t)b * 3136 + gr * 56 + gc) * Cc;
        }
        if (v1) {
            int r1i = rowA + 8;
            int gr = wh * 7 + r1i / 7 + 3; if (gr >= 56) gr -= 56;
            int gc = ww * 7 + r1i % 7 + 3; if (gc >= 56) gc -= 56;
            base1 = ((size_t)b * 3136 + gr * 56 + gc) * Cc;
        }
#pragma unroll
        for (int t = 0; t < 12; t++) {
            int col = 96 * wn + 8 * t + 2 * q;
            float pb0 = __ldg(proj_b + col), pb1 = __ldg(proj_b + col + 1);
            if (v0) {
                float2 xv = *(const float2*)(x + base0 + col);
                float2 r; r.x = xv.x + acc[t].x + pb0; r.y = xv.y + acc[t].y + pb1;
                *(float2*)(g_x2 + base0 + col) = r;
            }
            if (v1) {
                float2 xv = *(const float2*)(x + base1 + col);
                float2 r; r.x = xv.x + acc[t].z + pb0; r.y = xv.y + acc[t].w + pb1;
                *(float2*)(g_x2 + base1 + col) = r;
            }
        }
    }
}

// ---------------------------------------------------------------------------
// Kernel 2: LN2 + MLP (f16 mma) + residual; 64 tokens/block, 1568 blocks
// smem (halves): xn[64][200] | f1s[64][200] | hs[64][72] | f2s[192][72]
// ---------------------------------------------------------------------------
#define OFF_F1_H 12800
#define OFF_HS_H 25600
#define OFF_F2_H 30208
#define MLP_SM_BYTES (44032 * 2)

__global__ __launch_bounds__(256, 2) void swin_mlp_kernel(
    const float* __restrict__ n2w, const float* __restrict__ n2b,
    const float* __restrict__ fc1b, const float* __restrict__ fc2b,
    float* __restrict__ out)
{
    extern __shared__ __half smh[];
    __half* xnh = smh;                   // [64][200]
    uint32_t* xnu  = (uint32_t*)xnh;
    uint32_t* f1u  = (uint32_t*)(smh + OFF_F1_H);   // [64][100] u32
    __half2*  hs2  = (__half2*)(smh + OFF_HS_H);    // [64][36] half2
    uint32_t* hsu  = (uint32_t*)(smh + OFF_HS_H);
    uint32_t* f2u  = (uint32_t*)(smh + OFF_F2_H);   // [192][36] u32
    const uint32_t* fc1T_u = (const uint32_t*)g_fc1T;
    const uint32_t* fc2T_u = (const uint32_t*)g_fc2T;

    const int tid  = threadIdx.x;
    const int warp = tid >> 5;
    const int lane = tid & 31;
    const int g    = lane >> 2;
    const int q    = lane & 3;
    const int wm   = warp & 3;
    const int wn   = warp >> 2;
    const int rowA = 16 * wm + g;
    const size_t t0 = (size_t)blockIdx.x * 64;

    // ---- LN2 ----
    for (int n = warp; n < 64; n += 8) {
        const float* xr = g_x2 + (t0 + n) * Cc;
        float v[6]; float s = 0.f, ss = 0.f;
#pragma unroll
        for (int j = 0; j < 6; j++) { v[j] = xr[lane + 32 * j]; s += v[j]; ss += v[j] * v[j]; }
#pragma unroll
        for (int o = 16; o > 0; o >>= 1) {
            s  += __shfl_xor_sync(0xffffffffu, s,  o);
            ss += __shfl_xor_sync(0xffffffffu, ss, o);
        }
        float mean = s * (1.f / 192.f);
        float rinv = rsqrtf(ss * (1.f / 192.f) - mean * mean + 1e-5f);
#pragma unroll
        for (int j = 0; j < 6; j++) {
            int k = lane + 32 * j;
            xnh[n * XW_STRH + k] = __float2half((v[j] - mean) * rinv * n2w[k] + n2b[k]);
        }
    }

    float4 yacc[12];
#pragma unroll
    for (int t = 0; t < 12; t++) yacc[t] = make_float4(0.f, 0.f, 0.f, 0.f);

    for (int hc = 0; hc < HIDDEN; hc += 64) {
        __syncthreads();
        // stage fc1T rows [hc..hc+63] full k (64x96 u32), fc2T k-chunk (192x32 u32)
        for (int idx = tid; idx < 6144; idx += 256) {
            int n = idx / 96, w = idx % 96;
            f1u[n * 100 + w] = fc1T_u[(size_t)(hc + n) * 96 + w];
        }
        for (int idx = tid; idx < 6144; idx += 256) {
            int n = idx >> 5, w = idx & 31;
            f2u[n * 36 + w] = fc2T_u[(size_t)n * 384 + (hc >> 1) + w];
        }
        __syncthreads();

        // fc1: H(64x64) = xn(64x192) @ w1chunk ; warp tile m16 x n32
        float4 acc1[4];
#pragma unroll
        for (int t = 0; t < 4; t++) acc1[t] = make_float4(0.f, 0.f, 0.f, 0.f);
#pragma unroll
        for (int k0 = 0; k0 < 192; k0 += 16) {
            int kw = k0 >> 1;
            uint32_t a0 = xnu[rowA * 100 + kw + q];
            uint32_t a1 = xnu[(rowA + 8) * 100 + kw + q];
            uint32_t a2 = xnu[rowA * 100 + kw + q + 4];
            uint32_t a3 = xnu[(rowA + 8) * 100 + kw + q + 4];
#pragma unroll
            for (int t = 0; t < 4; t++) {
                int col = 32 * wn + 8 * t + g;
                uint32_t b0 = f1u[col * 100 + kw + q];
                uint32_t b1 = f1u[col * 100 + kw + q + 4];
                mma16(acc1[t], a0, a1, a2, a3, b0, b1);
            }
        }
        // bias + gelu -> hs (half2 stores)
#pragma unroll
        for (int t = 0; t < 4; t++) {
            int col = 32 * wn + 8 * t + 2 * q;
            float b0v = __ldg(fc1b + hc + col), b1v = __ldg(fc1b + hc + col + 1);
            int wi = 16 * wn + 4 * t + q;   // half2 index within row
            hs2[rowA * 36 + wi]       = __floats2half2_rn(gelu_exact(acc1[t].x + b0v),
                                                          gelu_exact(acc1[t].y + b1v));
            hs2[(rowA + 8) * 36 + wi] = __floats2half2_rn(gelu_exact(acc1[t].z + b0v),
                                                          gelu_exact(acc1[t].w + b1v));
        }
        __syncthreads();

        // fc2: Y(64x192) += H(64x64) @ w2chunk ; warp tile m16 x n96
#pragma unroll
        for (int k0 = 0; k0 < 64; k0 += 16) {
            int kw = k0 >> 1;
            uint32_t a0 = hsu[rowA * 36 + kw + q];
            uint32_t a1 = hsu[(rowA + 8) * 36 + kw + q];
            uint32_t a2 = hsu[rowA * 36 + kw + q + 4];
            uint32_t a3 = hsu[(rowA + 8) * 36 + kw + q + 4];
#pragma unroll
            for (int t = 0; t < 12; t++) {
                int col = 96 * wn + 8 * t + g;
                uint32_t b0 = f2u[col * 36 + kw + q];
                uint32_t b1 = f2u[col * 36 + kw + q + 4];
                mma16(yacc[t], a0, a1, a2, a3, b0, b1);
            }
        }
    }

    // ---- epilogue: out = g_x2 + Y + fc2_b ----
#pragma unroll
    for (int t = 0; t < 12; t++) {
        int col = 96 * wn + 8 * t + 2 * q;
        float b0v = __ldg(fc2b + col), b1v = __ldg(fc2b + col + 1);
        {
            size_t base = (t0 + rowA) * Cc + col;
            float2 xv = *(const float2*)(g_x2 + base);
            float2 r; r.x = xv.x + yacc[t].x + b0v; r.y = xv.y + yacc[t].y + b1v;
            *(float2*)(out + base) = r;
        }
        {
            size_t base = (t0 + rowA + 8) * Cc + col;
            float2 xv = *(const float2*)(g_x2 + base);
            float2 r; r.x = xv.x + yacc[t].z + b0v; r.y = xv.y + yacc[t].w + b1v;
            *(float2*)(out + base) = r;
        }
    }
}

// ---------------------------------------------------------------------------
extern "C" void kernel_launch(void* const* d_in, const int* in_sizes, int n_in,
                              void* d_out, int out_size)
{
    const float* x      = (const float*)d_in[0];
    const float* mask   = (const float*)d_in[1];
    const float* rel    = (const float*)d_in[2];
    const float* qkv_w  = (const float*)d_in[3];
    const float* qkv_b  = (const float*)d_in[4];
    const float* proj_w = (const float*)d_in[5];
    const float* proj_b = (const float*)d_in[6];
    const float* n1w    = (const float*)d_in[7];
    const float* n1b    = (const float*)d_in[8];
    const float* n2w    = (const float*)d_in[9];
    const float* n2b    = (const float*)d_in[10];
    const float* fc1w   = (const float*)d_in[11];
    const float* fc1b   = (const float*)d_in[12];
    const float* fc2w   = (const float*)d_in[13];
    const float* fc2b   = (const float*)d_in[14];
    float* out = (float*)d_out;

    cudaFuncSetAttribute(swin_attn_kernel, cudaFuncAttributeMaxDynamicSharedMemorySize,
                         ATTN_SM_BYTES);
    cudaFuncSetAttribute(swin_mlp_kernel, cudaFuncAttributeMaxDynamicSharedMemorySize,
                         MLP_SM_BYTES);

    convert_w<<<192, 256>>>(qkv_w, proj_w, fc1w, fc2w);
    swin_attn_kernel<<<Bn * 64, 256, ATTN_SM_BYTES>>>(
        x, mask, rel, qkv_b, proj_b, n1w, n1b);
    swin_mlp_kernel<<<1568, 256, MLP_SM_BYTES>>>(
        n2w, n2b, fc1b, fc2b, out);
}

// round 6
// speedup vs baseline: 4.4653x; 1.4948x over previous
#include <cuda_runtime.h>
#include <cuda_fp16.h>
#include <math.h>
#include <stdint.h>

#define Bn 32
#define Cc 192
#define WSZ 7
#define NHEAD 6
#define NT 49
#define HIDDEN 768
#define SCALE 0.17677669529663687f

// scratch for x + attention residual
__device__ float g_x2[(size_t)Bn * 56 * 56 * Cc];

// pre-transposed fp16 weights, [n][k] layout
__device__ __align__(16) __half g_qkvT[576 * 192];
__device__ __align__(16) __half g_projT[192 * 192];
__device__ __align__(16) __half g_fc1T[768 * 192];
__device__ __align__(16) __half g_fc2T[192 * 768];
// fused rel-pos bias + shift mask, padded: [win 64][head 6][row 64][col 56]
__device__ __align__(16) __half g_bias[64 * 6 * 64 * 56];

__global__ void convert_w(const float* __restrict__ qkv_w, const float* __restrict__ proj_w,
                          const float* __restrict__ fc1w, const float* __restrict__ fc2w,
                          const float* __restrict__ mask, const float* __restrict__ rel_table)
{
    int tid = blockIdx.x * blockDim.x + threadIdx.x;
    int stride = gridDim.x * blockDim.x;
    for (int j = tid; j < 192 * 576; j += stride) {
        int k = j / 576, n = j % 576;
        g_qkvT[n * 192 + k] = __float2half(qkv_w[j]);
    }
    for (int j = tid; j < 192 * 192; j += stride) {
        int k = j / 192, n = j % 192;
        g_projT[n * 192 + k] = __float2half(proj_w[j]);
    }
    for (int j = tid; j < 192 * 768; j += stride) {
        int k = j / 768, n = j % 768;
        g_fc1T[n * 192 + k] = __float2half(fc1w[j]);
    }
    for (int j = tid; j < 768 * 192; j += stride) {
        int k = j / 192, n = j % 192;
        g_fc2T[n * 768 + k] = __float2half(fc2w[j]);
    }
    for (int j = tid; j < 64 * 6 * 64 * 56; j += stride) {
        int col = j % 56;
        int rest = j / 56;
        int row = rest % 64; rest /= 64;
        int h = rest % 6;
        int w = rest / 6;
        float v;
        if (row >= NT)      v = 0.f;
        else if (col >= NT) v = -30000.f;
        else {
            int rr = row / 7 - col / 7 + 6;
            int cc = row % 7 - col % 7 + 6;
            v = rel_table[(rr * 13 + cc) * NHEAD + h] + mask[w * 2401 + row * 49 + col];
        }
        g_bias[j] = __float2half(v);
    }
}

// D = A(16x16 f16, row) x B(16x8 f16, col) + D, fp32 accum
__device__ __forceinline__ void mma16(float4& c, uint32_t a0, uint32_t a1, uint32_t a2,
                                      uint32_t a3, uint32_t b0, uint32_t b1) {
    asm volatile(
        "mma.sync.aligned.m16n8k16.row.col.f32.f16.f16.f32 "
        "{%0,%1,%2,%3},{%4,%5,%6,%7},{%8,%9},{%0,%1,%2,%3};"
        : "+f"(c.x), "+f"(c.y), "+f"(c.z), "+f"(c.w)
        : "r"(a0), "r"(a1), "r"(a2), "r"(a3), "r"(b0), "r"(b1));
}

__device__ __forceinline__ uint32_t packh2(float a, float b) {
    __half2 h = __floats2half2_rn(a, b);
    return *(uint32_t*)&h;
}

__device__ __forceinline__ float gelu_exact(float v) {
    return 0.5f * v * (1.0f + erff(v * 0.70710678118654752f));
}

// ---------------------------------------------------------------------------
// Kernel 1: per-window LN1 -> QKV(mma) -> mma attention -> proj(mma)
// smem halves: xw[64][200] | qk[56][392] (Q|K) | vT[192][68] | wst[192][40]
// ---------------------------------------------------------------------------
#define XW_STRH 200
#define QK_STRH 392           // 196 u32/row
#define VT_STRH 68            // 34 u32/row
#define OFF_QK_H 12800
#define OFF_VT_H 34752
#define OFF_WST_H 47808
#define ATTN_SM_BYTES (55488 * 2)

__global__ __launch_bounds__(256, 2) void swin_attn_kernel(
    const float* __restrict__ x,
    const float* __restrict__ qkv_b, const float* __restrict__ proj_b,
    const float* __restrict__ n1w, const float* __restrict__ n1b)
{
    extern __shared__ __half smh[];
    __half* xwh = smh;                   // [64][200]  LN1 out / attn out
    __half* qkh = smh + OFF_QK_H;        // [56][392]  Q(0..191) K(192..383)
    __half* vth = smh + OFF_VT_H;        // [192][68]  V transposed
    uint32_t* xwu  = (uint32_t*)xwh;
    uint32_t* qku  = (uint32_t*)qkh;
    uint32_t* vtu  = (uint32_t*)vth;
    uint32_t* wstu = (uint32_t*)(smh + OFF_WST_H);   // [192][20] u32 weight stage
    const uint32_t* qkvT_u  = (const uint32_t*)g_qkvT;
    const uint32_t* projT_u = (const uint32_t*)g_projT;

    const int bid  = blockIdx.x;
    const int b    = bid >> 6;
    const int w    = bid & 63;
    const int wh   = w >> 3;
    const int ww   = w & 7;
    const int tid  = threadIdx.x;
    const int warp = tid >> 5;
    const int lane = tid & 31;
    const int g    = lane >> 2;
    const int q    = lane & 3;
    const int wm   = warp & 3;
    const int wn   = warp >> 2;
    const int rowA = 16 * wm + g;

    // ---- zero pad regions: QK rows 49..55 and all of vT (pad keys must be 0) ----
    for (int idx = tid; idx < 192 * 34; idx += 256) vtu[idx] = 0u;
    for (int idx = tid; idx < 7 * 196; idx += 256) qku[(49 + idx / 196) * 196 + idx % 196] = 0u;

    // ---- Phase 1: gather (shifted window) + LN1 (xw rows>=49 zeroed) ----
    for (int n = warp; n < 64; n += 8) {
        if (n < NT) {
            int r  = wh * WSZ + n / WSZ;
            int c  = ww * WSZ + n % WSZ;
            int gr = r + 3; if (gr >= 56) gr -= 56;
            int gc = c + 3; if (gc >= 56) gc -= 56;
            const float* xr = x + ((size_t)b * 3136 + gr * 56 + gc) * Cc;
            float v[6]; float s = 0.f, ss = 0.f;
#pragma unroll
            for (int j = 0; j < 6; j++) { v[j] = xr[lane + 32 * j]; s += v[j]; ss += v[j] * v[j]; }
#pragma unroll
            for (int o = 16; o > 0; o >>= 1) {
                s  += __shfl_xor_sync(0xffffffffu, s,  o);
                ss += __shfl_xor_sync(0xffffffffu, ss, o);
            }
            float mean = s * (1.f / 192.f);
            float rinv = rsqrtf(ss * (1.f / 192.f) - mean * mean + 1e-5f);
#pragma unroll
            for (int j = 0; j < 6; j++) {
                int k = lane + 32 * j;
                xwh[n * XW_STRH + k] = __float2half((v[j] - mean) * rinv * n1w[k] + n1b[k]);
            }
        } else {
#pragma unroll
            for (int j = 0; j < 3; j++) xwu[n * 100 + lane + 32 * j] = 0u;
        }
    }

    // ---- Phase 2: QKV via f16 mma : out(64x192) per pass ----
    const bool v0 = rowA < NT, v1 = (rowA + 8) < NT;
    for (int p = 0; p < 3; p++) {
        float4 acc[12];
#pragma unroll
        for (int t = 0; t < 12; t++) acc[t] = make_float4(0.f, 0.f, 0.f, 0.f);

        for (int kc = 0; kc < 192; kc += 32) {
            __syncthreads();
            for (int idx = tid; idx < 3072; idx += 256) {
                int n = idx >> 4, kk = idx & 15;
                wstu[n * 20 + kk] = qkvT_u[(p * 192 + n) * 96 + (kc >> 1) + kk];
            }
            __syncthreads();
#pragma unroll
            for (int k0 = 0; k0 < 32; k0 += 16) {
                int kw = (kc + k0) >> 1;
                uint32_t a0 = xwu[rowA * 100 + kw + q];
                uint32_t a1 = xwu[(rowA + 8) * 100 + kw + q];
                uint32_t a2 = xwu[rowA * 100 + kw + q + 4];
                uint32_t a3 = xwu[(rowA + 8) * 100 + kw + q + 4];
#pragma unroll
                for (int t = 0; t < 12; t++) {
                    int col = 96 * wn + 8 * t + g;
                    uint32_t b0 = wstu[col * 20 + (k0 >> 1) + q];
                    uint32_t b1 = wstu[col * 20 + (k0 >> 1) + q + 4];
                    mma16(acc[t], a0, a1, a2, a3, b0, b1);
                }
            }
        }
#pragma unroll
        for (int t = 0; t < 12; t++) {
            int col = 96 * wn + 8 * t + 2 * q;
            int j   = 192 * p + col;
            float b0v = __ldg(qkv_b + j), b1v = __ldg(qkv_b + j + 1);
            float o00 = acc[t].x + b0v, o01 = acc[t].y + b1v;
            float o10 = acc[t].z + b0v, o11 = acc[t].w + b1v;
            if (p == 0) { o00 *= SCALE; o01 *= SCALE; o10 *= SCALE; o11 *= SCALE; }
            if (p < 2) {
                if (v0) *(__half2*)(qkh + rowA * QK_STRH + j)       = __floats2half2_rn(o00, o01);
                if (v1) *(__half2*)(qkh + (rowA + 8) * QK_STRH + j) = __floats2half2_rn(o10, o11);
            } else {
                // V transposed: vT[dim][key]
                if (v0) {
                    vth[col * VT_STRH + rowA]       = __float2half(o00);
                    vth[(col + 1) * VT_STRH + rowA] = __float2half(o01);
                }
                if (v1) {
                    vth[col * VT_STRH + rowA + 8]       = __float2half(o10);
                    vth[(col + 1) * VT_STRH + rowA + 8] = __float2half(o11);
                }
            }
        }
    }
    __syncthreads();

    // ---- Phase 3: mma attention, warp = head ----
    if (warp < NHEAD) {
        const int h = warp;
        const __half* bias = g_bias + ((size_t)(w * NHEAD + h)) * 64 * 56;
#pragma unroll 1
        for (int i = 0; i < 4; i++) {
            const int r0i = 16 * i + g, r1i = r0i + 8;
            // Q A-fragments (2 k-steps)
            uint32_t aq[2][4];
#pragma unroll
            for (int kk = 0; kk < 2; kk++) {
                int base = r0i * 196 + h * 16 + 8 * kk + q;
                aq[kk][0] = qku[base];
                aq[kk][1] = qku[base + 8 * 196];
                aq[kk][2] = qku[base + 4];
                aq[kk][3] = qku[base + 8 * 196 + 4];
            }
            // S = Q K^T + bias
            float4 S[7];
#pragma unroll
            for (int j = 0; j < 7; j++) {
                S[j] = make_float4(0.f, 0.f, 0.f, 0.f);
                int kb = (8 * j + g) * 196 + 96 + h * 16;
#pragma unroll
                for (int kk = 0; kk < 2; kk++)
                    mma16(S[j], aq[kk][0], aq[kk][1], aq[kk][2], aq[kk][3],
                          qku[kb + 8 * kk + q], qku[kb + 8 * kk + q + 4]);
                float2 b0 = __half22float2(*(const __half2*)(bias + r0i * 56 + 8 * j + 2 * q));
                float2 b1 = __half22float2(*(const __half2*)(bias + r1i * 56 + 8 * j + 2 * q));
                S[j].x += b0.x; S[j].y += b0.y; S[j].z += b1.x; S[j].w += b1.y;
            }
            // row softmax (rows r0i, r1i) via quad reduction
            float mx0 = -1e30f, mx1 = -1e30f;
#pragma unroll
            for (int j = 0; j < 7; j++) {
                mx0 = fmaxf(mx0, fmaxf(S[j].x, S[j].y));
                mx1 = fmaxf(mx1, fmaxf(S[j].z, S[j].w));
            }
#pragma unroll
            for (int o = 1; o < 4; o <<= 1) {
                mx0 = fmaxf(mx0, __shfl_xor_sync(0xffffffffu, mx0, o));
                mx1 = fmaxf(mx1, __shfl_xor_sync(0xffffffffu, mx1, o));
            }
            float sum0 = 0.f, sum1 = 0.f;
#pragma unroll
            for (int j = 0; j < 7; j++) {
                S[j].x = __expf(S[j].x - mx0); S[j].y = __expf(S[j].y - mx0);
                S[j].z = __expf(S[j].z - mx1); S[j].w = __expf(S[j].w - mx1);
                sum0 += S[j].x + S[j].y; sum1 += S[j].z + S[j].w;
            }
#pragma unroll
            for (int o = 1; o < 4; o <<= 1) {
                sum0 += __shfl_xor_sync(0xffffffffu, sum0, o);
                sum1 += __shfl_xor_sync(0xffffffffu, sum1, o);
            }
            float rc0 = 1.f / sum0, rc1 = 1.f / sum1;
            // pack P into A-fragments (C-layout == A-layout identity)
            uint32_t pa[4][4];
#pragma unroll
            for (int kk = 0; kk < 3; kk++) {
                pa[kk][0] = packh2(S[2 * kk].x, S[2 * kk].y);
                pa[kk][1] = packh2(S[2 * kk].z, S[2 * kk].w);
                pa[kk][2] = packh2(S[2 * kk + 1].x, S[2 * kk + 1].y);
                pa[kk][3] = packh2(S[2 * kk + 1].z, S[2 * kk + 1].w);
            }
            pa[3][0] = packh2(S[6].x, S[6].y);
            pa[3][1] = packh2(S[6].z, S[6].w);
            pa[3][2] = 0u; pa[3][3] = 0u;
            // O = P V  (V from vT, pad keys zeroed) — NOTE head offset h*32 in dim
            float4 O[4];
#pragma unroll
            for (int vj = 0; vj < 4; vj++) O[vj] = make_float4(0.f, 0.f, 0.f, 0.f);
#pragma unroll
            for (int kk = 0; kk < 4; kk++) {
#pragma unroll
                for (int vj = 0; vj < 4; vj++) {
                    int vb = (h * 32 + 8 * vj + g) * 34 + 8 * kk + q;
                    mma16(O[vj], pa[kk][0], pa[kk][1], pa[kk][2], pa[kk][3],
                          vtu[vb], vtu[vb + 4]);
                }
            }
            // store normalized rows (<49) into xw
#pragma unroll
            for (int vj = 0; vj < 4; vj++) {
                int col = h * 32 + 8 * vj + 2 * q;
                if (r0i < NT)
                    *(__half2*)(xwh + r0i * XW_STRH + col) =
                        __floats2half2_rn(O[vj].x * rc0, O[vj].y * rc0);
                if (r1i < NT)
                    *(__half2*)(xwh + r1i * XW_STRH + col) =
                        __floats2half2_rn(O[vj].z * rc1, O[vj].w * rc1);
            }
        }
    }

    // ---- Phase 4: proj via f16 mma, fused residual scatter ----
    {
        float4 acc[12];
#pragma unroll
        for (int t = 0; t < 12; t++) acc[t] = make_float4(0.f, 0.f, 0.f, 0.f);

        for (int kc = 0; kc < 192; kc += 32) {
            __syncthreads();
            for (int idx = tid; idx < 3072; idx += 256) {
                int n = idx >> 4, kk = idx & 15;
                wstu[n * 20 + kk] = projT_u[n * 96 + (kc >> 1) + kk];
            }
            __syncthreads();
#pragma unroll
            for (int k0 = 0; k0 < 32; k0 += 16) {
                int kw = (kc + k0) >> 1;
                uint32_t a0 = xwu[rowA * 100 + kw + q];
                uint32_t a1 = xwu[(rowA + 8) * 100 + kw + q];
                uint32_t a2 = xwu[rowA * 100 + kw + q + 4];
                uint32_t a3 = xwu[(rowA + 8) * 100 + kw + q + 4];
#pragma unroll
                for (int t = 0; t < 12; t++) {
                    int col = 96 * wn + 8 * t + g;
                    uint32_t b0 = wstu[col * 20 + (k0 >> 1) + q];
                    uint32_t b1 = wstu[col * 20 + (k0 >> 1) + q + 4];
                    mma16(acc[t], a0, a1, a2, a3, b0, b1);
                }
            }
        }

        size_t base0 = 0, base1 = 0;
        if (v0) {
            int gr = wh * 7 + rowA / 7 + 3; if (gr >= 56) gr -= 56;
            int gc = ww * 7 + rowA % 7 + 3; if (gc >= 56) gc -= 56;
            base0 = ((size_t)b * 3136 + gr * 56 + gc) * Cc;
        }
        if (v1) {
            int r1i = rowA + 8;
            int gr = wh * 7 + r1i / 7 + 3; if (gr >= 56) gr -= 56;
            int gc = ww * 7 + r1i % 7 + 3; if (gc >= 56) gc -= 56;
            base1 = ((size_t)b * 3136 + gr * 56 + gc) * Cc;
        }
#pragma unroll
        for (int t = 0; t < 12; t++) {
            int col = 96 * wn + 8 * t + 2 * q;
            float pb0 = __ldg(proj_b + col), pb1 = __ldg(proj_b + col + 1);
            if (v0) {
                float2 xv = *(const float2*)(x + base0 + col);
                float2 r; r.x = xv.x + acc[t].x + pb0; r.y = xv.y + acc[t].y + pb1;
                *(float2*)(g_x2 + base0 + col) = r;
            }
            if (v1) {
                float2 xv = *(const float2*)(x + base1 + col);
                float2 r; r.x = xv.x + acc[t].z + pb0; r.y = xv.y + acc[t].w + pb1;
                *(float2*)(g_x2 + base1 + col) = r;
            }
        }
    }
}

// ---------------------------------------------------------------------------
// Kernel 2: LN2 + MLP (f16 mma) + residual; 64 tokens/block, 1568 blocks
// ---------------------------------------------------------------------------
#define OFF_F1_H 12800
#define OFF_HS_H 25600
#define OFF_F2_H 30208
#define MLP_SM_BYTES (44032 * 2)

__global__ __launch_bounds__(256, 2) void swin_mlp_kernel(
    const float* __restrict__ n2w, const float* __restrict__ n2b,
    const float* __restrict__ fc1b, const float* __restrict__ fc2b,
    float* __restrict__ out)
{
    extern __shared__ __half smh[];
    __half* xnh = smh;                   // [64][200]
    uint32_t* xnu  = (uint32_t*)xnh;
    uint32_t* f1u  = (uint32_t*)(smh + OFF_F1_H);   // [64][100] u32
    __half2*  hs2  = (__half2*)(smh + OFF_HS_H);    // [64][36] half2
    uint32_t* hsu  = (uint32_t*)(smh + OFF_HS_H);
    uint32_t* f2u  = (uint32_t*)(smh + OFF_F2_H);   // [192][36] u32
    const uint32_t* fc1T_u = (const uint32_t*)g_fc1T;
    const uint32_t* fc2T_u = (const uint32_t*)g_fc2T;

    const int tid  = threadIdx.x;
    const int warp = tid >> 5;
    const int lane = tid & 31;
    const int g    = lane >> 2;
    const int q    = lane & 3;
    const int wm   = warp & 3;
    const int wn   = warp >> 2;
    const int rowA = 16 * wm + g;
    const size_t t0 = (size_t)blockIdx.x * 64;

    // ---- LN2 ----
    for (int n = warp; n < 64; n += 8) {
        const float* xr = g_x2 + (t0 + n) * Cc;
        float v[6]; float s = 0.f, ss = 0.f;
#pragma unroll
        for (int j = 0; j < 6; j++) { v[j] = xr[lane + 32 * j]; s += v[j]; ss += v[j] * v[j]; }
#pragma unroll
        for (int o = 16; o > 0; o >>= 1) {
            s  += __shfl_xor_sync(0xffffffffu, s,  o);
            ss += __shfl_xor_sync(0xffffffffu, ss, o);
        }
        float mean = s * (1.f / 192.f);
        float rinv = rsqrtf(ss * (1.f / 192.f) - mean * mean + 1e-5f);
#pragma unroll
        for (int j = 0; j < 6; j++) {
            int k = lane + 32 * j;
            xnh[n * XW_STRH + k] = __float2half((v[j] - mean) * rinv * n2w[k] + n2b[k]);
        }
    }

    float4 yacc[12];
#pragma unroll
    for (int t = 0; t < 12; t++) yacc[t] = make_float4(0.f, 0.f, 0.f, 0.f);

    for (int hc = 0; hc < HIDDEN; hc += 64) {
        __syncthreads();
        for (int idx = tid; idx < 6144; idx += 256) {
            int n = idx / 96, w = idx % 96;
            f1u[n * 100 + w] = fc1T_u[(size_t)(hc + n) * 96 + w];
        }
        for (int idx = tid; idx < 6144; idx += 256) {
            int n = idx >> 5, w = idx & 31;
            f2u[n * 36 + w] = fc2T_u[(size_t)n * 384 + (hc >> 1) + w];
        }
        __syncthreads();

        float4 acc1[4];
#pragma unroll
        for (int t = 0; t < 4; t++) acc1[t] = make_float4(0.f, 0.f, 0.f, 0.f);
#pragma unroll
        for (int k0 = 0; k0 < 192; k0 += 16) {
            int kw = k0 >> 1;
            uint32_t a0 = xnu[rowA * 100 + kw + q];
            uint32_t a1 = xnu[(rowA + 8) * 100 + kw + q];
            uint32_t a2 = xnu[rowA * 100 + kw + q + 4];
            uint32_t a3 = xnu[(rowA + 8) * 100 + kw + q + 4];
#pragma unroll
            for (int t = 0; t < 4; t++) {
                int col = 32 * wn + 8 * t + g;
                uint32_t b0 = f1u[col * 100 + kw + q];
                uint32_t b1 = f1u[col * 100 + kw + q + 4];
                mma16(acc1[t], a0, a1, a2, a3, b0, b1);
            }
        }
#pragma unroll
        for (int t = 0; t < 4; t++) {
            int col = 32 * wn + 8 * t + 2 * q;
            float b0v = __ldg(fc1b + hc + col), b1v = __ldg(fc1b + hc + col + 1);
            int wi = 16 * wn + 4 * t + q;
            hs2[rowA * 36 + wi]       = __floats2half2_rn(gelu_exact(acc1[t].x + b0v),
                                                          gelu_exact(acc1[t].y + b1v));
            hs2[(rowA + 8) * 36 + wi] = __floats2half2_rn(gelu_exact(acc1[t].z + b0v),
                                                          gelu_exact(acc1[t].w + b1v));
        }
        __syncthreads();

#pragma unroll
        for (int k0 = 0; k0 < 64; k0 += 16) {
            int kw = k0 >> 1;
            uint32_t a0 = hsu[rowA * 36 + kw + q];
            uint32_t a1 = hsu[(rowA + 8) * 36 + kw + q];
            uint32_t a2 = hsu[rowA * 36 + kw + q + 4];
            uint32_t a3 = hsu[(rowA + 8) * 36 + kw + q + 4];
#pragma unroll
            for (int t = 0; t < 12; t++) {
                int col = 96 * wn + 8 * t + g;
                uint32_t b0 = f2u[col * 36 + kw + q];
                uint32_t b1 = f2u[col * 36 + kw + q + 4];
                mma16(yacc[t], a0, a1, a2, a3, b0, b1);
            }
        }
    }

#pragma unroll
    for (int t = 0; t < 12; t++) {
        int col = 96 * wn + 8 * t + 2 * q;
        float b0v = __ldg(fc2b + col), b1v = __ldg(fc2b + col + 1);
        {
            size_t base = (t0 + rowA) * Cc + col;
            float2 xv = *(const float2*)(g_x2 + base);
            float2 r; r.x = xv.x + yacc[t].x + b0v; r.y = xv.y + yacc[t].y + b1v;
            *(float2*)(out + base) = r;
        }
        {
            size_t base = (t0 + rowA + 8) * Cc + col;
            float2 xv = *(const float2*)(g_x2 + base);
            float2 r; r.x = xv.x + yacc[t].z + b0v; r.y = xv.y + yacc[t].w + b1v;
            *(float2*)(out + base) = r;
        }
    }
}

// ---------------------------------------------------------------------------
extern "C" void kernel_launch(void* const* d_in, const int* in_sizes, int n_in,
                              void* d_out, int out_size)
{
    const float* x      = (const float*)d_in[0];
    const float* mask   = (const float*)d_in[1];
    const float* rel    = (const float*)d_in[2];
    const float* qkv_w  = (const float*)d_in[3];
    const float* qkv_b  = (const float*)d_in[4];
    const float* proj_w = (const float*)d_in[5];
    const float* proj_b = (const float*)d_in[6];
    const float* n1w    = (const float*)d_in[7];
    const float* n1b    = (const float*)d_in[8];
    const float* n2w    = (const float*)d_in[9];
    const float* n2b    = (const float*)d_in[10];
    const float* fc1w   = (const float*)d_in[11];
    const float* fc1b   = (const float*)d_in[12];
    const float* fc2w   = (const float*)d_in[13];
    const float* fc2b   = (const float*)d_in[14];
    float* out = (float*)d_out;

    cudaFuncSetAttribute(swin_attn_kernel, cudaFuncAttributeMaxDynamicSharedMemorySize,
                         ATTN_SM_BYTES);
    cudaFuncSetAttribute(swin_mlp_kernel, cudaFuncAttributeMaxDynamicSharedMemorySize,
                         MLP_SM_BYTES);

    convert_w<<<296, 256>>>(qkv_w, proj_w, fc1w, fc2w, mask, rel);
    swin_attn_kernel<<<Bn * 64, 256, ATTN_SM_BYTES>>>(x, qkv_b, proj_b, n1w, n1b);
    swin_mlp_kernel<<<1568, 256, MLP_SM_BYTES>>>(n2w, n2b, fc1b, fc2b, out);
}

// round 7
// speedup vs baseline: 4.5722x; 1.0239x over previous
#include <cuda_runtime.h>
#include <cuda_fp16.h>
#include <math.h>
#include <stdint.h>

#define Bn 32
#define Cc 192
#define WSZ 7
#define NHEAD 6
#define NT 49
#define HIDDEN 768
#define SCALE 0.17677669529663687f

// scratch for x + attention residual
__device__ float g_x2[(size_t)Bn * 56 * 56 * Cc];

// pre-transposed fp16 weights, [n][k] layout
__device__ __align__(16) __half g_qkvT[576 * 192];
__device__ __align__(16) __half g_projT[192 * 192];
__device__ __align__(16) __half g_fc1T[768 * 192];
__device__ __align__(16) __half g_fc2T[192 * 768];
// fused rel-pos bias + shift mask, padded: [win 64][head 6][row 64][col 56]
__device__ __align__(16) __half g_bias[64 * 6 * 64 * 56];

__global__ void convert_w(const float* __restrict__ qkv_w, const float* __restrict__ proj_w,
                          const float* __restrict__ fc1w, const float* __restrict__ fc2w,
                          const float* __restrict__ mask, const float* __restrict__ rel_table)
{
    int tid = blockIdx.x * blockDim.x + threadIdx.x;
    int stride = gridDim.x * blockDim.x;
    for (int j = tid; j < 192 * 576; j += stride) {
        int k = j / 576, n = j % 576;
        g_qkvT[n * 192 + k] = __float2half(qkv_w[j]);
    }
    for (int j = tid; j < 192 * 192; j += stride) {
        int k = j / 192, n = j % 192;
        g_projT[n * 192 + k] = __float2half(proj_w[j]);
    }
    for (int j = tid; j < 192 * 768; j += stride) {
        int k = j / 768, n = j % 768;
        g_fc1T[n * 192 + k] = __float2half(fc1w[j]);
    }
    for (int j = tid; j < 768 * 192; j += stride) {
        int k = j / 192, n = j % 192;
        g_fc2T[n * 768 + k] = __float2half(fc2w[j]);
    }
    for (int j = tid; j < 64 * 6 * 64 * 56; j += stride) {
        int col = j % 56;
        int rest = j / 56;
        int row = rest % 64; rest /= 64;
        int h = rest % 6;
        int w = rest / 6;
        float v;
        if (row >= NT)      v = 0.f;
        else if (col >= NT) v = -30000.f;
        else {
            int rr = row / 7 - col / 7 + 6;
            int cc = row % 7 - col % 7 + 6;
            v = rel_table[(rr * 13 + cc) * NHEAD + h] + mask[w * 2401 + row * 49 + col];
        }
        g_bias[j] = __float2half(v);
    }
}

// D = A(16x16 f16, row) x B(16x8 f16, col) + D, fp32 accum
__device__ __forceinline__ void mma16(float4& c, uint32_t a0, uint32_t a1, uint32_t a2,
                                      uint32_t a3, uint32_t b0, uint32_t b1) {
    asm volatile(
        "mma.sync.aligned.m16n8k16.row.col.f32.f16.f16.f32 "
        "{%0,%1,%2,%3},{%4,%5,%6,%7},{%8,%9},{%0,%1,%2,%3};"
        : "+f"(c.x), "+f"(c.y), "+f"(c.z), "+f"(c.w)
        : "r"(a0), "r"(a1), "r"(a2), "r"(a3), "r"(b0), "r"(b1));
}

__device__ __forceinline__ uint32_t smaddr(const void* p) {
    return (uint32_t)__cvta_generic_to_shared(p);
}

__device__ __forceinline__ void ldsm4(uint32_t& r0, uint32_t& r1, uint32_t& r2,
                                      uint32_t& r3, uint32_t a) {
    asm volatile("ldmatrix.sync.aligned.m8n8.x4.shared.b16 {%0,%1,%2,%3},[%4];"
                 : "=r"(r0), "=r"(r1), "=r"(r2), "=r"(r3) : "r"(a));
}

__device__ __forceinline__ uint32_t packh2(float a, float b) {
    __half2 h = __floats2half2_rn(a, b);
    return *(uint32_t*)&h;
}

__device__ __forceinline__ float gelu_exact(float v) {
    return 0.5f * v * (1.0f + erff(v * 0.70710678118654752f));
}

// ---------------------------------------------------------------------------
// Kernel 1: per-window LN1 -> QKV(mma) -> mma attention -> proj(mma)
// smem halves: xw[64][200] | qk[56][392] (Q|K) | vT[192][72] | wst[192][40]
// ---------------------------------------------------------------------------
#define XW_STRH 200
#define QK_STRH 392
#define VT_STRH 72
#define OFF_QK_H 12800        // 64*200
#define OFF_VT_H 34752        // + 56*392
#define OFF_WST_H 48576       // + 192*72
#define ATTN_SM_BYTES (56256 * 2)

__global__ __launch_bounds__(256, 2) void swin_attn_kernel(
    const float* __restrict__ x,
    const float* __restrict__ qkv_b, const float* __restrict__ proj_b,
    const float* __restrict__ n1w, const float* __restrict__ n1b)
{
    extern __shared__ __half smh[];
    __half* xwh = smh;                   // [64][200]  LN1 out / attn out
    __half* qkh = smh + OFF_QK_H;        // [56][392]  Q(0..191) K(192..383)
    __half* vth = smh + OFF_VT_H;        // [192][72]  V transposed
    uint32_t* xwu  = (uint32_t*)xwh;
    uint32_t* vtu  = (uint32_t*)vth;
    uint32_t* wstu = (uint32_t*)(smh + OFF_WST_H);   // [192][20] u32 weight stage
    const uint32_t* qkvT_u  = (const uint32_t*)g_qkvT;
    const uint32_t* projT_u = (const uint32_t*)g_projT;

    const int bid  = blockIdx.x;
    const int b    = bid >> 6;
    const int w    = bid & 63;
    const int wh   = w >> 3;
    const int ww   = w & 7;
    const int tid  = threadIdx.x;
    const int warp = tid >> 5;
    const int lane = tid & 31;
    const int g    = lane >> 2;
    const int q    = lane & 3;
    const int wm   = warp & 3;
    const int wn   = warp >> 2;
    const int rowA = 16 * wm + g;
    const int lr   = lane & 7;
    const int lb8  = (lane >> 3) & 1;
    const int lb16 = lane >> 4;

    // ldmatrix bases for the big GEMM loops
    const uint32_t aBase = smaddr(xwh + (16 * wm + lr + 8 * lb8) * XW_STRH + 8 * lb16);
    const uint32_t bBase = smaddr((__half*)wstu + (96 * wn + 8 * lb16 + lr) * 40 + 8 * lb8);

    // ---- zero pad regions: QK rows 49..55 and all of vT (pad keys must be 0) ----
    for (int idx = tid; idx < 192 * 36; idx += 256) vtu[idx] = 0u;
    for (int idx = tid; idx < 7 * 196; idx += 256)
        ((uint32_t*)qkh)[(49 + idx / 196) * 196 + idx % 196] = 0u;

    // ---- Phase 1: gather (shifted window) + LN1 (xw rows>=49 zeroed) ----
    for (int n = warp; n < 64; n += 8) {
        if (n < NT) {
            int r  = wh * WSZ + n / WSZ;
            int c  = ww * WSZ + n % WSZ;
            int gr = r + 3; if (gr >= 56) gr -= 56;
            int gc = c + 3; if (gc >= 56) gc -= 56;
            const float* xr = x + ((size_t)b * 3136 + gr * 56 + gc) * Cc;
            float v[6]; float s = 0.f, ss = 0.f;
#pragma unroll
            for (int j = 0; j < 6; j++) { v[j] = xr[lane + 32 * j]; s += v[j]; ss += v[j] * v[j]; }
#pragma unroll
            for (int o = 16; o > 0; o >>= 1) {
                s  += __shfl_xor_sync(0xffffffffu, s,  o);
                ss += __shfl_xor_sync(0xffffffffu, ss, o);
            }
            float mean = s * (1.f / 192.f);
            float rinv = rsqrtf(ss * (1.f / 192.f) - mean * mean + 1e-5f);
#pragma unroll
            for (int j = 0; j < 6; j++) {
                int k = lane + 32 * j;
                xwh[n * XW_STRH + k] = __float2half((v[j] - mean) * rinv * n1w[k] + n1b[k]);
            }
        } else {
#pragma unroll
            for (int j = 0; j < 3; j++) xwu[n * 100 + lane + 32 * j] = 0u;
        }
    }

    // ---- Phase 2: QKV via f16 mma : out(64x192) per pass ----
    const bool v0 = rowA < NT, v1 = (rowA + 8) < NT;
    for (int p = 0; p < 3; p++) {
        float4 acc[12];
#pragma unroll
        for (int t = 0; t < 12; t++) acc[t] = make_float4(0.f, 0.f, 0.f, 0.f);

        for (int kc = 0; kc < 192; kc += 32) {
            __syncthreads();
            for (int idx = tid; idx < 768; idx += 256) {
                int n = idx >> 2, c = idx & 3;
                *(uint4*)(wstu + n * 20 + c * 4) =
                    *(const uint4*)(qkvT_u + (size_t)(p * 192 + n) * 96 + (kc >> 1) + c * 4);
            }
            __syncthreads();
#pragma unroll
            for (int k0 = 0; k0 < 32; k0 += 16) {
                uint32_t a0, a1, a2, a3;
                ldsm4(a0, a1, a2, a3, aBase + (kc + k0) * 2);
#pragma unroll
                for (int tp = 0; tp < 6; tp++) {
                    uint32_t b0, b1, b2, b3;
                    ldsm4(b0, b1, b2, b3, bBase + tp * 1280 + k0 * 2);
                    mma16(acc[2 * tp],     a0, a1, a2, a3, b0, b1);
                    mma16(acc[2 * tp + 1], a0, a1, a2, a3, b2, b3);
                }
            }
        }
#pragma unroll
        for (int t = 0; t < 12; t++) {
            int col = 96 * wn + 8 * t + 2 * q;
            int j   = 192 * p + col;
            float b0v = __ldg(qkv_b + j), b1v = __ldg(qkv_b + j + 1);
            float o00 = acc[t].x + b0v, o01 = acc[t].y + b1v;
            float o10 = acc[t].z + b0v, o11 = acc[t].w + b1v;
            if (p == 0) { o00 *= SCALE; o01 *= SCALE; o10 *= SCALE; o11 *= SCALE; }
            if (p < 2) {
                if (v0) *(__half2*)(qkh + rowA * QK_STRH + j)       = __floats2half2_rn(o00, o01);
                if (v1) *(__half2*)(qkh + (rowA + 8) * QK_STRH + j) = __floats2half2_rn(o10, o11);
            } else {
                if (v0) {
                    vth[col * VT_STRH + rowA]       = __float2half(o00);
                    vth[(col + 1) * VT_STRH + rowA] = __float2half(o01);
                }
                if (v1) {
                    vth[col * VT_STRH + rowA + 8]       = __float2half(o10);
                    vth[(col + 1) * VT_STRH + rowA + 8] = __float2half(o11);
                }
            }
        }
    }
    __syncthreads();

    // ---- Phase 3: mma attention, warp = head ----
    if (warp < NHEAD) {
        const int h = warp;
        const __half* bias = g_bias + ((size_t)(w * NHEAD + h)) * 64 * 56;
        const uint32_t kBase = smaddr(qkh + lr * QK_STRH + 192 + h * 32 + 8 * (lane >> 3));
        const uint32_t vBase = smaddr(vth + (h * 32 + lr) * VT_STRH + 8 * (lane >> 3));
#pragma unroll 1
        for (int i = 0; i < 4; i++) {
            const int r0i = 16 * i + g, r1i = r0i + 8;
            uint32_t qA = smaddr(qkh + (16 * i + lr + 8 * lb8) * QK_STRH + h * 32 + 8 * lb16);
            uint32_t aq[2][4];
            ldsm4(aq[0][0], aq[0][1], aq[0][2], aq[0][3], qA);
            ldsm4(aq[1][0], aq[1][1], aq[1][2], aq[1][3], qA + 32);
            // S = Q K^T + bias
            float4 S[7];
#pragma unroll
            for (int j = 0; j < 7; j++) {
                S[j] = make_float4(0.f, 0.f, 0.f, 0.f);
                uint32_t b0, b1, b2, b3;
                ldsm4(b0, b1, b2, b3, kBase + j * (8 * QK_STRH * 2));
                mma16(S[j], aq[0][0], aq[0][1], aq[0][2], aq[0][3], b0, b1);
                mma16(S[j], aq[1][0], aq[1][1], aq[1][2], aq[1][3], b2, b3);
                float2 bb0 = __half22float2(*(const __half2*)(bias + r0i * 56 + 8 * j + 2 * q));
                float2 bb1 = __half22float2(*(const __half2*)(bias + r1i * 56 + 8 * j + 2 * q));
                S[j].x += bb0.x; S[j].y += bb0.y; S[j].z += bb1.x; S[j].w += bb1.y;
            }
            // row softmax via quad reduction
            float mx0 = -1e30f, mx1 = -1e30f;
#pragma unroll
            for (int j = 0; j < 7; j++) {
                mx0 = fmaxf(mx0, fmaxf(S[j].x, S[j].y));
                mx1 = fmaxf(mx1, fmaxf(S[j].z, S[j].w));
            }
#pragma unroll
            for (int o = 1; o < 4; o <<= 1) {
                mx0 = fmaxf(mx0, __shfl_xor_sync(0xffffffffu, mx0, o));
                mx1 = fmaxf(mx1, __shfl_xor_sync(0xffffffffu, mx1, o));
            }
            float sum0 = 0.f, sum1 = 0.f;
#pragma unroll
            for (int j = 0; j < 7; j++) {
                S[j].x = __expf(S[j].x - mx0); S[j].y = __expf(S[j].y - mx0);
                S[j].z = __expf(S[j].z - mx1); S[j].w = __expf(S[j].w - mx1);
                sum0 += S[j].x + S[j].y; sum1 += S[j].z + S[j].w;
            }
#pragma unroll
            for (int o = 1; o < 4; o <<= 1) {
                sum0 += __shfl_xor_sync(0xffffffffu, sum0, o);
                sum1 += __shfl_xor_sync(0xffffffffu, sum1, o);
            }
            float rc0 = 1.f / sum0, rc1 = 1.f / sum1;
            // pack P into A-fragments (C-layout == A-layout identity)
            uint32_t pa[4][4];
#pragma unroll
            for (int kk = 0; kk < 3; kk++) {
                pa[kk][0] = packh2(S[2 * kk].x, S[2 * kk].y);
                pa[kk][1] = packh2(S[2 * kk].z, S[2 * kk].w);
                pa[kk][2] = packh2(S[2 * kk + 1].x, S[2 * kk + 1].y);
                pa[kk][3] = packh2(S[2 * kk + 1].z, S[2 * kk + 1].w);
            }
            pa[3][0] = packh2(S[6].x, S[6].y);
            pa[3][1] = packh2(S[6].z, S[6].w);
            pa[3][2] = 0u; pa[3][3] = 0u;
            // O = P V  (V from vT, pad keys zeroed)
            float4 O[4];
#pragma unroll
            for (int vj = 0; vj < 4; vj++) {
                O[vj] = make_float4(0.f, 0.f, 0.f, 0.f);
                uint32_t va0, va1, va2, va3, vb0, vb1, vb2, vb3;
                ldsm4(va0, va1, va2, va3, vBase + vj * (8 * VT_STRH * 2));
                ldsm4(vb0, vb1, vb2, vb3, vBase + vj * (8 * VT_STRH * 2) + 64);
                mma16(O[vj], pa[0][0], pa[0][1], pa[0][2], pa[0][3], va0, va1);
                mma16(O[vj], pa[1][0], pa[1][1], pa[1][2], pa[1][3], va2, va3);
                mma16(O[vj], pa[2][0], pa[2][1], pa[2][2], pa[2][3], vb0, vb1);
                mma16(O[vj], pa[3][0], pa[3][1], pa[3][2], pa[3][3], vb2, vb3);
            }
            // store normalized rows (<49) into xw
#pragma unroll
            for (int vj = 0; vj < 4; vj++) {
                int col = h * 32 + 8 * vj + 2 * q;
                if (r0i < NT)
                    *(__half2*)(xwh + r0i * XW_STRH + col) =
                        __floats2half2_rn(O[vj].x * rc0, O[vj].y * rc0);
                if (r1i < NT)
                    *(__half2*)(xwh + r1i * XW_STRH + col) =
                        __floats2half2_rn(O[vj].z * rc1, O[vj].w * rc1);
            }
        }
    }

    // ---- Phase 4: proj via f16 mma, fused residual scatter ----
    {
        float4 acc[12];
#pragma unroll
        for (int t = 0; t < 12; t++) acc[t] = make_float4(0.f, 0.f, 0.f, 0.f);

        for (int kc = 0; kc < 192; kc += 32) {
            __syncthreads();
            for (int idx = tid; idx < 768; idx += 256) {
                int n = idx >> 2, c = idx & 3;
                *(uint4*)(wstu + n * 20 + c * 4) =
                    *(const uint4*)(projT_u + (size_t)n * 96 + (kc >> 1) + c * 4);
            }
            __syncthreads();
#pragma unroll
            for (int k0 = 0; k0 < 32; k0 += 16) {
                uint32_t a0, a1, a2, a3;
                ldsm4(a0, a1, a2, a3, aBase + (kc + k0) * 2);
#pragma unroll
                for (int tp = 0; tp < 6; tp++) {
                    uint32_t b0, b1, b2, b3;
                    ldsm4(b0, b1, b2, b3, bBase + tp * 1280 + k0 * 2);
                    mma16(acc[2 * tp],     a0, a1, a2, a3, b0, b1);
                    mma16(acc[2 * tp + 1], a0, a1, a2, a3, b2, b3);
                }
            }
        }

        size_t base0 = 0, base1 = 0;
        if (v0) {
            int gr = wh * 7 + rowA / 7 + 3; if (gr >= 56) gr -= 56;
            int gc = ww * 7 + rowA % 7 + 3; if (gc >= 56) gc -= 56;
            base0 = ((size_t)b * 3136 + gr * 56 + gc) * Cc;
        }
        if (v1) {
            int r1i = rowA + 8;
            int gr = wh * 7 + r1i / 7 + 3; if (gr >= 56) gr -= 56;
            int gc = ww * 7 + r1i % 7 + 3; if (gc >= 56) gc -= 56;
            base1 = ((size_t)b * 3136 + gr * 56 + gc) * Cc;
        }
#pragma unroll
        for (int t = 0; t < 12; t++) {
            int col = 96 * wn + 8 * t + 2 * q;
            float pb0 = __ldg(proj_b + col), pb1 = __ldg(proj_b + col + 1);
            if (v0) {
                float2 xv = *(const float2*)(x + base0 + col);
                float2 r; r.x = xv.x + acc[t].x + pb0; r.y = xv.y + acc[t].y + pb1;
                *(float2*)(g_x2 + base0 + col) = r;
            }
            if (v1) {
                float2 xv = *(const float2*)(x + base1 + col);
                float2 r; r.x = xv.x + acc[t].z + pb0; r.y = xv.y + acc[t].w + pb1;
                *(float2*)(g_x2 + base1 + col) = r;
            }
        }
    }
}

// ---------------------------------------------------------------------------
// Kernel 2: LN2 + MLP (f16 mma) + residual; 64 tokens/block, 1568 blocks
// ---------------------------------------------------------------------------
#define OFF_F1_H 12800
#define OFF_HS_H 25600
#define OFF_F2_H 30208
#define MLP_SM_BYTES (44032 * 2)

__global__ __launch_bounds__(256, 2) void swin_mlp_kernel(
    const float* __restrict__ n2w, const float* __restrict__ n2b,
    const float* __restrict__ fc1b, const float* __restrict__ fc2b,
    float* __restrict__ out)
{
    extern __shared__ __half smh[];
    __half* xnh = smh;                   // [64][200]
    uint32_t* f1u  = (uint32_t*)(smh + OFF_F1_H);   // [64][100] u32
    __half2*  hs2  = (__half2*)(smh + OFF_HS_H);    // [64][36] half2
    uint32_t* f2u  = (uint32_t*)(smh + OFF_F2_H);   // [192][36] u32
    const uint32_t* fc1T_u = (const uint32_t*)g_fc1T;
    const uint32_t* fc2T_u = (const uint32_t*)g_fc2T;

    const int tid  = threadIdx.x;
    const int warp = tid >> 5;
    const int lane = tid & 31;
    const int g    = lane >> 2;
    const int q    = lane & 3;
    const int wm   = warp & 3;
    const int wn   = warp >> 2;
    const int rowA = 16 * wm + g;
    const int lr   = lane & 7;
    const int lb8  = (lane >> 3) & 1;
    const int lb16 = lane >> 4;
    const size_t t0 = (size_t)blockIdx.x * 64;

    const uint32_t aBase1 = smaddr(xnh + (16 * wm + lr + 8 * lb8) * XW_STRH + 8 * lb16);
    const uint32_t b1Base = smaddr((__half*)f1u + (32 * wn + 8 * lb16 + lr) * 200 + 8 * lb8);
    const uint32_t aBase2 = smaddr((__half*)hs2 + (16 * wm + lr + 8 * lb8) * 72 + 8 * lb16);
    const uint32_t b2Base = smaddr((__half*)f2u + (96 * wn + 8 * lb16 + lr) * 72 + 8 * lb8);

    // ---- LN2 ----
    for (int n = warp; n < 64; n += 8) {
        const float* xr = g_x2 + (t0 + n) * Cc;
        float v[6]; float s = 0.f, ss = 0.f;
#pragma unroll
        for (int j = 0; j < 6; j++) { v[j] = xr[lane + 32 * j]; s += v[j]; ss += v[j] * v[j]; }
#pragma unroll
        for (int o = 16; o > 0; o >>= 1) {
            s  += __shfl_xor_sync(0xffffffffu, s,  o);
            ss += __shfl_xor_sync(0xffffffffu, ss, o);
        }
        float mean = s * (1.f / 192.f);
        float rinv = rsqrtf(ss * (1.f / 192.f) - mean * mean + 1e-5f);
#pragma unroll
        for (int j = 0; j < 6; j++) {
            int k = lane + 32 * j;
            xnh[n * XW_STRH + k] = __float2half((v[j] - mean) * rinv * n2w[k] + n2b[k]);
        }
    }

    float4 yacc[12];
#pragma unroll
    for (int t = 0; t < 12; t++) yacc[t] = make_float4(0.f, 0.f, 0.f, 0.f);

    for (int hc = 0; hc < HIDDEN; hc += 64) {
        __syncthreads();
        // stage fc1T rows [hc..hc+63] full k (64 x 24 uint4)
        for (int idx = tid; idx < 1536; idx += 256) {
            int n = idx / 24, c = idx % 24;
            *(uint4*)(f1u + n * 100 + c * 4) =
                *(const uint4*)(fc1T_u + (size_t)(hc + n) * 96 + c * 4);
        }
        // stage fc2T k-chunk (192 x 8 uint4)
        for (int idx = tid; idx < 1536; idx += 256) {
            int n = idx >> 3, c = idx & 7;
            *(uint4*)(f2u + n * 36 + c * 4) =
                *(const uint4*)(fc2T_u + (size_t)n * 384 + (hc >> 1) + c * 4);
        }
        __syncthreads();

        // fc1: H(64x64) = xn(64x192) @ w1chunk ; warp tile m16 x n32
        float4 acc1[4];
#pragma unroll
        for (int t = 0; t < 4; t++) acc1[t] = make_float4(0.f, 0.f, 0.f, 0.f);
#pragma unroll
        for (int k0 = 0; k0 < 192; k0 += 16) {
            uint32_t a0, a1, a2, a3;
            ldsm4(a0, a1, a2, a3, aBase1 + k0 * 2);
#pragma unroll
            for (int tp = 0; tp < 2; tp++) {
                uint32_t b0, b1, b2, b3;
                ldsm4(b0, b1, b2, b3, b1Base + tp * 6400 + k0 * 2);
                mma16(acc1[2 * tp],     a0, a1, a2, a3, b0, b1);
                mma16(acc1[2 * tp + 1], a0, a1, a2, a3, b2, b3);
            }
        }
        // bias + gelu -> hs
#pragma unroll
        for (int t = 0; t < 4; t++) {
            int col = 32 * wn + 8 * t + 2 * q;
            float b0v = __ldg(fc1b + hc + col), b1v = __ldg(fc1b + hc + col + 1);
            int wi = 16 * wn + 4 * t + q;
            hs2[rowA * 36 + wi]       = __floats2half2_rn(gelu_exact(acc1[t].x + b0v),
                                                          gelu_exact(acc1[t].y + b1v));
            hs2[(rowA + 8) * 36 + wi] = __floats2half2_rn(gelu_exact(acc1[t].z + b0v),
                                                          gelu_exact(acc1[t].w + b1v));
        }
        __syncthreads();

        // fc2: Y(64x192) += H(64x64) @ w2chunk ; warp tile m16 x n96
#pragma unroll
        for (int k0 = 0; k0 < 64; k0 += 16) {
            uint32_t a0, a1, a2, a3;
            ldsm4(a0, a1, a2, a3, aBase2 + k0 * 2);
#pragma unroll
            for (int tp = 0; tp < 6; tp++) {
                uint32_t b0, b1, b2, b3;
                ldsm4(b0, b1, b2, b3, b2Base + tp * 2304 + k0 * 2);
                mma16(yacc[2 * tp],     a0, a1, a2, a3, b0, b1);
                mma16(yacc[2 * tp + 1], a0, a1, a2, a3, b2, b3);
            }
        }
    }

#pragma unroll
    for (int t = 0; t < 12; t++) {
        int col = 96 * wn + 8 * t + 2 * q;
        float b0v = __ldg(fc2b + col), b1v = __ldg(fc2b + col + 1);
        {
            size_t base = (t0 + rowA) * Cc + col;
            float2 xv = *(const float2*)(g_x2 + base);
            float2 r; r.x = xv.x + yacc[t].x + b0v; r.y = xv.y + yacc[t].y + b1v;
            *(float2*)(out + base) = r;
        }
        {
            size_t base = (t0 + rowA + 8) * Cc + col;
            float2 xv = *(const float2*)(g_x2 + base);
            float2 r; r.x = xv.x + yacc[t].z + b0v; r.y = xv.y + yacc[t].w + b1v;
            *(float2*)(out + base) = r;
        }
    }
}

// ---------------------------------------------------------------------------
extern "C" void kernel_launch(void* const* d_in, const int* in_sizes, int n_in,
                              void* d_out, int out_size)
{
    const float* x      = (const float*)d_in[0];
    const float* mask   = (const float*)d_in[1];
    const float* rel    = (const float*)d_in[2];
    const float* qkv_w  = (const float*)d_in[3];
    const float* qkv_b  = (const float*)d_in[4];
    const float* proj_w = (const float*)d_in[5];
    const float* proj_b = (const float*)d_in[6];
    const float* n1w    = (const float*)d_in[7];
    const float* n1b    = (const float*)d_in[8];
    const float* n2w    = (const float*)d_in[9];
    const float* n2b    = (const float*)d_in[10];
    const float* fc1w   = (const float*)d_in[11];
    const float* fc1b   = (const float*)d_in[12];
    const float* fc2w   = (const float*)d_in[13];
    const float* fc2b   = (const float*)d_in[14];
    float* out = (float*)d_out;

    cudaFuncSetAttribute(swin_attn_kernel, cudaFuncAttributeMaxDynamicSharedMemorySize,
                         ATTN_SM_BYTES);
    cudaFuncSetAttribute(swin_mlp_kernel, cudaFuncAttributeMaxDynamicSharedMemorySize,
                         MLP_SM_BYTES);

    convert_w<<<296, 256>>>(qkv_w, proj_w, fc1w, fc2w, mask, rel);
    swin_attn_kernel<<<Bn * 64, 256, ATTN_SM_BYTES>>>(x, qkv_b, proj_b, n1w, n1b);
    swin_mlp_kernel<<<1568, 256, MLP_SM_BYTES>>>(n2w, n2b, fc1b, fc2b, out);
}

// round 8
// speedup vs baseline: 5.1028x; 1.1161x over previous
#include <cuda_runtime.h>
#include <cuda_fp16.h>
#include <math.h>
#include <stdint.h>

#define Bn 32
#define Cc 192
#define WSZ 7
#define NHEAD 6
#define NT 49
#define HIDDEN 768
#define SCALE 0.17677669529663687f

// scratch for x + attention residual
__device__ float g_x2[(size_t)Bn * 56 * 56 * Cc];

// pre-transposed fp16 weights, [n][k] layout
__device__ __align__(16) __half g_qkvT[576 * 192];
__device__ __align__(16) __half g_projT[192 * 192];
__device__ __align__(16) __half g_fc1T[768 * 192];
__device__ __align__(16) __half g_fc2T[192 * 768];
// fused rel-pos bias + shift mask, padded: [win 64][head 6][row 64][col 56]
__device__ __align__(16) __half g_bias[64 * 6 * 64 * 56];

__global__ void convert_w(const float* __restrict__ qkv_w, const float* __restrict__ proj_w,
                          const float* __restrict__ fc1w, const float* __restrict__ fc2w,
                          const float* __restrict__ mask, const float* __restrict__ rel_table)
{
    int tid = blockIdx.x * blockDim.x + threadIdx.x;
    int stride = gridDim.x * blockDim.x;
    for (int j = tid; j < 192 * 576; j += stride) {
        int k = j / 576, n = j % 576;
        g_qkvT[n * 192 + k] = __float2half(qkv_w[j]);
    }
    for (int j = tid; j < 192 * 192; j += stride) {
        int k = j / 192, n = j % 192;
        g_projT[n * 192 + k] = __float2half(proj_w[j]);
    }
    for (int j = tid; j < 192 * 768; j += stride) {
        int k = j / 768, n = j % 768;
        g_fc1T[n * 192 + k] = __float2half(fc1w[j]);
    }
    for (int j = tid; j < 768 * 192; j += stride) {
        int k = j / 192, n = j % 192;
        g_fc2T[n * 768 + k] = __float2half(fc2w[j]);
    }
    for (int j = tid; j < 64 * 6 * 64 * 56; j += stride) {
        int col = j % 56;
        int rest = j / 56;
        int row = rest % 64; rest /= 64;
        int h = rest % 6;
        int w = rest / 6;
        float v;
        if (row >= NT)      v = 0.f;
        else if (col >= NT) v = -30000.f;
        else {
            int rr = row / 7 - col / 7 + 6;
            int cc = row % 7 - col % 7 + 6;
            v = rel_table[(rr * 13 + cc) * NHEAD + h] + mask[w * 2401 + row * 49 + col];
        }
        g_bias[j] = __float2half(v);
    }
}

// D = A(16x16 f16, row) x B(16x8 f16, col) + D, fp32 accum
__device__ __forceinline__ void mma16(float4& c, uint32_t a0, uint32_t a1, uint32_t a2,
                                      uint32_t a3, uint32_t b0, uint32_t b1) {
    asm volatile(
        "mma.sync.aligned.m16n8k16.row.col.f32.f16.f16.f32 "
        "{%0,%1,%2,%3},{%4,%5,%6,%7},{%8,%9},{%0,%1,%2,%3};"
        : "+f"(c.x), "+f"(c.y), "+f"(c.z), "+f"(c.w)
        : "r"(a0), "r"(a1), "r"(a2), "r"(a3), "r"(b0), "r"(b1));
}

__device__ __forceinline__ uint32_t smaddr(const void* p) {
    return (uint32_t)__cvta_generic_to_shared(p);
}

__device__ __forceinline__ void ldsm4(uint32_t& r0, uint32_t& r1, uint32_t& r2,
                                      uint32_t& r3, uint32_t a) {
    asm volatile("ldmatrix.sync.aligned.m8n8.x4.shared.b16 {%0,%1,%2,%3},[%4];"
                 : "=r"(r0), "=r"(r1), "=r"(r2), "=r"(r3) : "r"(a));
}

__device__ __forceinline__ uint32_t packh2(float a, float b) {
    __half2 h = __floats2half2_rn(a, b);
    return *(uint32_t*)&h;
}

__device__ __forceinline__ float gelu_exact(float v) {
    return 0.5f * v * (1.0f + erff(v * 0.70710678118654752f));
}

// ---------------------------------------------------------------------------
// Kernel 1: per-window LN1 -> QKV(mma) -> mma attention -> proj(mma)
// smem halves: xw[64][200] | qk[56][392] (Q|K) | vT[192][72] | wst[192][40]
// ---------------------------------------------------------------------------
#define XW_STRH 200
#define QK_STRH 392
#define VT_STRH 72
#define OFF_QK_H 12800        // 64*200
#define OFF_VT_H 34752        // + 56*392
#define OFF_WST_H 48576       // + 192*72
#define ATTN_SM_BYTES (56256 * 2)

__global__ __launch_bounds__(256, 2) void swin_attn_kernel(
    const float* __restrict__ x,
    const float* __restrict__ qkv_b, const float* __restrict__ proj_b,
    const float* __restrict__ n1w, const float* __restrict__ n1b)
{
    extern __shared__ __half smh[];
    __half* xwh = smh;                   // [64][200]  LN1 out / attn out
    __half* qkh = smh + OFF_QK_H;        // [56][392]  Q(0..191) K(192..383)
    __half* vth = smh + OFF_VT_H;        // [192][72]  V transposed
    uint32_t* xwu  = (uint32_t*)xwh;
    uint32_t* vtu  = (uint32_t*)vth;
    uint32_t* wstu = (uint32_t*)(smh + OFF_WST_H);   // [192][20] u32 weight stage
    const uint32_t* qkvT_u  = (const uint32_t*)g_qkvT;
    const uint32_t* projT_u = (const uint32_t*)g_projT;

    const int bid  = blockIdx.x;
    const int b    = bid >> 6;
    const int w    = bid & 63;
    const int wh   = w >> 3;
    const int ww   = w & 7;
    const int tid  = threadIdx.x;
    const int warp = tid >> 5;
    const int lane = tid & 31;
    const int g    = lane >> 2;
    const int q    = lane & 3;
    const int wm   = warp & 3;
    const int wn   = warp >> 2;
    const int rowA = 16 * wm + g;
    const int lr   = lane & 7;
    const int lb8  = (lane >> 3) & 1;
    const int lb16 = lane >> 4;

    // staging decomposition for this thread (768 uint4 per 32-k chunk)
    const int sn0 = tid >> 2, sc0 = (tid & 3) * 4;           // j=0
    const int sn1 = (tid + 256) >> 2, sc1 = ((tid + 256) & 3) * 4;
    const int sn2 = (tid + 512) >> 2, sc2 = ((tid + 512) & 3) * 4;

    // ldmatrix bases for the big GEMM loops
    const uint32_t aBase = smaddr(xwh + (16 * wm + lr + 8 * lb8) * XW_STRH + 8 * lb16);
    const uint32_t bBase = smaddr((__half*)wstu + (96 * wn + 8 * lb16 + lr) * 40 + 8 * lb8);

    // ---- zero pad regions: QK rows 49..55 and all of vT (pad keys must be 0) ----
    for (int idx = tid; idx < 192 * 36; idx += 256) vtu[idx] = 0u;
    for (int idx = tid; idx < 7 * 196; idx += 256)
        ((uint32_t*)qkh)[(49 + idx / 196) * 196 + idx % 196] = 0u;

    // prologue prefetch: QKV pass 0, chunk 0
    uint4 pre0 = *(const uint4*)(qkvT_u + (size_t)sn0 * 96 + sc0);
    uint4 pre1 = *(const uint4*)(qkvT_u + (size_t)sn1 * 96 + sc1);
    uint4 pre2 = *(const uint4*)(qkvT_u + (size_t)sn2 * 96 + sc2);

    // ---- Phase 1: gather (shifted window) + LN1 (xw rows>=49 zeroed) ----
    for (int n = warp; n < 64; n += 8) {
        if (n < NT) {
            int r  = wh * WSZ + n / WSZ;
            int c  = ww * WSZ + n % WSZ;
            int gr = r + 3; if (gr >= 56) gr -= 56;
            int gc = c + 3; if (gc >= 56) gc -= 56;
            const float* xr = x + ((size_t)b * 3136 + gr * 56 + gc) * Cc;
            float v[6]; float s = 0.f, ss = 0.f;
#pragma unroll
            for (int j = 0; j < 6; j++) { v[j] = xr[lane + 32 * j]; s += v[j]; ss += v[j] * v[j]; }
#pragma unroll
            for (int o = 16; o > 0; o >>= 1) {
                s  += __shfl_xor_sync(0xffffffffu, s,  o);
                ss += __shfl_xor_sync(0xffffffffu, ss, o);
            }
            float mean = s * (1.f / 192.f);
            float rinv = rsqrtf(ss * (1.f / 192.f) - mean * mean + 1e-5f);
#pragma unroll
            for (int j = 0; j < 6; j++) {
                int k = lane + 32 * j;
                xwh[n * XW_STRH + k] = __float2half((v[j] - mean) * rinv * n1w[k] + n1b[k]);
            }
        } else {
#pragma unroll
            for (int j = 0; j < 3; j++) xwu[n * 100 + lane + 32 * j] = 0u;
        }
    }

    // ---- Phase 2: QKV via f16 mma : out(64x192) per pass ----
    const bool v0 = rowA < NT, v1 = (rowA + 8) < NT;
    for (int p = 0; p < 3; p++) {
        float4 acc[12];
#pragma unroll
        for (int t = 0; t < 12; t++) acc[t] = make_float4(0.f, 0.f, 0.f, 0.f);

        for (int kc = 0; kc < 192; kc += 32) {
            __syncthreads();
            *(uint4*)(wstu + sn0 * 20 + sc0) = pre0;
            *(uint4*)(wstu + sn1 * 20 + sc1) = pre1;
            *(uint4*)(wstu + sn2 * 20 + sc2) = pre2;
            __syncthreads();
            // prefetch next stage (overlaps with compute below)
            int s = p * 6 + (kc >> 5) + 1;
            if (s < 18) {
                int np = s / 6, nk = (s % 6) << 4;   // nk in u32 units (32k = 16 u32)
                pre0 = *(const uint4*)(qkvT_u + (size_t)(np * 192 + sn0) * 96 + nk + sc0);
                pre1 = *(const uint4*)(qkvT_u + (size_t)(np * 192 + sn1) * 96 + nk + sc1);
                pre2 = *(const uint4*)(qkvT_u + (size_t)(np * 192 + sn2) * 96 + nk + sc2);
            }
#pragma unroll
            for (int k0 = 0; k0 < 32; k0 += 16) {
                uint32_t a0, a1, a2, a3;
                ldsm4(a0, a1, a2, a3, aBase + (kc + k0) * 2);
#pragma unroll
                for (int tp = 0; tp < 6; tp++) {
                    uint32_t b0, b1, b2, b3;
                    ldsm4(b0, b1, b2, b3, bBase + tp * 1280 + k0 * 2);
                    mma16(acc[2 * tp],     a0, a1, a2, a3, b0, b1);
                    mma16(acc[2 * tp + 1], a0, a1, a2, a3, b2, b3);
                }
            }
        }
#pragma unroll
        for (int t = 0; t < 12; t++) {
            int col = 96 * wn + 8 * t + 2 * q;
            int j   = 192 * p + col;
            float b0v = __ldg(qkv_b + j), b1v = __ldg(qkv_b + j + 1);
            float o00 = acc[t].x + b0v, o01 = acc[t].y + b1v;
            float o10 = acc[t].z + b0v, o11 = acc[t].w + b1v;
            if (p == 0) { o00 *= SCALE; o01 *= SCALE; o10 *= SCALE; o11 *= SCALE; }
            if (p < 2) {
                if (v0) *(__half2*)(qkh + rowA * QK_STRH + j)       = __floats2half2_rn(o00, o01);
                if (v1) *(__half2*)(qkh + (rowA + 8) * QK_STRH + j) = __floats2half2_rn(o10, o11);
            } else {
                if (v0) {
                    vth[col * VT_STRH + rowA]       = __float2half(o00);
                    vth[(col + 1) * VT_STRH + rowA] = __float2half(o01);
                }
                if (v1) {
                    vth[col * VT_STRH + rowA + 8]       = __float2half(o10);
                    vth[(col + 1) * VT_STRH + rowA + 8] = __float2half(o11);
                }
            }
        }
    }
    __syncthreads();

    // ---- Phase 3: mma attention over 24 (head, m-tile) units, 3 per warp ----
    {
#pragma unroll 1
        for (int t = 0; t < 3; t++) {
            const int u = warp * 3 + t;
            const int h = u >> 2;
            const int i = u & 3;
            const __half* bias = g_bias + ((size_t)(w * NHEAD + h)) * 64 * 56;
            const uint32_t kBase = smaddr(qkh + lr * QK_STRH + 192 + h * 32 + 8 * (lane >> 3));
            const uint32_t vBase = smaddr(vth + (h * 32 + lr) * VT_STRH + 8 * (lane >> 3));
            const int r0i = 16 * i + g, r1i = r0i + 8;

            // batch bias loads first (latency overlaps mma chain)
            float2 bb0[7], bb1[7];
#pragma unroll
            for (int j = 0; j < 7; j++) {
                bb0[j] = __half22float2(*(const __half2*)(bias + r0i * 56 + 8 * j + 2 * q));
                bb1[j] = __half22float2(*(const __half2*)(bias + r1i * 56 + 8 * j + 2 * q));
            }

            uint32_t qA = smaddr(qkh + (16 * i + lr + 8 * lb8) * QK_STRH + h * 32 + 8 * lb16);
            uint32_t aq[2][4];
            ldsm4(aq[0][0], aq[0][1], aq[0][2], aq[0][3], qA);
            ldsm4(aq[1][0], aq[1][1], aq[1][2], aq[1][3], qA + 32);
            // S = Q K^T + bias
            float4 S[7];
#pragma unroll
            for (int j = 0; j < 7; j++) {
                S[j] = make_float4(0.f, 0.f, 0.f, 0.f);
                uint32_t b0, b1, b2, b3;
                ldsm4(b0, b1, b2, b3, kBase + j * (8 * QK_STRH * 2));
                mma16(S[j], aq[0][0], aq[0][1], aq[0][2], aq[0][3], b0, b1);
                mma16(S[j], aq[1][0], aq[1][1], aq[1][2], aq[1][3], b2, b3);
                S[j].x += bb0[j].x; S[j].y += bb0[j].y;
                S[j].z += bb1[j].x; S[j].w += bb1[j].y;
            }
            // row softmax via quad reduction
            float mx0 = -1e30f, mx1 = -1e30f;
#pragma unroll
            for (int j = 0; j < 7; j++) {
                mx0 = fmaxf(mx0, fmaxf(S[j].x, S[j].y));
                mx1 = fmaxf(mx1, fmaxf(S[j].z, S[j].w));
            }
#pragma unroll
            for (int o = 1; o < 4; o <<= 1) {
                mx0 = fmaxf(mx0, __shfl_xor_sync(0xffffffffu, mx0, o));
                mx1 = fmaxf(mx1, __shfl_xor_sync(0xffffffffu, mx1, o));
            }
            float sum0 = 0.f, sum1 = 0.f;
#pragma unroll
            for (int j = 0; j < 7; j++) {
                S[j].x = __expf(S[j].x - mx0); S[j].y = __expf(S[j].y - mx0);
                S[j].z = __expf(S[j].z - mx1); S[j].w = __expf(S[j].w - mx1);
                sum0 += S[j].x + S[j].y; sum1 += S[j].z + S[j].w;
            }
#pragma unroll
            for (int o = 1; o < 4; o <<= 1) {
                sum0 += __shfl_xor_sync(0xffffffffu, sum0, o);
                sum1 += __shfl_xor_sync(0xffffffffu, sum1, o);
            }
            float rc0 = 1.f / sum0, rc1 = 1.f / sum1;
            // pack P into A-fragments (C-layout == A-layout identity)
            uint32_t pa[4][4];
#pragma unroll
            for (int kk = 0; kk < 3; kk++) {
                pa[kk][0] = packh2(S[2 * kk].x, S[2 * kk].y);
                pa[kk][1] = packh2(S[2 * kk].z, S[2 * kk].w);
                pa[kk][2] = packh2(S[2 * kk + 1].x, S[2 * kk + 1].y);
                pa[kk][3] = packh2(S[2 * kk + 1].z, S[2 * kk + 1].w);
            }
            pa[3][0] = packh2(S[6].x, S[6].y);
            pa[3][1] = packh2(S[6].z, S[6].w);
            pa[3][2] = 0u; pa[3][3] = 0u;
            // O = P V  (V from vT, pad keys zeroed)
            float4 O[4];
#pragma unroll
            for (int vj = 0; vj < 4; vj++) {
                O[vj] = make_float4(0.f, 0.f, 0.f, 0.f);
                uint32_t va0, va1, va2, va3, vb0, vb1, vb2, vb3;
                ldsm4(va0, va1, va2, va3, vBase + vj * (8 * VT_STRH * 2));
                ldsm4(vb0, vb1, vb2, vb3, vBase + vj * (8 * VT_STRH * 2) + 64);
                mma16(O[vj], pa[0][0], pa[0][1], pa[0][2], pa[0][3], va0, va1);
                mma16(O[vj], pa[1][0], pa[1][1], pa[1][2], pa[1][3], va2, va3);
                mma16(O[vj], pa[2][0], pa[2][1], pa[2][2], pa[2][3], vb0, vb1);
                mma16(O[vj], pa[3][0], pa[3][1], pa[3][2], pa[3][3], vb2, vb3);
            }
            // store normalized rows (<49) into xw
#pragma unroll
            for (int vj = 0; vj < 4; vj++) {
                int col = h * 32 + 8 * vj + 2 * q;
                if (r0i < NT)
                    *(__half2*)(xwh + r0i * XW_STRH + col) =
                        __floats2half2_rn(O[vj].x * rc0, O[vj].y * rc0);
                if (r1i < NT)
                    *(__half2*)(xwh + r1i * XW_STRH + col) =
                        __floats2half2_rn(O[vj].z * rc1, O[vj].w * rc1);
            }
        }
    }

    // ---- Phase 4: proj via f16 mma, fused residual scatter ----
    {
        float4 acc[12];
#pragma unroll
        for (int t = 0; t < 12; t++) acc[t] = make_float4(0.f, 0.f, 0.f, 0.f);

        // prologue prefetch proj chunk 0
        pre0 = *(const uint4*)(projT_u + (size_t)sn0 * 96 + sc0);
        pre1 = *(const uint4*)(projT_u + (size_t)sn1 * 96 + sc1);
        pre2 = *(const uint4*)(projT_u + (size_t)sn2 * 96 + sc2);

        for (int kc = 0; kc < 192; kc += 32) {
            __syncthreads();
            *(uint4*)(wstu + sn0 * 20 + sc0) = pre0;
            *(uint4*)(wstu + sn1 * 20 + sc1) = pre1;
            *(uint4*)(wstu + sn2 * 20 + sc2) = pre2;
            __syncthreads();
            if (kc + 32 < 192) {
                int nk = (kc >> 1) + 16;
                pre0 = *(const uint4*)(projT_u + (size_t)sn0 * 96 + nk + sc0);
                pre1 = *(const uint4*)(projT_u + (size_t)sn1 * 96 + nk + sc1);
                pre2 = *(const uint4*)(projT_u + (size_t)sn2 * 96 + nk + sc2);
            }
#pragma unroll
            for (int k0 = 0; k0 < 32; k0 += 16) {
                uint32_t a0, a1, a2, a3;
                ldsm4(a0, a1, a2, a3, aBase + (kc + k0) * 2);
#pragma unroll
                for (int tp = 0; tp < 6; tp++) {
                    uint32_t b0, b1, b2, b3;
                    ldsm4(b0, b1, b2, b3, bBase + tp * 1280 + k0 * 2);
                    mma16(acc[2 * tp],     a0, a1, a2, a3, b0, b1);
                    mma16(acc[2 * tp + 1], a0, a1, a2, a3, b2, b3);
                }
            }
        }

        size_t base0 = 0, base1 = 0;
        if (v0) {
            int gr = wh * 7 + rowA / 7 + 3; if (gr >= 56) gr -= 56;
            int gc = ww * 7 + rowA % 7 + 3; if (gc >= 56) gc -= 56;
            base0 = ((size_t)b * 3136 + gr * 56 + gc) * Cc;
        }
        if (v1) {
            int r1i = rowA + 8;
            int gr = wh * 7 + r1i / 7 + 3; if (gr >= 56) gr -= 56;
            int gc = ww * 7 + r1i % 7 + 3; if (gc >= 56) gc -= 56;
            base1 = ((size_t)b * 3136 + gr * 56 + gc) * Cc;
        }
#pragma unroll
        for (int t = 0; t < 12; t++) {
            int col = 96 * wn + 8 * t + 2 * q;
            float pb0 = __ldg(proj_b + col), pb1 = __ldg(proj_b + col + 1);
            if (v0) {
                float2 xv = *(const float2*)(x + base0 + col);
                float2 r; r.x = xv.x + acc[t].x + pb0; r.y = xv.y + acc[t].y + pb1;
                *(float2*)(g_x2 + base0 + col) = r;
            }
            if (v1) {
                float2 xv = *(const float2*)(x + base1 + col);
                float2 r; r.x = xv.x + acc[t].z + pb0; r.y = xv.y + acc[t].w + pb1;
                *(float2*)(g_x2 + base1 + col) = r;
            }
        }
    }
}

// ---------------------------------------------------------------------------
// Kernel 2: LN2 + MLP (f16 mma) + residual; 64 tokens/block, 1568 blocks
// ---------------------------------------------------------------------------
#define OFF_F1_H 12800
#define OFF_HS_H 25600
#define OFF_F2_H 30208
#define MLP_SM_BYTES (44032 * 2)

__global__ __launch_bounds__(256, 2) void swin_mlp_kernel(
    const float* __restrict__ n2w, const float* __restrict__ n2b,
    const float* __restrict__ fc1b, const float* __restrict__ fc2b,
    float* __restrict__ out)
{
    extern __shared__ __half smh[];
    __half* xnh = smh;                   // [64][200]
    uint32_t* f1u  = (uint32_t*)(smh + OFF_F1_H);   // [64][100] u32
    __half2*  hs2  = (__half2*)(smh + OFF_HS_H);    // [64][36] half2
    uint32_t* f2u  = (uint32_t*)(smh + OFF_F2_H);   // [192][36] u32
    const uint32_t* fc1T_u = (const uint32_t*)g_fc1T;
    const uint32_t* fc2T_u = (const uint32_t*)g_fc2T;

    const int tid  = threadIdx.x;
    const int warp = tid >> 5;
    const int lane = tid & 31;
    const int g    = lane >> 2;
    const int q    = lane & 3;
    const int wm   = warp & 3;
    const int wn   = warp >> 2;
    const int rowA = 16 * wm + g;
    const int lr   = lane & 7;
    const int lb8  = (lane >> 3) & 1;
    const int lb16 = lane >> 4;
    const size_t t0 = (size_t)blockIdx.x * 64;

    const uint32_t aBase1 = smaddr(xnh + (16 * wm + lr + 8 * lb8) * XW_STRH + 8 * lb16);
    const uint32_t b1Base = smaddr((__half*)f1u + (32 * wn + 8 * lb16 + lr) * 200 + 8 * lb8);
    const uint32_t aBase2 = smaddr((__half*)hs2 + (16 * wm + lr + 8 * lb8) * 72 + 8 * lb16);
    const uint32_t b2Base = smaddr((__half*)f2u + (96 * wn + 8 * lb16 + lr) * 72 + 8 * lb8);

    // fc1 staging decomposition (1536 uint4 per chunk, 6 per thread)
    int f1n[6], f1c[6];
#pragma unroll
    for (int j = 0; j < 6; j++) {
        int idx = tid + j * 256;
        f1n[j] = idx / 24; f1c[j] = (idx % 24) * 4;
    }
    // prologue prefetch fc1 chunk 0
    uint4 pre[6];
#pragma unroll
    for (int j = 0; j < 6; j++)
        pre[j] = *(const uint4*)(fc1T_u + (size_t)f1n[j] * 96 + f1c[j]);

    // ---- LN2 ----
    for (int n = warp; n < 64; n += 8) {
        const float* xr = g_x2 + (t0 + n) * Cc;
        float v[6]; float s = 0.f, ss = 0.f;
#pragma unroll
        for (int j = 0; j < 6; j++) { v[j] = xr[lane + 32 * j]; s += v[j]; ss += v[j] * v[j]; }
#pragma unroll
        for (int o = 16; o > 0; o >>= 1) {
            s  += __shfl_xor_sync(0xffffffffu, s,  o);
            ss += __shfl_xor_sync(0xffffffffu, ss, o);
        }
        float mean = s * (1.f / 192.f);
        float rinv = rsqrtf(ss * (1.f / 192.f) - mean * mean + 1e-5f);
#pragma unroll
        for (int j = 0; j < 6; j++) {
            int k = lane + 32 * j;
            xnh[n * XW_STRH + k] = __float2half((v[j] - mean) * rinv * n2w[k] + n2b[k]);
        }
    }

    float4 yacc[12];
#pragma unroll
    for (int t = 0; t < 12; t++) yacc[t] = make_float4(0.f, 0.f, 0.f, 0.f);

    for (int hc = 0; hc < HIDDEN; hc += 64) {
        __syncthreads();
        // store prefetched fc1 chunk
#pragma unroll
        for (int j = 0; j < 6; j++)
            *(uint4*)(f1u + f1n[j] * 100 + f1c[j]) = pre[j];
        // stage fc2T k-chunk directly (192 x 8 uint4)
        for (int idx = tid; idx < 1536; idx += 256) {
            int n = idx >> 3, c = idx & 7;
            *(uint4*)(f2u + n * 36 + c * 4) =
                *(const uint4*)(fc2T_u + (size_t)n * 384 + (hc >> 1) + c * 4);
        }
        __syncthreads();
        // prefetch next fc1 chunk (overlaps with compute)
        if (hc + 64 < HIDDEN) {
#pragma unroll
            for (int j = 0; j < 6; j++)
                pre[j] = *(const uint4*)(fc1T_u + (size_t)(hc + 64 + f1n[j]) * 96 + f1c[j]);
        }

        // fc1: H(64x64) = xn(64x192) @ w1chunk ; warp tile m16 x n32
        float4 acc1[4];
#pragma unroll
        for (int t = 0; t < 4; t++) acc1[t] = make_float4(0.f, 0.f, 0.f, 0.f);
#pragma unroll
        for (int k0 = 0; k0 < 192; k0 += 16) {
            uint32_t a0, a1, a2, a3;
            ldsm4(a0, a1, a2, a3, aBase1 + k0 * 2);
#pragma unroll
            for (int tp = 0; tp < 2; tp++) {
                uint32_t b0, b1, b2, b3;
                ldsm4(b0, b1, b2, b3, b1Base + tp * 6400 + k0 * 2);
                mma16(acc1[2 * tp],     a0, a1, a2, a3, b0, b1);
                mma16(acc1[2 * tp + 1], a0, a1, a2, a3, b2, b3);
            }
        }
        // bias + gelu -> hs
#pragma unroll
        for (int t = 0; t < 4; t++) {
            int col = 32 * wn + 8 * t + 2 * q;
            float b0v = __ldg(fc1b + hc + col), b1v = __ldg(fc1b + hc + col + 1);
            int wi = 16 * wn + 4 * t + q;
            hs2[rowA * 36 + wi]       = __floats2half2_rn(gelu_exact(acc1[t].x + b0v),
                                                          gelu_exact(acc1[t].y + b1v));
            hs2[(rowA + 8) * 36 + wi] = __floats2half2_rn(gelu_exact(acc1[t].z + b0v),
                                                          gelu_exact(acc1[t].w + b1v));
        }
        __syncthreads();

        // fc2: Y(64x192) += H(64x64) @ w2chunk ; warp tile m16 x n96
#pragma unroll
        for (int k0 = 0; k0 < 64; k0 += 16) {
            uint32_t a0, a1, a2, a3;
            ldsm4(a0, a1, a2, a3, aBase2 + k0 * 2);
#pragma unroll
            for (int tp = 0; tp < 6; tp++) {
                uint32_t b0, b1, b2, b3;
                ldsm4(b0, b1, b2, b3, b2Base + tp * 2304 + k0 * 2);
                mma16(yacc[2 * tp],     a0, a1, a2, a3, b0, b1);
                mma16(yacc[2 * tp + 1], a0, a1, a2, a3, b2, b3);
            }
        }
    }

#pragma unroll
    for (int t = 0; t < 12; t++) {
        int col = 96 * wn + 8 * t + 2 * q;
        float b0v = __ldg(fc2b + col), b1v = __ldg(fc2b + col + 1);
        {
            size_t base = (t0 + rowA) * Cc + col;
            float2 xv = *(const float2*)(g_x2 + base);
            float2 r; r.x = xv.x + yacc[t].x + b0v; r.y = xv.y + yacc[t].y + b1v;
            *(float2*)(out + base) = r;
        }
        {
            size_t base = (t0 + rowA + 8) * Cc + col;
            float2 xv = *(const float2*)(g_x2 + base);
            float2 r; r.x = xv.x + yacc[t].z + b0v; r.y = xv.y + yacc[t].w + b1v;
            *(float2*)(out + base) = r;
        }
    }
}

// ---------------------------------------------------------------------------
extern "C" void kernel_launch(void* const* d_in, const int* in_sizes, int n_in,
                              void* d_out, int out_size)
{
    const float* x      = (const float*)d_in[0];
    const float* mask   = (const float*)d_in[1];
    const float* rel    = (const float*)d_in[2];
    const float* qkv_w  = (const float*)d_in[3];
    const float* qkv_b  = (const float*)d_in[4];
    const float* proj_w = (const float*)d_in[5];
    const float* proj_b = (const float*)d_in[6];
    const float* n1w    = (const float*)d_in[7];
    const float* n1b    = (const float*)d_in[8];
    const float* n2w    = (const float*)d_in[9];
    const float* n2b    = (const float*)d_in[10];
    const float* fc1w   = (const float*)d_in[11];
    const float* fc1b   = (const float*)d_in[12];
    const float* fc2w   = (const float*)d_in[13];
    const float* fc2b   = (const float*)d_in[14];
    float* out = (float*)d_out;

    cudaFuncSetAttribute(swin_attn_kernel, cudaFuncAttributeMaxDynamicSharedMemorySize,
                         ATTN_SM_BYTES);
    cudaFuncSetAttribute(swin_mlp_kernel, cudaFuncAttributeMaxDynamicSharedMemorySize,
                         MLP_SM_BYTES);

    convert_w<<<296, 256>>>(qkv_w, proj_w, fc1w, fc2w, mask, rel);
    swin_attn_kernel<<<Bn * 64, 256, ATTN_SM_BYTES>>>(x, qkv_b, proj_b, n1w, n1b);
    swin_mlp_kernel<<<1568, 256, MLP_SM_BYTES>>>(n2w, n2b, fc1b, fc2b, out);
}

// round 9
// speedup vs baseline: 5.3909x; 1.0565x over previous
#include <cuda_runtime.h>
#include <cuda_fp16.h>
#include <math.h>
#include <stdint.h>

#define Bn 32
#define Cc 192
#define WSZ 7
#define NHEAD 6
#define NT 49
#define HIDDEN 768
#define SCALE 0.17677669529663687f

// scratch for x + attention residual
__device__ float g_x2[(size_t)Bn * 56 * 56 * Cc];

// pre-transposed fp16 weights, [n][k] layout
__device__ __align__(16) __half g_qkvT[576 * 192];
__device__ __align__(16) __half g_projT[192 * 192];
__device__ __align__(16) __half g_fc1T[768 * 192];
__device__ __align__(16) __half g_fc2T[192 * 768];
// fused rel-pos bias + shift mask, padded: [win 64][head 6][row 64][col 56]
__device__ __align__(16) __half g_bias[64 * 6 * 64 * 56];

__global__ void convert_w(const float* __restrict__ qkv_w, const float* __restrict__ proj_w,
                          const float* __restrict__ fc1w, const float* __restrict__ fc2w,
                          const float* __restrict__ mask, const float* __restrict__ rel_table)
{
    int tid = blockIdx.x * blockDim.x + threadIdx.x;
    int stride = gridDim.x * blockDim.x;
    for (int j = tid; j < 192 * 576; j += stride) {
        int k = j / 576, n = j % 576;
        g_qkvT[n * 192 + k] = __float2half(qkv_w[j]);
    }
    for (int j = tid; j < 192 * 192; j += stride) {
        int k = j / 192, n = j % 192;
        g_projT[n * 192 + k] = __float2half(proj_w[j]);
    }
    for (int j = tid; j < 192 * 768; j += stride) {
        int k = j / 768, n = j % 768;
        g_fc1T[n * 192 + k] = __float2half(fc1w[j]);
    }
    for (int j = tid; j < 768 * 192; j += stride) {
        int k = j / 192, n = j % 192;
        g_fc2T[n * 768 + k] = __float2half(fc2w[j]);
    }
    for (int j = tid; j < 64 * 6 * 64 * 56; j += stride) {
        int col = j % 56;
        int rest = j / 56;
        int row = rest % 64; rest /= 64;
        int h = rest % 6;
        int w = rest / 6;
        float v;
        if (row >= NT)      v = 0.f;
        else if (col >= NT) v = -30000.f;
        else {
            int rr = row / 7 - col / 7 + 6;
            int cc = row % 7 - col % 7 + 6;
            v = rel_table[(rr * 13 + cc) * NHEAD + h] + mask[w * 2401 + row * 49 + col];
        }
        g_bias[j] = __float2half(v);
    }
}

// D = A(16x16 f16, row) x B(16x8 f16, col) + D, fp32 accum
__device__ __forceinline__ void mma16(float4& c, uint32_t a0, uint32_t a1, uint32_t a2,
                                      uint32_t a3, uint32_t b0, uint32_t b1) {
    asm volatile(
        "mma.sync.aligned.m16n8k16.row.col.f32.f16.f16.f32 "
        "{%0,%1,%2,%3},{%4,%5,%6,%7},{%8,%9},{%0,%1,%2,%3};"
        : "+f"(c.x), "+f"(c.y), "+f"(c.z), "+f"(c.w)
        : "r"(a0), "r"(a1), "r"(a2), "r"(a3), "r"(b0), "r"(b1));
}

__device__ __forceinline__ uint32_t smaddr(const void* p) {
    return (uint32_t)__cvta_generic_to_shared(p);
}

__device__ __forceinline__ void ldsm4(uint32_t& r0, uint32_t& r1, uint32_t& r2,
                                      uint32_t& r3, uint32_t a) {
    asm volatile("ldmatrix.sync.aligned.m8n8.x4.shared.b16 {%0,%1,%2,%3},[%4];"
                 : "=r"(r0), "=r"(r1), "=r"(r2), "=r"(r3) : "r"(a));
}

__device__ __forceinline__ uint32_t packh2(float a, float b) {
    __half2 h = __floats2half2_rn(a, b);
    return *(uint32_t*)&h;
}

__device__ __forceinline__ float gelu_exact(float v) {
    return 0.5f * v * (1.0f + erff(v * 0.70710678118654752f));
}

// ---------------------------------------------------------------------------
// Kernel 1: per-window LN1 -> QKV(mma) -> mma attention -> proj(mma)
// smem halves: xw[64][200] | qk[56][392] (Q|K) | vT[192][72] | wst[192][40]
// ---------------------------------------------------------------------------
#define XW_STRH 200
#define QK_STRH 392
#define VT_STRH 72
#define OFF_QK_H 12800        // 64*200
#define OFF_VT_H 34752        // + 56*392
#define OFF_WST_H 48576       // + 192*72
#define ATTN_SM_BYTES (56256 * 2)

__global__ __launch_bounds__(256, 2) void swin_attn_kernel(
    const float* __restrict__ x,
    const float* __restrict__ qkv_b, const float* __restrict__ proj_b,
    const float* __restrict__ n1w, const float* __restrict__ n1b)
{
    extern __shared__ __half smh[];
    __half* xwh = smh;                   // [64][200]  LN1 out / attn out
    __half* qkh = smh + OFF_QK_H;        // [56][392]  Q(0..191) K(192..383)
    __half* vth = smh + OFF_VT_H;        // [192][72]  V transposed
    uint32_t* xwu  = (uint32_t*)xwh;
    uint32_t* vtu  = (uint32_t*)vth;
    uint32_t* wstu = (uint32_t*)(smh + OFF_WST_H);   // [192][20] u32 weight stage
    const uint32_t* qkvT_u  = (const uint32_t*)g_qkvT;
    const uint32_t* projT_u = (const uint32_t*)g_projT;

    const int bid  = blockIdx.x;
    const int b    = bid >> 6;
    const int w    = bid & 63;
    const int wh   = w >> 3;
    const int ww   = w & 7;
    const int tid  = threadIdx.x;
    const int warp = tid >> 5;
    const int lane = tid & 31;
    const int g    = lane >> 2;
    const int q    = lane & 3;
    const int wm   = warp & 3;
    const int wn   = warp >> 2;
    const int rowA = 16 * wm + g;
    const int lr   = lane & 7;
    const int lb8  = (lane >> 3) & 1;
    const int lb16 = lane >> 4;

    // staging decomposition for this thread (768 uint4 per 32-k chunk)
    const int sn0 = tid >> 2, sc0 = (tid & 3) * 4;           // j=0
    const int sn1 = (tid + 256) >> 2, sc1 = ((tid + 256) & 3) * 4;
    const int sn2 = (tid + 512) >> 2, sc2 = ((tid + 512) & 3) * 4;

    // ldmatrix bases for the big GEMM loops
    const uint32_t aBase = smaddr(xwh + (16 * wm + lr + 8 * lb8) * XW_STRH + 8 * lb16);
    const uint32_t bBase = smaddr((__half*)wstu + (96 * wn + 8 * lb16 + lr) * 40 + 8 * lb8);

    // ---- zero pad regions: QK rows 49..55 and all of vT (pad keys must be 0) ----
    for (int idx = tid; idx < 192 * 36; idx += 256) vtu[idx] = 0u;
    for (int idx = tid; idx < 7 * 196; idx += 256)
        ((uint32_t*)qkh)[(49 + idx / 196) * 196 + idx % 196] = 0u;

    // prologue prefetch: QKV pass 0, chunk 0
    uint4 pre0 = *(const uint4*)(qkvT_u + (size_t)sn0 * 96 + sc0);
    uint4 pre1 = *(const uint4*)(qkvT_u + (size_t)sn1 * 96 + sc1);
    uint4 pre2 = *(const uint4*)(qkvT_u + (size_t)sn2 * 96 + sc2);

    // ---- Phase 1: gather (shifted window) + LN1 (xw rows>=49 zeroed) ----
    for (int n = warp; n < 64; n += 8) {
        if (n < NT) {
            int r  = wh * WSZ + n / WSZ;
            int c  = ww * WSZ + n % WSZ;
            int gr = r + 3; if (gr >= 56) gr -= 56;
            int gc = c + 3; if (gc >= 56) gc -= 56;
            const float* xr = x + ((size_t)b * 3136 + gr * 56 + gc) * Cc;
            float v[6]; float s = 0.f, ss = 0.f;
#pragma unroll
            for (int j = 0; j < 6; j++) { v[j] = xr[lane + 32 * j]; s += v[j]; ss += v[j] * v[j]; }
#pragma unroll
            for (int o = 16; o > 0; o >>= 1) {
                s  += __shfl_xor_sync(0xffffffffu, s,  o);
                ss += __shfl_xor_sync(0xffffffffu, ss, o);
            }
            float mean = s * (1.f / 192.f);
            float rinv = rsqrtf(ss * (1.f / 192.f) - mean * mean + 1e-5f);
#pragma unroll
            for (int j = 0; j < 6; j++) {
                int k = lane + 32 * j;
                xwh[n * XW_STRH + k] = __float2half((v[j] - mean) * rinv * n1w[k] + n1b[k]);
            }
        } else {
#pragma unroll
            for (int j = 0; j < 3; j++) xwu[n * 100 + lane + 32 * j] = 0u;
        }
    }

    // ---- Phase 2: QKV via f16 mma : out(64x192) per pass ----
    const bool v0 = rowA < NT, v1 = (rowA + 8) < NT;
    for (int p = 0; p < 3; p++) {
        float4 acc[12];
#pragma unroll
        for (int t = 0; t < 12; t++) acc[t] = make_float4(0.f, 0.f, 0.f, 0.f);

        for (int kc = 0; kc < 192; kc += 32) {
            __syncthreads();
            *(uint4*)(wstu + sn0 * 20 + sc0) = pre0;
            *(uint4*)(wstu + sn1 * 20 + sc1) = pre1;
            *(uint4*)(wstu + sn2 * 20 + sc2) = pre2;
            __syncthreads();
            // prefetch next stage (overlaps with compute below)
            int s = p * 6 + (kc >> 5) + 1;
            if (s < 18) {
                int np = s / 6, nk = (s % 6) << 4;   // nk in u32 units (32k = 16 u32)
                pre0 = *(const uint4*)(qkvT_u + (size_t)(np * 192 + sn0) * 96 + nk + sc0);
                pre1 = *(const uint4*)(qkvT_u + (size_t)(np * 192 + sn1) * 96 + nk + sc1);
                pre2 = *(const uint4*)(qkvT_u + (size_t)(np * 192 + sn2) * 96 + nk + sc2);
            } else {
                // prefetch proj chunk 0 (hidden behind attention phase)
                pre0 = *(const uint4*)(projT_u + (size_t)sn0 * 96 + sc0);
                pre1 = *(const uint4*)(projT_u + (size_t)sn1 * 96 + sc1);
                pre2 = *(const uint4*)(projT_u + (size_t)sn2 * 96 + sc2);
            }
#pragma unroll
            for (int k0 = 0; k0 < 32; k0 += 16) {
                uint32_t a0, a1, a2, a3;
                ldsm4(a0, a1, a2, a3, aBase + (kc + k0) * 2);
#pragma unroll
                for (int tp = 0; tp < 6; tp++) {
                    uint32_t b0, b1, b2, b3;
                    ldsm4(b0, b1, b2, b3, bBase + tp * 1280 + k0 * 2);
                    mma16(acc[2 * tp],     a0, a1, a2, a3, b0, b1);
                    mma16(acc[2 * tp + 1], a0, a1, a2, a3, b2, b3);
                }
            }
        }
#pragma unroll
        for (int t = 0; t < 12; t++) {
            int col = 96 * wn + 8 * t + 2 * q;
            int j   = 192 * p + col;
            float b0v = __ldg(qkv_b + j), b1v = __ldg(qkv_b + j + 1);
            float o00 = acc[t].x + b0v, o01 = acc[t].y + b1v;
            float o10 = acc[t].z + b0v, o11 = acc[t].w + b1v;
            if (p == 0) { o00 *= SCALE; o01 *= SCALE; o10 *= SCALE; o11 *= SCALE; }
            if (p < 2) {
                if (v0) *(__half2*)(qkh + rowA * QK_STRH + j)       = __floats2half2_rn(o00, o01);
                if (v1) *(__half2*)(qkh + (rowA + 8) * QK_STRH + j) = __floats2half2_rn(o10, o11);
            } else {
                if (v0) {
                    vth[col * VT_STRH + rowA]       = __float2half(o00);
                    vth[(col + 1) * VT_STRH + rowA] = __float2half(o01);
                }
                if (v1) {
                    vth[col * VT_STRH + rowA + 8]       = __float2half(o10);
                    vth[(col + 1) * VT_STRH + rowA + 8] = __float2half(o11);
                }
            }
        }
    }
    __syncthreads();

    // ---- Phase 3: mma attention over 24 (head, m-tile) units, 3 per warp ----
    {
#pragma unroll 1
        for (int t = 0; t < 3; t++) {
            const int u = warp * 3 + t;
            const int h = u >> 2;
            const int i = u & 3;
            const __half* bias = g_bias + ((size_t)(w * NHEAD + h)) * 64 * 56;
            const uint32_t kBase = smaddr(qkh + lr * QK_STRH + 192 + h * 32 + 8 * (lane >> 3));
            const uint32_t vBase = smaddr(vth + (h * 32 + lr) * VT_STRH + 8 * (lane >> 3));
            const int r0i = 16 * i + g, r1i = r0i + 8;

            // batch bias loads first (latency overlaps mma chain)
            float2 bb0[7], bb1[7];
#pragma unroll
            for (int j = 0; j < 7; j++) {
                bb0[j] = __half22float2(*(const __half2*)(bias + r0i * 56 + 8 * j + 2 * q));
                bb1[j] = __half22float2(*(const __half2*)(bias + r1i * 56 + 8 * j + 2 * q));
            }

            uint32_t qA = smaddr(qkh + (16 * i + lr + 8 * lb8) * QK_STRH + h * 32 + 8 * lb16);
            uint32_t aq[2][4];
            ldsm4(aq[0][0], aq[0][1], aq[0][2], aq[0][3], qA);
            ldsm4(aq[1][0], aq[1][1], aq[1][2], aq[1][3], qA + 32);
            // S = Q K^T + bias
            float4 S[7];
#pragma unroll
            for (int j = 0; j < 7; j++) {
                S[j] = make_float4(0.f, 0.f, 0.f, 0.f);
                uint32_t b0, b1, b2, b3;
                ldsm4(b0, b1, b2, b3, kBase + j * (8 * QK_STRH * 2));
                mma16(S[j], aq[0][0], aq[0][1], aq[0][2], aq[0][3], b0, b1);
                mma16(S[j], aq[1][0], aq[1][1], aq[1][2], aq[1][3], b2, b3);
                S[j].x += bb0[j].x; S[j].y += bb0[j].y;
                S[j].z += bb1[j].x; S[j].w += bb1[j].y;
            }
            // row softmax via quad reduction
            float mx0 = -1e30f, mx1 = -1e30f;
#pragma unroll
            for (int j = 0; j < 7; j++) {
                mx0 = fmaxf(mx0, fmaxf(S[j].x, S[j].y));
                mx1 = fmaxf(mx1, fmaxf(S[j].z, S[j].w));
            }
#pragma unroll
            for (int o = 1; o < 4; o <<= 1) {
                mx0 = fmaxf(mx0, __shfl_xor_sync(0xffffffffu, mx0, o));
                mx1 = fmaxf(mx1, __shfl_xor_sync(0xffffffffu, mx1, o));
            }
            float sum0 = 0.f, sum1 = 0.f;
#pragma unroll
            for (int j = 0; j < 7; j++) {
                S[j].x = __expf(S[j].x - mx0); S[j].y = __expf(S[j].y - mx0);
                S[j].z = __expf(S[j].z - mx1); S[j].w = __expf(S[j].w - mx1);
                sum0 += S[j].x + S[j].y; sum1 += S[j].z + S[j].w;
            }
#pragma unroll
            for (int o = 1; o < 4; o <<= 1) {
                sum0 += __shfl_xor_sync(0xffffffffu, sum0, o);
                sum1 += __shfl_xor_sync(0xffffffffu, sum1, o);
            }
            float rc0 = 1.f / sum0, rc1 = 1.f / sum1;
            // pack P into A-fragments (C-layout == A-layout identity)
            uint32_t pa[4][4];
#pragma unroll
            for (int kk = 0; kk < 3; kk++) {
                pa[kk][0] = packh2(S[2 * kk].x, S[2 * kk].y);
                pa[kk][1] = packh2(S[2 * kk].z, S[2 * kk].w);
                pa[kk][2] = packh2(S[2 * kk + 1].x, S[2 * kk + 1].y);
                pa[kk][3] = packh2(S[2 * kk + 1].z, S[2 * kk + 1].w);
            }
            pa[3][0] = packh2(S[6].x, S[6].y);
            pa[3][1] = packh2(S[6].z, S[6].w);
            pa[3][2] = 0u; pa[3][3] = 0u;
            // O = P V  (V from vT, pad keys zeroed)
            float4 O[4];
#pragma unroll
            for (int vj = 0; vj < 4; vj++) {
                O[vj] = make_float4(0.f, 0.f, 0.f, 0.f);
                uint32_t va0, va1, va2, va3, vb0, vb1, vb2, vb3;
                ldsm4(va0, va1, va2, va3, vBase + vj * (8 * VT_STRH * 2));
                ldsm4(vb0, vb1, vb2, vb3, vBase + vj * (8 * VT_STRH * 2) + 64);
                mma16(O[vj], pa[0][0], pa[0][1], pa[0][2], pa[0][3], va0, va1);
                mma16(O[vj], pa[1][0], pa[1][1], pa[1][2], pa[1][3], va2, va3);
                mma16(O[vj], pa[2][0], pa[2][1], pa[2][2], pa[2][3], vb0, vb1);
                mma16(O[vj], pa[3][0], pa[3][1], pa[3][2], pa[3][3], vb2, vb3);
            }
            // store normalized rows (<49) into xw
#pragma unroll
            for (int vj = 0; vj < 4; vj++) {
                int col = h * 32 + 8 * vj + 2 * q;
                if (r0i < NT)
                    *(__half2*)(xwh + r0i * XW_STRH + col) =
                        __floats2half2_rn(O[vj].x * rc0, O[vj].y * rc0);
                if (r1i < NT)
                    *(__half2*)(xwh + r1i * XW_STRH + col) =
                        __floats2half2_rn(O[vj].z * rc1, O[vj].w * rc1);
            }
        }
    }

    // ---- Phase 4: proj via f16 mma, fused residual scatter ----
    {
        float4 acc[12];
#pragma unroll
        for (int t = 0; t < 12; t++) acc[t] = make_float4(0.f, 0.f, 0.f, 0.f);

        for (int kc = 0; kc < 192; kc += 32) {
            __syncthreads();
            *(uint4*)(wstu + sn0 * 20 + sc0) = pre0;
            *(uint4*)(wstu + sn1 * 20 + sc1) = pre1;
            *(uint4*)(wstu + sn2 * 20 + sc2) = pre2;
            __syncthreads();
            if (kc + 32 < 192) {
                int nk = (kc >> 1) + 16;
                pre0 = *(const uint4*)(projT_u + (size_t)sn0 * 96 + nk + sc0);
                pre1 = *(const uint4*)(projT_u + (size_t)sn1 * 96 + nk + sc1);
                pre2 = *(const uint4*)(projT_u + (size_t)sn2 * 96 + nk + sc2);
            }
#pragma unroll
            for (int k0 = 0; k0 < 32; k0 += 16) {
                uint32_t a0, a1, a2, a3;
                ldsm4(a0, a1, a2, a3, aBase + (kc + k0) * 2);
#pragma unroll
                for (int tp = 0; tp < 6; tp++) {
                    uint32_t b0, b1, b2, b3;
                    ldsm4(b0, b1, b2, b3, bBase + tp * 1280 + k0 * 2);
                    mma16(acc[2 * tp],     a0, a1, a2, a3, b0, b1);
                    mma16(acc[2 * tp + 1], a0, a1, a2, a3, b2, b3);
                }
            }
        }

        size_t base0 = 0, base1 = 0;
        if (v0) {
            int gr = wh * 7 + rowA / 7 + 3; if (gr >= 56) gr -= 56;
            int gc = ww * 7 + rowA % 7 + 3; if (gc >= 56) gc -= 56;
            base0 = ((size_t)b * 3136 + gr * 56 + gc) * Cc;
        }
        if (v1) {
            int r1i = rowA + 8;
            int gr = wh * 7 + r1i / 7 + 3; if (gr >= 56) gr -= 56;
            int gc = ww * 7 + r1i % 7 + 3; if (gc >= 56) gc -= 56;
            base1 = ((size_t)b * 3136 + gr * 56 + gc) * Cc;
        }
#pragma unroll
        for (int t = 0; t < 12; t++) {
            int col = 96 * wn + 8 * t + 2 * q;
            float pb0 = __ldg(proj_b + col), pb1 = __ldg(proj_b + col + 1);
            if (v0) {
                float2 xv = *(const float2*)(x + base0 + col);
                float2 r; r.x = xv.x + acc[t].x + pb0; r.y = xv.y + acc[t].y + pb1;
                *(float2*)(g_x2 + base0 + col) = r;
            }
            if (v1) {
                float2 xv = *(const float2*)(x + base1 + col);
                float2 r; r.x = xv.x + acc[t].z + pb0; r.y = xv.y + acc[t].w + pb1;
                *(float2*)(g_x2 + base1 + col) = r;
            }
        }
    }
}

// ---------------------------------------------------------------------------
// Kernel 2: LN2 + MLP (f16 mma) + residual; 64 tokens/block, 1568 blocks
// ---------------------------------------------------------------------------
#define OFF_F1_H 12800
#define OFF_HS_H 25600
#define OFF_F2_H 30208
#define MLP_SM_BYTES (44032 * 2)

__global__ __launch_bounds__(256, 2) void swin_mlp_kernel(
    const float* __restrict__ n2w, const float* __restrict__ n2b,
    const float* __restrict__ fc1b, const float* __restrict__ fc2b,
    float* __restrict__ out)
{
    extern __shared__ __half smh[];
    __half* xnh = smh;                   // [64][200]
    uint32_t* f1u  = (uint32_t*)(smh + OFF_F1_H);   // [64][100] u32
    __half2*  hs2  = (__half2*)(smh + OFF_HS_H);    // [64][36] half2
    uint32_t* f2u  = (uint32_t*)(smh + OFF_F2_H);   // [192][36] u32
    const uint32_t* fc1T_u = (const uint32_t*)g_fc1T;
    const uint32_t* fc2T_u = (const uint32_t*)g_fc2T;

    const int tid  = threadIdx.x;
    const int warp = tid >> 5;
    const int lane = tid & 31;
    const int g    = lane >> 2;
    const int q    = lane & 3;
    const int wm   = warp & 3;
    const int wn   = warp >> 2;
    const int rowA = 16 * wm + g;
    const int lr   = lane & 7;
    const int lb8  = (lane >> 3) & 1;
    const int lb16 = lane >> 4;
    const size_t t0 = (size_t)blockIdx.x * 64;

    const uint32_t aBase1 = smaddr(xnh + (16 * wm + lr + 8 * lb8) * XW_STRH + 8 * lb16);
    const uint32_t b1Base = smaddr((__half*)f1u + (32 * wn + 8 * lb16 + lr) * 200 + 8 * lb8);
    const uint32_t aBase2 = smaddr((__half*)hs2 + (16 * wm + lr + 8 * lb8) * 72 + 8 * lb16);
    const uint32_t b2Base = smaddr((__half*)f2u + (96 * wn + 8 * lb16 + lr) * 72 + 8 * lb8);

    // fc1 staging decomposition (1536 uint4 per chunk, 6 per thread)
    int f1n[6], f1c[6], f2n[6], f2c[6];
#pragma unroll
    for (int j = 0; j < 6; j++) {
        int idx = tid + j * 256;
        f1n[j] = idx / 24; f1c[j] = (idx % 24) * 4;
        f2n[j] = idx >> 3; f2c[j] = (idx & 7) * 4;
    }
    // prologue prefetch fc1 + fc2 chunk 0
    uint4 preA[6], preB[6];
#pragma unroll
    for (int j = 0; j < 6; j++) {
        preA[j] = *(const uint4*)(fc1T_u + (size_t)f1n[j] * 96 + f1c[j]);
        preB[j] = *(const uint4*)(fc2T_u + (size_t)f2n[j] * 384 + f2c[j]);
    }

    // ---- LN2 ----
    for (int n = warp; n < 64; n += 8) {
        const float* xr = g_x2 + (t0 + n) * Cc;
        float v[6]; float s = 0.f, ss = 0.f;
#pragma unroll
        for (int j = 0; j < 6; j++) { v[j] = xr[lane + 32 * j]; s += v[j]; ss += v[j] * v[j]; }
#pragma unroll
        for (int o = 16; o > 0; o >>= 1) {
            s  += __shfl_xor_sync(0xffffffffu, s,  o);
            ss += __shfl_xor_sync(0xffffffffu, ss, o);
        }
        float mean = s * (1.f / 192.f);
        float rinv = rsqrtf(ss * (1.f / 192.f) - mean * mean + 1e-5f);
#pragma unroll
        for (int j = 0; j < 6; j++) {
            int k = lane + 32 * j;
            xnh[n * XW_STRH + k] = __float2half((v[j] - mean) * rinv * n2w[k] + n2b[k]);
        }
    }

    float4 yacc[12];
#pragma unroll
    for (int t = 0; t < 12; t++) yacc[t] = make_float4(0.f, 0.f, 0.f, 0.f);

    for (int hc = 0; hc < HIDDEN; hc += 64) {
        __syncthreads();
        // store prefetched fc1 + fc2 chunks
#pragma unroll
        for (int j = 0; j < 6; j++) {
            *(uint4*)(f1u + f1n[j] * 100 + f1c[j]) = preA[j];
            *(uint4*)(f2u + f2n[j] * 36 + f2c[j]) = preB[j];
        }
        __syncthreads();
        // prefetch next chunks (overlaps with compute)
        if (hc + 64 < HIDDEN) {
#pragma unroll
            for (int j = 0; j < 6; j++) {
                preA[j] = *(const uint4*)(fc1T_u + (size_t)(hc + 64 + f1n[j]) * 96 + f1c[j]);
                preB[j] = *(const uint4*)(fc2T_u + (size_t)f2n[j] * 384 + ((hc + 64) >> 1) + f2c[j]);
            }
        }

        // fc1: H(64x64) = xn(64x192) @ w1chunk ; warp tile m16 x n32
        float4 acc1[4];
#pragma unroll
        for (int t = 0; t < 4; t++) acc1[t] = make_float4(0.f, 0.f, 0.f, 0.f);
#pragma unroll
        for (int k0 = 0; k0 < 192; k0 += 16) {
            uint32_t a0, a1, a2, a3;
            ldsm4(a0, a1, a2, a3, aBase1 + k0 * 2);
#pragma unroll
            for (int tp = 0; tp < 2; tp++) {
                uint32_t b0, b1, b2, b3;
                ldsm4(b0, b1, b2, b3, b1Base + tp * 6400 + k0 * 2);
                mma16(acc1[2 * tp],     a0, a1, a2, a3, b0, b1);
                mma16(acc1[2 * tp + 1], a0, a1, a2, a3, b2, b3);
            }
        }
        // bias + gelu -> hs
#pragma unroll
        for (int t = 0; t < 4; t++) {
            int col = 32 * wn + 8 * t + 2 * q;
            float b0v = __ldg(fc1b + hc + col), b1v = __ldg(fc1b + hc + col + 1);
            int wi = 16 * wn + 4 * t + q;
            hs2[rowA * 36 + wi]       = __floats2half2_rn(gelu_exact(acc1[t].x + b0v),
                                                          gelu_exact(acc1[t].y + b1v));
            hs2[(rowA + 8) * 36 + wi] = __floats2half2_rn(gelu_exact(acc1[t].z + b0v),
                                                          gelu_exact(acc1[t].w + b1v));
        }
        __syncthreads();

        // fc2: Y(64x192) += H(64x64) @ w2chunk ; warp tile m16 x n96
#pragma unroll
        for (int k0 = 0; k0 < 64; k0 += 16) {
            uint32_t a0, a1, a2, a3;
            ldsm4(a0, a1, a2, a3, aBase2 + k0 * 2);
#pragma unroll
            for (int tp = 0; tp < 6; tp++) {
                uint32_t b0, b1, b2, b3;
                ldsm4(b0, b1, b2, b3, b2Base + tp * 2304 + k0 * 2);
                mma16(yacc[2 * tp],     a0, a1, a2, a3, b0, b1);
                mma16(yacc[2 * tp + 1], a0, a1, a2, a3, b2, b3);
            }
        }
    }

#pragma unroll
    for (int t = 0; t < 12; t++) {
        int col = 96 * wn + 8 * t + 2 * q;
        float b0v = __ldg(fc2b + col), b1v = __ldg(fc2b + col + 1);
        {
            size_t base = (t0 + rowA) * Cc + col;
            float2 xv = *(const float2*)(g_x2 + base);
            float2 r; r.x = xv.x + yacc[t].x + b0v; r.y = xv.y + yacc[t].y + b1v;
            *(float2*)(out + base) = r;
        }
        {
            size_t base = (t0 + rowA + 8) * Cc + col;
            float2 xv = *(const float2*)(g_x2 + base);
            float2 r; r.x = xv.x + yacc[t].z + b0v; r.y = xv.y + yacc[t].w + b1v;
            *(float2*)(out + base) = r;
        }
    }
}

// ---------------------------------------------------------------------------
extern "C" void kernel_launch(void* const* d_in, const int* in_sizes, int n_in,
                              void* d_out, int out_size)
{
    const float* x      = (const float*)d_in[0];
    const float* mask   = (const float*)d_in[1];
    const float* rel    = (const float*)d_in[2];
    const float* qkv_w  = (const float*)d_in[3];
    const float* qkv_b  = (const float*)d_in[4];
    const float* proj_w = (const float*)d_in[5];
    const float* proj_b = (const float*)d_in[6];
    const float* n1w    = (const float*)d_in[7];
    const float* n1b    = (const float*)d_in[8];
    const float* n2w    = (const float*)d_in[9];
    const float* n2b    = (const float*)d_in[10];
    const float* fc1w   = (const float*)d_in[11];
    const float* fc1b   = (const float*)d_in[12];
    const float* fc2w   = (const float*)d_in[13];
    const float* fc2b   = (const float*)d_in[14];
    float* out = (float*)d_out;

    cudaFuncSetAttribute(swin_attn_kernel, cudaFuncAttributeMaxDynamicSharedMemorySize,
                         ATTN_SM_BYTES);
    cudaFuncSetAttribute(swin_mlp_kernel, cudaFuncAttributeMaxDynamicSharedMemorySize,
                         MLP_SM_BYTES);

    convert_w<<<1184, 256>>>(qkv_w, proj_w, fc1w, fc2w, mask, rel);
    swin_attn_kernel<<<Bn * 64, 256, ATTN_SM_BYTES>>>(x, qkv_b, proj_b, n1w, n1b);
    swin_mlp_kernel<<<1568, 256, MLP_SM_BYTES>>>(n2w, n2b, fc1b, fc2b, out);
}

// round 10
// speedup vs baseline: 5.5018x; 1.0206x over previous
#include <cuda_runtime.h>
#include <cuda_fp16.h>
#include <math.h>
#include <stdint.h>

#define Bn 32
#define Cc 192
#define WSZ 7
#define NHEAD 6
#define NT 49
#define HIDDEN 768
#define SCALE 0.17677669529663687f
#define ATTN_BLOCKS 2048
#define MLP_BLOCKS 1568

// scratch for x + attention residual
__device__ float g_x2[(size_t)Bn * 56 * 56 * Cc];
// dependency counters: [batch 32][band 8] — band wh complete when count==8
__device__ int g_dep[Bn * 8];

// pre-transposed fp16 weights, [n][k] layout
__device__ __align__(16) __half g_qkvT[576 * 192];
__device__ __align__(16) __half g_projT[192 * 192];
__device__ __align__(16) __half g_fc1T[768 * 192];
__device__ __align__(16) __half g_fc2T[192 * 768];
// fused rel-pos bias + shift mask, padded: [win 64][head 6][row 64][col 56]
__device__ __align__(16) __half g_bias[64 * 6 * 64 * 56];

__global__ void convert_w(const float* __restrict__ qkv_w, const float* __restrict__ proj_w,
                          const float* __restrict__ fc1w, const float* __restrict__ fc2w,
                          const float* __restrict__ mask, const float* __restrict__ rel_table)
{
    int tid = blockIdx.x * blockDim.x + threadIdx.x;
    int stride = gridDim.x * blockDim.x;
    if (tid < Bn * 8) g_dep[tid] = 0;          // reset dependency counters each replay
    for (int j = tid; j < 192 * 576; j += stride) {
        int k = j / 576, n = j % 576;
        g_qkvT[n * 192 + k] = __float2half(qkv_w[j]);
    }
    for (int j = tid; j < 192 * 192; j += stride) {
        int k = j / 192, n = j % 192;
        g_projT[n * 192 + k] = __float2half(proj_w[j]);
    }
    for (int j = tid; j < 192 * 768; j += stride) {
        int k = j / 768, n = j % 768;
        g_fc1T[n * 192 + k] = __float2half(fc1w[j]);
    }
    for (int j = tid; j < 768 * 192; j += stride) {
        int k = j / 192, n = j % 192;
        g_fc2T[n * 768 + k] = __float2half(fc2w[j]);
    }
    for (int j = tid; j < 64 * 6 * 64 * 56; j += stride) {
        int col = j % 56;
        int rest = j / 56;
        int row = rest % 64; rest /= 64;
        int h = rest % 6;
        int w = rest / 6;
        float v;
        if (row >= NT)      v = 0.f;
        else if (col >= NT) v = -30000.f;
        else {
            int rr = row / 7 - col / 7 + 6;
            int cc = row % 7 - col % 7 + 6;
            v = rel_table[(rr * 13 + cc) * NHEAD + h] + mask[w * 2401 + row * 49 + col];
        }
        g_bias[j] = __float2half(v);
    }
}

// D = A(16x16 f16, row) x B(16x8 f16, col) + D, fp32 accum
__device__ __forceinline__ void mma16(float4& c, uint32_t a0, uint32_t a1, uint32_t a2,
                                      uint32_t a3, uint32_t b0, uint32_t b1) {
    asm volatile(
        "mma.sync.aligned.m16n8k16.row.col.f32.f16.f16.f32 "
        "{%0,%1,%2,%3},{%4,%5,%6,%7},{%8,%9},{%0,%1,%2,%3};"
        : "+f"(c.x), "+f"(c.y), "+f"(c.z), "+f"(c.w)
        : "r"(a0), "r"(a1), "r"(a2), "r"(a3), "r"(b0), "r"(b1));
}

__device__ __forceinline__ uint32_t smaddr(const void* p) {
    return (uint32_t)__cvta_generic_to_shared(p);
}

__device__ __forceinline__ void ldsm4(uint32_t& r0, uint32_t& r1, uint32_t& r2,
                                      uint32_t& r3, uint32_t a) {
    asm volatile("ldmatrix.sync.aligned.m8n8.x4.shared.b16 {%0,%1,%2,%3},[%4];"
                 : "=r"(r0), "=r"(r1), "=r"(r2), "=r"(r3) : "r"(a));
}

__device__ __forceinline__ uint32_t packh2(float a, float b) {
    __half2 h = __floats2half2_rn(a, b);
    return *(uint32_t*)&h;
}

__device__ __forceinline__ float gelu_exact(float v) {
    return 0.5f * v * (1.0f + erff(v * 0.70710678118654752f));
}

// ---------------------------------------------------------------------------
// Fused kernel: bids [0,2048) attention path, [2048,3616) MLP path
// attn smem halves: xw[64][200] | qk[56][392] | vT[192][72] | wst[192][40]
// mlp  smem halves: xn[64][200] | f1[64][200] | hs[64][72] | f2[192][72]
// ---------------------------------------------------------------------------
#define XW_STRH 200
#define QK_STRH 392
#define VT_STRH 72
#define OFF_QK_H 12800        // 64*200
#define OFF_VT_H 34752        // + 56*392
#define OFF_WST_H 48576       // + 192*72
#define FUSED_SM_BYTES (56256 * 2)
#define OFF_F1_H 12800
#define OFF_HS_H 25600
#define OFF_F2_H 30208

__device__ __forceinline__ void attn_body(
    __half* smh, int bid,
    const float* __restrict__ x,
    const float* __restrict__ qkv_b, const float* __restrict__ proj_b,
    const float* __restrict__ n1w, const float* __restrict__ n1b)
{
    __half* xwh = smh;                   // [64][200]  LN1 out / attn out
    __half* qkh = smh + OFF_QK_H;        // [56][392]  Q(0..191) K(192..383)
    __half* vth = smh + OFF_VT_H;        // [192][72]  V transposed
    uint32_t* xwu  = (uint32_t*)xwh;
    uint32_t* vtu  = (uint32_t*)vth;
    uint32_t* wstu = (uint32_t*)(smh + OFF_WST_H);   // [192][20] u32 weight stage
    const uint32_t* qkvT_u  = (const uint32_t*)g_qkvT;
    const uint32_t* projT_u = (const uint32_t*)g_projT;

    const int b    = bid >> 6;
    const int w    = bid & 63;
    const int wh   = w >> 3;
    const int ww   = w & 7;
    const int tid  = threadIdx.x;
    const int warp = tid >> 5;
    const int lane = tid & 31;
    const int g    = lane >> 2;
    const int q    = lane & 3;
    const int wm   = warp & 3;
    const int wn   = warp >> 2;
    const int rowA = 16 * wm + g;
    const int lr   = lane & 7;
    const int lb8  = (lane >> 3) & 1;
    const int lb16 = lane >> 4;

    // staging decomposition for this thread (768 uint4 per 32-k chunk)
    const int sn0 = tid >> 2, sc0 = (tid & 3) * 4;
    const int sn1 = (tid + 256) >> 2, sc1 = ((tid + 256) & 3) * 4;
    const int sn2 = (tid + 512) >> 2, sc2 = ((tid + 512) & 3) * 4;

    const uint32_t aBase = smaddr(xwh + (16 * wm + lr + 8 * lb8) * XW_STRH + 8 * lb16);
    const uint32_t bBase = smaddr((__half*)wstu + (96 * wn + 8 * lb16 + lr) * 40 + 8 * lb8);

    // ---- zero pad regions ----
    for (int idx = tid; idx < 192 * 36; idx += 256) vtu[idx] = 0u;
    for (int idx = tid; idx < 7 * 196; idx += 256)
        ((uint32_t*)qkh)[(49 + idx / 196) * 196 + idx % 196] = 0u;

    // prologue prefetch: QKV pass 0, chunk 0
    uint4 pre0 = *(const uint4*)(qkvT_u + (size_t)sn0 * 96 + sc0);
    uint4 pre1 = *(const uint4*)(qkvT_u + (size_t)sn1 * 96 + sc1);
    uint4 pre2 = *(const uint4*)(qkvT_u + (size_t)sn2 * 96 + sc2);

    // ---- Phase 1: gather (shifted window) + LN1 ----
    for (int n = warp; n < 64; n += 8) {
        if (n < NT) {
            int r  = wh * WSZ + n / WSZ;
            int c  = ww * WSZ + n % WSZ;
            int gr = r + 3; if (gr >= 56) gr -= 56;
            int gc = c + 3; if (gc >= 56) gc -= 56;
            const float* xr = x + ((size_t)b * 3136 + gr * 56 + gc) * Cc;
            float v[6]; float s = 0.f, ss = 0.f;
#pragma unroll
            for (int j = 0; j < 6; j++) { v[j] = xr[lane + 32 * j]; s += v[j]; ss += v[j] * v[j]; }
#pragma unroll
            for (int o = 16; o > 0; o >>= 1) {
                s  += __shfl_xor_sync(0xffffffffu, s,  o);
                ss += __shfl_xor_sync(0xffffffffu, ss, o);
            }
            float mean = s * (1.f / 192.f);
            float rinv = rsqrtf(ss * (1.f / 192.f) - mean * mean + 1e-5f);
#pragma unroll
            for (int j = 0; j < 6; j++) {
                int k = lane + 32 * j;
                xwh[n * XW_STRH + k] = __float2half((v[j] - mean) * rinv * n1w[k] + n1b[k]);
            }
        } else {
#pragma unroll
            for (int j = 0; j < 3; j++) xwu[n * 100 + lane + 32 * j] = 0u;
        }
    }

    // ---- Phase 2: QKV via f16 mma ----
    const bool v0 = rowA < NT, v1 = (rowA + 8) < NT;
    for (int p = 0; p < 3; p++) {
        float4 acc[12];
#pragma unroll
        for (int t = 0; t < 12; t++) acc[t] = make_float4(0.f, 0.f, 0.f, 0.f);

        for (int kc = 0; kc < 192; kc += 32) {
            __syncthreads();
            *(uint4*)(wstu + sn0 * 20 + sc0) = pre0;
            *(uint4*)(wstu + sn1 * 20 + sc1) = pre1;
            *(uint4*)(wstu + sn2 * 20 + sc2) = pre2;
            __syncthreads();
            int s = p * 6 + (kc >> 5) + 1;
            if (s < 18) {
                int np = s / 6, nk = (s % 6) << 4;
                pre0 = *(const uint4*)(qkvT_u + (size_t)(np * 192 + sn0) * 96 + nk + sc0);
                pre1 = *(const uint4*)(qkvT_u + (size_t)(np * 192 + sn1) * 96 + nk + sc1);
                pre2 = *(const uint4*)(qkvT_u + (size_t)(np * 192 + sn2) * 96 + nk + sc2);
            } else {
                pre0 = *(const uint4*)(projT_u + (size_t)sn0 * 96 + sc0);
                pre1 = *(const uint4*)(projT_u + (size_t)sn1 * 96 + sc1);
                pre2 = *(const uint4*)(projT_u + (size_t)sn2 * 96 + sc2);
            }
#pragma unroll
            for (int k0 = 0; k0 < 32; k0 += 16) {
                uint32_t a0, a1, a2, a3;
                ldsm4(a0, a1, a2, a3, aBase + (kc + k0) * 2);
#pragma unroll
                for (int tp = 0; tp < 6; tp++) {
                    uint32_t b0, b1, b2, b3;
                    ldsm4(b0, b1, b2, b3, bBase + tp * 1280 + k0 * 2);
                    mma16(acc[2 * tp],     a0, a1, a2, a3, b0, b1);
                    mma16(acc[2 * tp + 1], a0, a1, a2, a3, b2, b3);
                }
            }
        }
#pragma unroll
        for (int t = 0; t < 12; t++) {
            int col = 96 * wn + 8 * t + 2 * q;
            int j   = 192 * p + col;
            float b0v = __ldg(qkv_b + j), b1v = __ldg(qkv_b + j + 1);
            float o00 = acc[t].x + b0v, o01 = acc[t].y + b1v;
            float o10 = acc[t].z + b0v, o11 = acc[t].w + b1v;
            if (p == 0) { o00 *= SCALE; o01 *= SCALE; o10 *= SCALE; o11 *= SCALE; }
            if (p < 2) {
                if (v0) *(__half2*)(qkh + rowA * QK_STRH + j)       = __floats2half2_rn(o00, o01);
                if (v1) *(__half2*)(qkh + (rowA + 8) * QK_STRH + j) = __floats2half2_rn(o10, o11);
            } else {
                if (v0) {
                    vth[col * VT_STRH + rowA]       = __float2half(o00);
                    vth[(col + 1) * VT_STRH + rowA] = __float2half(o01);
                }
                if (v1) {
                    vth[col * VT_STRH + rowA + 8]       = __float2half(o10);
                    vth[(col + 1) * VT_STRH + rowA + 8] = __float2half(o11);
                }
            }
        }
    }
    __syncthreads();

    // ---- Phase 3: mma attention over 24 (head, m-tile) units, 3 per warp ----
    {
#pragma unroll 1
        for (int t = 0; t < 3; t++) {
            const int u = warp * 3 + t;
            const int h = u >> 2;
            const int i = u & 3;
            const __half* bias = g_bias + ((size_t)(w * NHEAD + h)) * 64 * 56;
            const uint32_t kBase = smaddr(qkh + lr * QK_STRH + 192 + h * 32 + 8 * (lane >> 3));
            const uint32_t vBase = smaddr(vth + (h * 32 + lr) * VT_STRH + 8 * (lane >> 3));
            const int r0i = 16 * i + g, r1i = r0i + 8;

            float2 bb0[7], bb1[7];
#pragma unroll
            for (int j = 0; j < 7; j++) {
                bb0[j] = __half22float2(*(const __half2*)(bias + r0i * 56 + 8 * j + 2 * q));
                bb1[j] = __half22float2(*(const __half2*)(bias + r1i * 56 + 8 * j + 2 * q));
            }

            uint32_t qA = smaddr(qkh + (16 * i + lr + 8 * lb8) * QK_STRH + h * 32 + 8 * lb16);
            uint32_t aq[2][4];
            ldsm4(aq[0][0], aq[0][1], aq[0][2], aq[0][3], qA);
            ldsm4(aq[1][0], aq[1][1], aq[1][2], aq[1][3], qA + 32);
            float4 S[7];
#pragma unroll
            for (int j = 0; j < 7; j++) {
                S[j] = make_float4(0.f, 0.f, 0.f, 0.f);
                uint32_t b0, b1, b2, b3;
                ldsm4(b0, b1, b2, b3, kBase + j * (8 * QK_STRH * 2));
                mma16(S[j], aq[0][0], aq[0][1], aq[0][2], aq[0][3], b0, b1);
                mma16(S[j], aq[1][0], aq[1][1], aq[1][2], aq[1][3], b2, b3);
                S[j].x += bb0[j].x; S[j].y += bb0[j].y;
                S[j].z += bb1[j].x; S[j].w += bb1[j].y;
            }
            float mx0 = -1e30f, mx1 = -1e30f;
#pragma unroll
            for (int j = 0; j < 7; j++) {
                mx0 = fmaxf(mx0, fmaxf(S[j].x, S[j].y));
                mx1 = fmaxf(mx1, fmaxf(S[j].z, S[j].w));
            }
#pragma unroll
            for (int o = 1; o < 4; o <<= 1) {
                mx0 = fmaxf(mx0, __shfl_xor_sync(0xffffffffu, mx0, o));
                mx1 = fmaxf(mx1, __shfl_xor_sync(0xffffffffu, mx1, o));
            }
            float sum0 = 0.f, sum1 = 0.f;
#pragma unroll
            for (int j = 0; j < 7; j++) {
                S[j].x = __expf(S[j].x - mx0); S[j].y = __expf(S[j].y - mx0);
                S[j].z = __expf(S[j].z - mx1); S[j].w = __expf(S[j].w - mx1);
                sum0 += S[j].x + S[j].y; sum1 += S[j].z + S[j].w;
            }
#pragma unroll
            for (int o = 1; o < 4; o <<= 1) {
                sum0 += __shfl_xor_sync(0xffffffffu, sum0, o);
                sum1 += __shfl_xor_sync(0xffffffffu, sum1, o);
            }
            float rc0 = 1.f / sum0, rc1 = 1.f / sum1;
            uint32_t pa[4][4];
#pragma unroll
            for (int kk = 0; kk < 3; kk++) {
                pa[kk][0] = packh2(S[2 * kk].x, S[2 * kk].y);
                pa[kk][1] = packh2(S[2 * kk].z, S[2 * kk].w);
                pa[kk][2] = packh2(S[2 * kk + 1].x, S[2 * kk + 1].y);
                pa[kk][3] = packh2(S[2 * kk + 1].z, S[2 * kk + 1].w);
            }
            pa[3][0] = packh2(S[6].x, S[6].y);
            pa[3][1] = packh2(S[6].z, S[6].w);
            pa[3][2] = 0u; pa[3][3] = 0u;
            float4 O[4];
#pragma unroll
            for (int vj = 0; vj < 4; vj++) {
                O[vj] = make_float4(0.f, 0.f, 0.f, 0.f);
                uint32_t va0, va1, va2, va3, vb0, vb1, vb2, vb3;
                ldsm4(va0, va1, va2, va3, vBase + vj * (8 * VT_STRH * 2));
                ldsm4(vb0, vb1, vb2, vb3, vBase + vj * (8 * VT_STRH * 2) + 64);
                mma16(O[vj], pa[0][0], pa[0][1], pa[0][2], pa[0][3], va0, va1);
                mma16(O[vj], pa[1][0], pa[1][1], pa[1][2], pa[1][3], va2, va3);
                mma16(O[vj], pa[2][0], pa[2][1], pa[2][2], pa[2][3], vb0, vb1);
                mma16(O[vj], pa[3][0], pa[3][1], pa[3][2], pa[3][3], vb2, vb3);
            }
#pragma unroll
            for (int vj = 0; vj < 4; vj++) {
                int col = h * 32 + 8 * vj + 2 * q;
                if (r0i < NT)
                    *(__half2*)(xwh + r0i * XW_STRH + col) =
                        __floats2half2_rn(O[vj].x * rc0, O[vj].y * rc0);
                if (r1i < NT)
                    *(__half2*)(xwh + r1i * XW_STRH + col) =
                        __floats2half2_rn(O[vj].z * rc1, O[vj].w * rc1);
            }
        }
    }

    // ---- Phase 4: proj via f16 mma, fused residual scatter ----
    {
        float4 acc[12];
#pragma unroll
        for (int t = 0; t < 12; t++) acc[t] = make_float4(0.f, 0.f, 0.f, 0.f);

        for (int kc = 0; kc < 192; kc += 32) {
            __syncthreads();
            *(uint4*)(wstu + sn0 * 20 + sc0) = pre0;
            *(uint4*)(wstu + sn1 * 20 + sc1) = pre1;
            *(uint4*)(wstu + sn2 * 20 + sc2) = pre2;
            __syncthreads();
            if (kc + 32 < 192) {
                int nk = (kc >> 1) + 16;
                pre0 = *(const uint4*)(projT_u + (size_t)sn0 * 96 + nk + sc0);
                pre1 = *(const uint4*)(projT_u + (size_t)sn1 * 96 + nk + sc1);
                pre2 = *(const uint4*)(projT_u + (size_t)sn2 * 96 + nk + sc2);
            }
#pragma unroll
            for (int k0 = 0; k0 < 32; k0 += 16) {
                uint32_t a0, a1, a2, a3;
                ldsm4(a0, a1, a2, a3, aBase + (kc + k0) * 2);
#pragma unroll
                for (int tp = 0; tp < 6; tp++) {
                    uint32_t b0, b1, b2, b3;
                    ldsm4(b0, b1, b2, b3, bBase + tp * 1280 + k0 * 2);
                    mma16(acc[2 * tp],     a0, a1, a2, a3, b0, b1);
                    mma16(acc[2 * tp + 1], a0, a1, a2, a3, b2, b3);
                }
            }
        }

        size_t base0 = 0, base1 = 0;
        if (v0) {
            int gr = wh * 7 + rowA / 7 + 3; if (gr >= 56) gr -= 56;
            int gc = ww * 7 + rowA % 7 + 3; if (gc >= 56) gc -= 56;
            base0 = ((size_t)b * 3136 + gr * 56 + gc) * Cc;
        }
        if (v1) {
            int r1i = rowA + 8;
            int gr = wh * 7 + r1i / 7 + 3; if (gr >= 56) gr -= 56;
            int gc = ww * 7 + r1i % 7 + 3; if (gc >= 56) gc -= 56;
            base1 = ((size_t)b * 3136 + gr * 56 + gc) * Cc;
        }
#pragma unroll
        for (int t = 0; t < 12; t++) {
            int col = 96 * wn + 8 * t + 2 * q;
            float pb0 = __ldg(proj_b + col), pb1 = __ldg(proj_b + col + 1);
            if (v0) {
                float2 xv = *(const float2*)(x + base0 + col);
                float2 r; r.x = xv.x + acc[t].x + pb0; r.y = xv.y + acc[t].y + pb1;
                *(float2*)(g_x2 + base0 + col) = r;
            }
            if (v1) {
                float2 xv = *(const float2*)(x + base1 + col);
                float2 r; r.x = xv.x + acc[t].z + pb0; r.y = xv.y + acc[t].w + pb1;
                *(float2*)(g_x2 + base1 + col) = r;
            }
        }
    }

    // ---- release: band (b, wh) progress ----
    __threadfence();
    __syncthreads();
    if (tid == 0) atomicAdd(&g_dep[b * 8 + wh], 1);
}

__device__ __forceinline__ void mlp_body(
    __half* smh, int m,
    const float* __restrict__ n2w, const float* __restrict__ n2b,
    const float* __restrict__ fc1b, const float* __restrict__ fc2b,
    float* __restrict__ out)
{
    __half* xnh = smh;                   // [64][200]
    uint32_t* f1u  = (uint32_t*)(smh + OFF_F1_H);   // [64][100] u32
    __half2*  hs2  = (__half2*)(smh + OFF_HS_H);    // [64][36] half2
    uint32_t* f2u  = (uint32_t*)(smh + OFF_F2_H);   // [192][36] u32
    const uint32_t* fc1T_u = (const uint32_t*)g_fc1T;
    const uint32_t* fc2T_u = (const uint32_t*)g_fc2T;

    const int tid  = threadIdx.x;
    const int warp = tid >> 5;
    const int lane = tid & 31;
    const int g    = lane >> 2;
    const int q    = lane & 3;
    const int wm   = warp & 3;
    const int wn   = warp >> 2;
    const int rowA = 16 * wm + g;
    const int lr   = lane & 7;
    const int lb8  = (lane >> 3) & 1;
    const int lb16 = lane >> 4;
    const size_t t0 = (size_t)m * 64;

    const uint32_t aBase1 = smaddr(xnh + (16 * wm + lr + 8 * lb8) * XW_STRH + 8 * lb16);
    const uint32_t b1Base = smaddr((__half*)f1u + (32 * wn + 8 * lb16 + lr) * 200 + 8 * lb8);
    const uint32_t aBase2 = smaddr((__half*)hs2 + (16 * wm + lr + 8 * lb8) * 72 + 8 * lb16);
    const uint32_t b2Base = smaddr((__half*)f2u + (96 * wn + 8 * lb16 + lr) * 72 + 8 * lb8);

    int f1n[6], f1c[6], f2n[6], f2c[6];
#pragma unroll
    for (int j = 0; j < 6; j++) {
        int idx = tid + j * 256;
        f1n[j] = idx / 24; f1c[j] = (idx % 24) * 4;
        f2n[j] = idx >> 3; f2c[j] = (idx & 7) * 4;
    }
    uint4 preA[6], preB[6];
#pragma unroll
    for (int j = 0; j < 6; j++) {
        preA[j] = *(const uint4*)(fc1T_u + (size_t)f1n[j] * 96 + f1c[j]);
        preB[j] = *(const uint4*)(fc2T_u + (size_t)f2n[j] * 384 + f2c[j]);
    }

    // ---- acquire: wait for the attn bands covering these 64 tokens ----
    {
        int mm = m % 49;
        int bb = m / 49;
        int gr0 = (mm * 64) / 56;
        int gr1 = (mm * 64 + 63) / 56;
        int i0 = bb * 8 + ((gr0 + 53) % 56) / 7;
        int i1 = bb * 8 + ((gr1 + 53) % 56) / 7;
        if (tid == 0) {
            while (atomicAdd(&g_dep[i0], 0) < 8 || atomicAdd(&g_dep[i1], 0) < 8)
                __nanosleep(100);
        }
        __syncthreads();
    }

    // ---- LN2 ----
    for (int n = warp; n < 64; n += 8) {
        const float* xr = g_x2 + (t0 + n) * Cc;
        float v[6]; float s = 0.f, ss = 0.f;
#pragma unroll
        for (int j = 0; j < 6; j++) { v[j] = xr[lane + 32 * j]; s += v[j]; ss += v[j] * v[j]; }
#pragma unroll
        for (int o = 16; o > 0; o >>= 1) {
            s  += __shfl_xor_sync(0xffffffffu, s,  o);
            ss += __shfl_xor_sync(0xffffffffu, ss, o);
        }
        float mean = s * (1.f / 192.f);
        float rinv = rsqrtf(ss * (1.f / 192.f) - mean * mean + 1e-5f);
#pragma unroll
        for (int j = 0; j < 6; j++) {
            int k = lane + 32 * j;
            xnh[n * XW_STRH + k] = __float2half((v[j] - mean) * rinv * n2w[k] + n2b[k]);
        }
    }

    float4 yacc[12];
#pragma unroll
    for (int t = 0; t < 12; t++) yacc[t] = make_float4(0.f, 0.f, 0.f, 0.f);

    for (int hc = 0; hc < HIDDEN; hc += 64) {
        __syncthreads();
#pragma unroll
        for (int j = 0; j < 6; j++) {
            *(uint4*)(f1u + f1n[j] * 100 + f1c[j]) = preA[j];
            *(uint4*)(f2u + f2n[j] * 36 + f2c[j]) = preB[j];
        }
        __syncthreads();
        if (hc + 64 < HIDDEN) {
#pragma unroll
            for (int j = 0; j < 6; j++) {
                preA[j] = *(const uint4*)(fc1T_u + (size_t)(hc + 64 + f1n[j]) * 96 + f1c[j]);
                preB[j] = *(const uint4*)(fc2T_u + (size_t)f2n[j] * 384 + ((hc + 64) >> 1) + f2c[j]);
            }
        }

        float4 acc1[4];
#pragma unroll
        for (int t = 0; t < 4; t++) acc1[t] = make_float4(0.f, 0.f, 0.f, 0.f);
#pragma unroll
        for (int k0 = 0; k0 < 192; k0 += 16) {
            uint32_t a0, a1, a2, a3;
            ldsm4(a0, a1, a2, a3, aBase1 + k0 * 2);
#pragma unroll
            for (int tp = 0; tp < 2; tp++) {
                uint32_t b0, b1, b2, b3;
                ldsm4(b0, b1, b2, b3, b1Base + tp * 6400 + k0 * 2);
                mma16(acc1[2 * tp],     a0, a1, a2, a3, b0, b1);
                mma16(acc1[2 * tp + 1], a0, a1, a2, a3, b2, b3);
            }
        }
#pragma unroll
        for (int t = 0; t < 4; t++) {
            int col = 32 * wn + 8 * t + 2 * q;
            float b0v = __ldg(fc1b + hc + col), b1v = __ldg(fc1b + hc + col + 1);
            int wi = 16 * wn + 4 * t + q;
            hs2[rowA * 36 + wi]       = __floats2half2_rn(gelu_exact(acc1[t].x + b0v),
                                                          gelu_exact(acc1[t].y + b1v));
            hs2[(rowA + 8) * 36 + wi] = __floats2half2_rn(gelu_exact(acc1[t].z + b0v),
                                                          gelu_exact(acc1[t].w + b1v));
        }
        __syncthreads();

#pragma unroll
        for (int k0 = 0; k0 < 64; k0 += 16) {
            uint32_t a0, a1, a2, a3;
            ldsm4(a0, a1, a2, a3, aBase2 + k0 * 2);
#pragma unroll
            for (int tp = 0; tp < 6; tp++) {
                uint32_t b0, b1, b2, b3;
                ldsm4(b0, b1, b2, b3, b2Base + tp * 2304 + k0 * 2);
                mma16(yacc[2 * tp],     a0, a1, a2, a3, b0, b1);
                mma16(yacc[2 * tp + 1], a0, a1, a2, a3, b2, b3);
            }
        }
    }

#pragma unroll
    for (int t = 0; t < 12; t++) {
        int col = 96 * wn + 8 * t + 2 * q;
        float b0v = __ldg(fc2b + col), b1v = __ldg(fc2b + col + 1);
        {
            size_t base = (t0 + rowA) * Cc + col;
            float2 xv = *(const float2*)(g_x2 + base);
            float2 r; r.x = xv.x + yacc[t].x + b0v; r.y = xv.y + yacc[t].y + b1v;
            *(float2*)(out + base) = r;
        }
        {
            size_t base = (t0 + rowA + 8) * Cc + col;
            float2 xv = *(const float2*)(g_x2 + base);
            float2 r; r.x = xv.x + yacc[t].z + b0v; r.y = xv.y + yacc[t].w + b1v;
            *(float2*)(out + base) = r;
        }
    }
}

__global__ __launch_bounds__(256, 2) void swin_fused_kernel(
    const float* __restrict__ x,
    const float* __restrict__ qkv_b, const float* __restrict__ proj_b,
    const float* __restrict__ n1w, const float* __restrict__ n1b,
    const float* __restrict__ n2w, const float* __restrict__ n2b,
    const float* __restrict__ fc1b, const float* __restrict__ fc2b,
    float* __restrict__ out)
{
    extern __shared__ __half smh[];
    const int bid = blockIdx.x;
    if (bid < ATTN_BLOCKS) {
        attn_body(smh, bid, x, qkv_b, proj_b, n1w, n1b);
    } else {
        mlp_body(smh, bid - ATTN_BLOCKS, n2w, n2b, fc1b, fc2b, out);
    }
}

// ---------------------------------------------------------------------------
extern "C" void kernel_launch(void* const* d_in, const int* in_sizes, int n_in,
                              void* d_out, int out_size)
{
    const float* x      = (const float*)d_in[0];
    const float* mask   = (const float*)d_in[1];
    const float* rel    = (const float*)d_in[2];
    const float* qkv_w  = (const float*)d_in[3];
    const float* qkv_b  = (const float*)d_in[4];
    const float* proj_w = (const float*)d_in[5];
    const float* proj_b = (const float*)d_in[6];
    const float* n1w    = (const float*)d_in[7];
    const float* n1b    = (const float*)d_in[8];
    const float* n2w    = (const float*)d_in[9];
    const float* n2b    = (const float*)d_in[10];
    const float* fc1w   = (const float*)d_in[11];
    const float* fc1b   = (const float*)d_in[12];
    const float* fc2w   = (const float*)d_in[13];
    const float* fc2b   = (const float*)d_in[14];
    float* out = (float*)d_out;

    cudaFuncSetAttribute(swin_fused_kernel, cudaFuncAttributeMaxDynamicSharedMemorySize,
                         FUSED_SM_BYTES);

    convert_w<<<1184, 256>>>(qkv_w, proj_w, fc1w, fc2w, mask, rel);
    swin_fused_kernel<<<ATTN_BLOCKS + MLP_BLOCKS, 256, FUSED_SM_BYTES>>>(
        x, qkv_b, proj_b, n1w, n1b, n2w, n2b, fc1b, fc2b, out);
}

// round 11
// speedup vs baseline: 5.7949x; 1.0533x over previous
#include <cuda_runtime.h>
#include <cuda_fp16.h>
#include <math.h>
#include <stdint.h>

#define Bn 32
#define Cc 192
#define WSZ 7
#define NHEAD 6
#define NT 49
#define HIDDEN 768
#define SCALE 0.17677669529663687f
#define ATTN_BLOCKS 2048
#define MLP_BLOCKS 1568

// scratch for x + attention residual
__device__ float g_x2[(size_t)Bn * 56 * 56 * Cc];
// dependency counters: [batch 32][band 8] — band wh complete when count==8
__device__ int g_dep[Bn * 8];

// pre-transposed fp16 weights, [n][k] layout
__device__ __align__(16) __half g_qkvT[576 * 192];
__device__ __align__(16) __half g_projT[192 * 192];
__device__ __align__(16) __half g_fc1T[768 * 192];
__device__ __align__(16) __half g_fc2T[192 * 768];
// fused rel-pos bias + shift mask, padded: [win 64][head 6][row 64][col 56]
__device__ __align__(16) __half g_bias[64 * 6 * 64 * 56];

__global__ void convert_w(const float* __restrict__ qkv_w, const float* __restrict__ proj_w,
                          const float* __restrict__ fc1w, const float* __restrict__ fc2w,
                          const float* __restrict__ mask, const float* __restrict__ rel_table)
{
    int tid = blockIdx.x * blockDim.x + threadIdx.x;
    int stride = gridDim.x * blockDim.x;
    if (tid < Bn * 8) g_dep[tid] = 0;          // reset dependency counters each replay
    for (int j = tid; j < 192 * 576; j += stride) {
        int k = j / 576, n = j % 576;
        g_qkvT[n * 192 + k] = __float2half(qkv_w[j]);
    }
    for (int j = tid; j < 192 * 192; j += stride) {
        int k = j / 192, n = j % 192;
        g_projT[n * 192 + k] = __float2half(proj_w[j]);
    }
    for (int j = tid; j < 192 * 768; j += stride) {
        int k = j / 768, n = j % 768;
        g_fc1T[n * 192 + k] = __float2half(fc1w[j]);
    }
    for (int j = tid; j < 768 * 192; j += stride) {
        int k = j / 192, n = j % 192;
        g_fc2T[n * 768 + k] = __float2half(fc2w[j]);
    }
    for (int j = tid; j < 64 * 6 * 64 * 56; j += stride) {
        int col = j % 56;
        int rest = j / 56;
        int row = rest % 64; rest /= 64;
        int h = rest % 6;
        int w = rest / 6;
        float v;
        if (row >= NT)      v = 0.f;
        else if (col >= NT) v = -30000.f;
        else {
            int rr = row / 7 - col / 7 + 6;
            int cc = row % 7 - col % 7 + 6;
            v = rel_table[(rr * 13 + cc) * NHEAD + h] + mask[w * 2401 + row * 49 + col];
        }
        g_bias[j] = __float2half(v);
    }
}

// D = A(16x16 f16, row) x B(16x8 f16, col) + D, fp32 accum
__device__ __forceinline__ void mma16(float4& c, uint32_t a0, uint32_t a1, uint32_t a2,
                                      uint32_t a3, uint32_t b0, uint32_t b1) {
    asm volatile(
        "mma.sync.aligned.m16n8k16.row.col.f32.f16.f16.f32 "
        "{%0,%1,%2,%3},{%4,%5,%6,%7},{%8,%9},{%0,%1,%2,%3};"
        : "+f"(c.x), "+f"(c.y), "+f"(c.z), "+f"(c.w)
        : "r"(a0), "r"(a1), "r"(a2), "r"(a3), "r"(b0), "r"(b1));
}

__device__ __forceinline__ uint32_t smaddr(const void* p) {
    return (uint32_t)__cvta_generic_to_shared(p);
}

__device__ __forceinline__ void ldsm4(uint32_t& r0, uint32_t& r1, uint32_t& r2,
                                      uint32_t& r3, uint32_t a) {
    asm volatile("ldmatrix.sync.aligned.m8n8.x4.shared.b16 {%0,%1,%2,%3},[%4];"
                 : "=r"(r0), "=r"(r1), "=r"(r2), "=r"(r3) : "r"(a));
}

__device__ __forceinline__ uint32_t packh2(float a, float b) {
    __half2 h = __floats2half2_rn(a, b);
    return *(uint32_t*)&h;
}

__device__ __forceinline__ float gelu_exact(float v) {
    return 0.5f * v * (1.0f + erff(v * 0.70710678118654752f));
}

// ---------------------------------------------------------------------------
// Fused kernel: bids [0,2048) attention path, [2048,3616) MLP path
// GEMM warp tiling: 2 m-halves (32 rows) x 4 n-quarters (48 cols)
// ---------------------------------------------------------------------------
#define XW_STRH 200
#define QK_STRH 392
#define VT_STRH 72
#define OFF_QK_H 12800        // 64*200
#define OFF_VT_H 34752        // + 56*392
#define OFF_WST_H 48576       // + 192*72
#define FUSED_SM_BYTES (56256 * 2)
#define OFF_F1_H 12800
#define OFF_HS_H 25600
#define OFF_F2_H 30208

__device__ __forceinline__ void attn_body(
    __half* smh, int bid,
    const float* __restrict__ x,
    const float* __restrict__ qkv_b, const float* __restrict__ proj_b,
    const float* __restrict__ n1w, const float* __restrict__ n1b)
{
    __half* xwh = smh;                   // [64][200]  LN1 out / attn out
    __half* qkh = smh + OFF_QK_H;        // [56][392]  Q(0..191) K(192..383)
    __half* vth = smh + OFF_VT_H;        // [192][72]  V transposed
    uint32_t* xwu  = (uint32_t*)xwh;
    uint32_t* vtu  = (uint32_t*)vth;
    uint32_t* wstu = (uint32_t*)(smh + OFF_WST_H);   // [192][20] u32 weight stage
    const uint32_t* qkvT_u  = (const uint32_t*)g_qkvT;
    const uint32_t* projT_u = (const uint32_t*)g_projT;

    const int b    = bid >> 6;
    const int w    = bid & 63;
    const int wh   = w >> 3;
    const int ww   = w & 7;
    const int tid  = threadIdx.x;
    const int warp = tid >> 5;
    const int lane = tid & 31;
    const int g    = lane >> 2;
    const int q    = lane & 3;
    const int wm   = warp & 1;      // m-half (32 rows)
    const int wn   = warp >> 1;     // n-quarter (48 cols)
    const int lr   = lane & 7;
    const int lb8  = (lane >> 3) & 1;
    const int lb16 = lane >> 4;

    // staging decomposition for this thread (768 uint4 per 32-k chunk)
    const int sn0 = tid >> 2, sc0 = (tid & 3) * 4;
    const int sn1 = (tid + 256) >> 2, sc1 = ((tid + 256) & 3) * 4;
    const int sn2 = (tid + 512) >> 2, sc2 = ((tid + 512) & 3) * 4;

    const uint32_t aBase = smaddr(xwh + (32 * wm + lr + 8 * lb8) * XW_STRH + 8 * lb16);
    const uint32_t bBase = smaddr((__half*)wstu + (48 * wn + 8 * lb16 + lr) * 40 + 8 * lb8);

    // ---- zero pad regions ----
    for (int idx = tid; idx < 192 * 36; idx += 256) vtu[idx] = 0u;
    for (int idx = tid; idx < 7 * 196; idx += 256)
        ((uint32_t*)qkh)[(49 + idx / 196) * 196 + idx % 196] = 0u;

    // prologue prefetch: QKV pass 0, chunk 0
    uint4 pre0 = *(const uint4*)(qkvT_u + (size_t)sn0 * 96 + sc0);
    uint4 pre1 = *(const uint4*)(qkvT_u + (size_t)sn1 * 96 + sc1);
    uint4 pre2 = *(const uint4*)(qkvT_u + (size_t)sn2 * 96 + sc2);

    // ---- Phase 1: gather (shifted window) + LN1 ----
    for (int n = warp; n < 64; n += 8) {
        if (n < NT) {
            int r  = wh * WSZ + n / WSZ;
            int c  = ww * WSZ + n % WSZ;
            int gr = r + 3; if (gr >= 56) gr -= 56;
            int gc = c + 3; if (gc >= 56) gc -= 56;
            const float* xr = x + ((size_t)b * 3136 + gr * 56 + gc) * Cc;
            float v[6]; float s = 0.f, ss = 0.f;
#pragma unroll
            for (int j = 0; j < 6; j++) { v[j] = xr[lane + 32 * j]; s += v[j]; ss += v[j] * v[j]; }
#pragma unroll
            for (int o = 16; o > 0; o >>= 1) {
                s  += __shfl_xor_sync(0xffffffffu, s,  o);
                ss += __shfl_xor_sync(0xffffffffu, ss, o);
            }
            float mean = s * (1.f / 192.f);
            float rinv = rsqrtf(ss * (1.f / 192.f) - mean * mean + 1e-5f);
#pragma unroll
            for (int j = 0; j < 6; j++) {
                int k = lane + 32 * j;
                xwh[n * XW_STRH + k] = __float2half((v[j] - mean) * rinv * n1w[k] + n1b[k]);
            }
        } else {
#pragma unroll
            for (int j = 0; j < 3; j++) xwu[n * 100 + lane + 32 * j] = 0u;
        }
    }

    // ---- Phase 2: QKV via f16 mma : 2m x 4n tiling ----
    for (int p = 0; p < 3; p++) {
        float4 acc[2][6];
#pragma unroll
        for (int mf = 0; mf < 2; mf++)
#pragma unroll
            for (int t = 0; t < 6; t++) acc[mf][t] = make_float4(0.f, 0.f, 0.f, 0.f);

        for (int kc = 0; kc < 192; kc += 32) {
            __syncthreads();
            *(uint4*)(wstu + sn0 * 20 + sc0) = pre0;
            *(uint4*)(wstu + sn1 * 20 + sc1) = pre1;
            *(uint4*)(wstu + sn2 * 20 + sc2) = pre2;
            __syncthreads();
            int s = p * 6 + (kc >> 5) + 1;
            if (s < 18) {
                int np = s / 6, nk = (s % 6) << 4;
                pre0 = *(const uint4*)(qkvT_u + (size_t)(np * 192 + sn0) * 96 + nk + sc0);
                pre1 = *(const uint4*)(qkvT_u + (size_t)(np * 192 + sn1) * 96 + nk + sc1);
                pre2 = *(const uint4*)(qkvT_u + (size_t)(np * 192 + sn2) * 96 + nk + sc2);
            } else {
                pre0 = *(const uint4*)(projT_u + (size_t)sn0 * 96 + sc0);
                pre1 = *(const uint4*)(projT_u + (size_t)sn1 * 96 + sc1);
                pre2 = *(const uint4*)(projT_u + (size_t)sn2 * 96 + sc2);
            }
#pragma unroll
            for (int k0 = 0; k0 < 32; k0 += 16) {
                uint32_t a[2][4];
                ldsm4(a[0][0], a[0][1], a[0][2], a[0][3], aBase + (kc + k0) * 2);
                ldsm4(a[1][0], a[1][1], a[1][2], a[1][3], aBase + 6400 + (kc + k0) * 2);
#pragma unroll
                for (int tp = 0; tp < 3; tp++) {
                    uint32_t b0, b1, b2, b3;
                    ldsm4(b0, b1, b2, b3, bBase + tp * 1280 + k0 * 2);
#pragma unroll
                    for (int mf = 0; mf < 2; mf++) {
                        mma16(acc[mf][2 * tp],     a[mf][0], a[mf][1], a[mf][2], a[mf][3], b0, b1);
                        mma16(acc[mf][2 * tp + 1], a[mf][0], a[mf][1], a[mf][2], a[mf][3], b2, b3);
                    }
                }
            }
        }
#pragma unroll
        for (int mf = 0; mf < 2; mf++) {
            int r0 = 32 * wm + 16 * mf + g;
            bool u0 = r0 < NT, u1 = (r0 + 8) < NT;
#pragma unroll
            for (int t = 0; t < 6; t++) {
                int col = 48 * wn + 8 * t + 2 * q;
                int j   = 192 * p + col;
                float b0v = __ldg(qkv_b + j), b1v = __ldg(qkv_b + j + 1);
                float o00 = acc[mf][t].x + b0v, o01 = acc[mf][t].y + b1v;
                float o10 = acc[mf][t].z + b0v, o11 = acc[mf][t].w + b1v;
                if (p == 0) { o00 *= SCALE; o01 *= SCALE; o10 *= SCALE; o11 *= SCALE; }
                if (p < 2) {
                    if (u0) *(__half2*)(qkh + r0 * QK_STRH + j)       = __floats2half2_rn(o00, o01);
                    if (u1) *(__half2*)(qkh + (r0 + 8) * QK_STRH + j) = __floats2half2_rn(o10, o11);
                } else {
                    if (u0) {
                        vth[col * VT_STRH + r0]       = __float2half(o00);
                        vth[(col + 1) * VT_STRH + r0] = __float2half(o01);
                    }
                    if (u1) {
                        vth[col * VT_STRH + r0 + 8]       = __float2half(o10);
                        vth[(col + 1) * VT_STRH + r0 + 8] = __float2half(o11);
                    }
                }
            }
        }
    }
    __syncthreads();

    // ---- Phase 3: mma attention over 24 (head, m-tile) units, 3 per warp ----
    {
#pragma unroll 1
        for (int t = 0; t < 3; t++) {
            const int u = warp * 3 + t;
            const int h = u >> 2;
            const int i = u & 3;
            const __half* bias = g_bias + ((size_t)(w * NHEAD + h)) * 64 * 56;
            const uint32_t kBase = smaddr(qkh + lr * QK_STRH + 192 + h * 32 + 8 * (lane >> 3));
            const uint32_t vBase = smaddr(vth + (h * 32 + lr) * VT_STRH + 8 * (lane >> 3));
            const int r0i = 16 * i + g, r1i = r0i + 8;

            float2 bb0[7], bb1[7];
#pragma unroll
            for (int j = 0; j < 7; j++) {
                bb0[j] = __half22float2(*(const __half2*)(bias + r0i * 56 + 8 * j + 2 * q));
                bb1[j] = __half22float2(*(const __half2*)(bias + r1i * 56 + 8 * j + 2 * q));
            }

            uint32_t qA = smaddr(qkh + (16 * i + lr + 8 * lb8) * QK_STRH + h * 32 + 8 * lb16);
            uint32_t aq[2][4];
            ldsm4(aq[0][0], aq[0][1], aq[0][2], aq[0][3], qA);
            ldsm4(aq[1][0], aq[1][1], aq[1][2], aq[1][3], qA + 32);
            float4 S[7];
#pragma unroll
            for (int j = 0; j < 7; j++) {
                S[j] = make_float4(0.f, 0.f, 0.f, 0.f);
                uint32_t b0, b1, b2, b3;
                ldsm4(b0, b1, b2, b3, kBase + j * (8 * QK_STRH * 2));
                mma16(S[j], aq[0][0], aq[0][1], aq[0][2], aq[0][3], b0, b1);
                mma16(S[j], aq[1][0], aq[1][1], aq[1][2], aq[1][3], b2, b3);
                S[j].x += bb0[j].x; S[j].y += bb0[j].y;
                S[j].z += bb1[j].x; S[j].w += bb1[j].y;
            }
            float mx0 = -1e30f, mx1 = -1e30f;
#pragma unroll
            for (int j = 0; j < 7; j++) {
                mx0 = fmaxf(mx0, fmaxf(S[j].x, S[j].y));
                mx1 = fmaxf(mx1, fmaxf(S[j].z, S[j].w));
            }
#pragma unroll
            for (int o = 1; o < 4; o <<= 1) {
                mx0 = fmaxf(mx0, __shfl_xor_sync(0xffffffffu, mx0, o));
                mx1 = fmaxf(mx1, __shfl_xor_sync(0xffffffffu, mx1, o));
            }
            float sum0 = 0.f, sum1 = 0.f;
#pragma unroll
            for (int j = 0; j < 7; j++) {
                S[j].x = __expf(S[j].x - mx0); S[j].y = __expf(S[j].y - mx0);
                S[j].z = __expf(S[j].z - mx1); S[j].w = __expf(S[j].w - mx1);
                sum0 += S[j].x + S[j].y; sum1 += S[j].z + S[j].w;
            }
#pragma unroll
            for (int o = 1; o < 4; o <<= 1) {
                sum0 += __shfl_xor_sync(0xffffffffu, sum0, o);
                sum1 += __shfl_xor_sync(0xffffffffu, sum1, o);
            }
            float rc0 = 1.f / sum0, rc1 = 1.f / sum1;
            uint32_t pa[4][4];
#pragma unroll
            for (int kk = 0; kk < 3; kk++) {
                pa[kk][0] = packh2(S[2 * kk].x, S[2 * kk].y);
                pa[kk][1] = packh2(S[2 * kk].z, S[2 * kk].w);
                pa[kk][2] = packh2(S[2 * kk + 1].x, S[2 * kk + 1].y);
                pa[kk][3] = packh2(S[2 * kk + 1].z, S[2 * kk + 1].w);
            }
            pa[3][0] = packh2(S[6].x, S[6].y);
            pa[3][1] = packh2(S[6].z, S[6].w);
            pa[3][2] = 0u; pa[3][3] = 0u;
            float4 O[4];
#pragma unroll
            for (int vj = 0; vj < 4; vj++) {
                O[vj] = make_float4(0.f, 0.f, 0.f, 0.f);
                uint32_t va0, va1, va2, va3, vb0, vb1, vb2, vb3;
                ldsm4(va0, va1, va2, va3, vBase + vj * (8 * VT_STRH * 2));
                ldsm4(vb0, vb1, vb2, vb3, vBase + vj * (8 * VT_STRH * 2) + 64);
                mma16(O[vj], pa[0][0], pa[0][1], pa[0][2], pa[0][3], va0, va1);
                mma16(O[vj], pa[1][0], pa[1][1], pa[1][2], pa[1][3], va2, va3);
                mma16(O[vj], pa[2][0], pa[2][1], pa[2][2], pa[2][3], vb0, vb1);
                mma16(O[vj], pa[3][0], pa[3][1], pa[3][2], pa[3][3], vb2, vb3);
            }
#pragma unroll
            for (int vj = 0; vj < 4; vj++) {
                int col = h * 32 + 8 * vj + 2 * q;
                if (r0i < NT)
                    *(__half2*)(xwh + r0i * XW_STRH + col) =
                        __floats2half2_rn(O[vj].x * rc0, O[vj].y * rc0);
                if (r1i < NT)
                    *(__half2*)(xwh + r1i * XW_STRH + col) =
                        __floats2half2_rn(O[vj].z * rc1, O[vj].w * rc1);
            }
        }
    }

    // ---- Phase 4: proj via f16 mma, fused residual scatter ----
    {
        float4 acc[2][6];
#pragma unroll
        for (int mf = 0; mf < 2; mf++)
#pragma unroll
            for (int t = 0; t < 6; t++) acc[mf][t] = make_float4(0.f, 0.f, 0.f, 0.f);

        for (int kc = 0; kc < 192; kc += 32) {
            __syncthreads();
            *(uint4*)(wstu + sn0 * 20 + sc0) = pre0;
            *(uint4*)(wstu + sn1 * 20 + sc1) = pre1;
            *(uint4*)(wstu + sn2 * 20 + sc2) = pre2;
            __syncthreads();
            if (kc + 32 < 192) {
                int nk = (kc >> 1) + 16;
                pre0 = *(const uint4*)(projT_u + (size_t)sn0 * 96 + nk + sc0);
                pre1 = *(const uint4*)(projT_u + (size_t)sn1 * 96 + nk + sc1);
                pre2 = *(const uint4*)(projT_u + (size_t)sn2 * 96 + nk + sc2);
            }
#pragma unroll
            for (int k0 = 0; k0 < 32; k0 += 16) {
                uint32_t a[2][4];
                ldsm4(a[0][0], a[0][1], a[0][2], a[0][3], aBase + (kc + k0) * 2);
                ldsm4(a[1][0], a[1][1], a[1][2], a[1][3], aBase + 6400 + (kc + k0) * 2);
#pragma unroll
                for (int tp = 0; tp < 3; tp++) {
                    uint32_t b0, b1, b2, b3;
                    ldsm4(b0, b1, b2, b3, bBase + tp * 1280 + k0 * 2);
#pragma unroll
                    for (int mf = 0; mf < 2; mf++) {
                        mma16(acc[mf][2 * tp],     a[mf][0], a[mf][1], a[mf][2], a[mf][3], b0, b1);
                        mma16(acc[mf][2 * tp + 1], a[mf][0], a[mf][1], a[mf][2], a[mf][3], b2, b3);
                    }
                }
            }
        }

#pragma unroll
        for (int mf = 0; mf < 2; mf++) {
            int r0 = 32 * wm + 16 * mf + g;
            bool u0 = r0 < NT, u1 = (r0 + 8) < NT;
            size_t base0 = 0, base1 = 0;
            if (u0) {
                int gr = wh * 7 + r0 / 7 + 3; if (gr >= 56) gr -= 56;
                int gc = ww * 7 + r0 % 7 + 3; if (gc >= 56) gc -= 56;
                base0 = ((size_t)b * 3136 + gr * 56 + gc) * Cc;
            }
            if (u1) {
                int r1 = r0 + 8;
                int gr = wh * 7 + r1 / 7 + 3; if (gr >= 56) gr -= 56;
                int gc = ww * 7 + r1 % 7 + 3; if (gc >= 56) gc -= 56;
                base1 = ((size_t)b * 3136 + gr * 56 + gc) * Cc;
            }
#pragma unroll
            for (int t = 0; t < 6; t++) {
                int col = 48 * wn + 8 * t + 2 * q;
                float pb0 = __ldg(proj_b + col), pb1 = __ldg(proj_b + col + 1);
                if (u0) {
                    float2 xv = *(const float2*)(x + base0 + col);
                    float2 r; r.x = xv.x + acc[mf][t].x + pb0; r.y = xv.y + acc[mf][t].y + pb1;
                    *(float2*)(g_x2 + base0 + col) = r;
                }
                if (u1) {
                    float2 xv = *(const float2*)(x + base1 + col);
                    float2 r; r.x = xv.x + acc[mf][t].z + pb0; r.y = xv.y + acc[mf][t].w + pb1;
                    *(float2*)(g_x2 + base1 + col) = r;
                }
            }
        }
    }

    // ---- release: band (b, wh) progress ----
    __threadfence();
    __syncthreads();
    if (tid == 0) atomicAdd(&g_dep[b * 8 + wh], 1);
}

__device__ __forceinline__ void mlp_body(
    __half* smh, int m,
    const float* __restrict__ n2w, const float* __restrict__ n2b,
    const float* __restrict__ fc1b, const float* __restrict__ fc2b,
    float* __restrict__ out)
{
    __half* xnh = smh;                   // [64][200]
    uint32_t* f1u  = (uint32_t*)(smh + OFF_F1_H);   // [64][100] u32
    __half2*  hs2  = (__half2*)(smh + OFF_HS_H);    // [64][36] half2
    uint32_t* f2u  = (uint32_t*)(smh + OFF_F2_H);   // [192][36] u32
    const uint32_t* fc1T_u = (const uint32_t*)g_fc1T;
    const uint32_t* fc2T_u = (const uint32_t*)g_fc2T;

    const int tid  = threadIdx.x;
    const int warp = tid >> 5;
    const int lane = tid & 31;
    const int g    = lane >> 2;
    const int q    = lane & 3;
    const int wm   = warp & 1;      // fc2 m-half
    const int wn   = warp >> 1;     // fc2 n-quarter
    const int wm1  = warp & 3;      // fc1 m-tile
    const int wn1  = warp >> 2;     // fc1 n-half
    const int rowF1 = 16 * wm1 + g;
    const int lr   = lane & 7;
    const int lb8  = (lane >> 3) & 1;
    const int lb16 = lane >> 4;
    const size_t t0 = (size_t)m * 64;

    const uint32_t aBase1 = smaddr(xnh + (16 * wm1 + lr + 8 * lb8) * XW_STRH + 8 * lb16);
    const uint32_t b1Base = smaddr((__half*)f1u + (32 * wn1 + 8 * lb16 + lr) * 200 + 8 * lb8);
    const uint32_t aBase2 = smaddr((__half*)hs2 + (32 * wm + lr + 8 * lb8) * 72 + 8 * lb16);
    const uint32_t b2Base = smaddr((__half*)f2u + (48 * wn + 8 * lb16 + lr) * 72 + 8 * lb8);

    int f1n[6], f1c[6], f2n[6], f2c[6];
#pragma unroll
    for (int j = 0; j < 6; j++) {
        int idx = tid + j * 256;
        f1n[j] = idx / 24; f1c[j] = (idx % 24) * 4;
        f2n[j] = idx >> 3; f2c[j] = (idx & 7) * 4;
    }
    uint4 preA[6], preB[6];
#pragma unroll
    for (int j = 0; j < 6; j++) {
        preA[j] = *(const uint4*)(fc1T_u + (size_t)f1n[j] * 96 + f1c[j]);
        preB[j] = *(const uint4*)(fc2T_u + (size_t)f2n[j] * 384 + f2c[j]);
    }

    // ---- acquire: wait for the attn bands covering these 64 tokens ----
    {
        int mm = m % 49;
        int bb = m / 49;
        int gr0 = (mm * 64) / 56;
        int gr1 = (mm * 64 + 63) / 56;
        int i0 = bb * 8 + ((gr0 + 53) % 56) / 7;
        int i1 = bb * 8 + ((gr1 + 53) % 56) / 7;
        if (tid == 0) {
            while (atomicAdd(&g_dep[i0], 0) < 8 || atomicAdd(&g_dep[i1], 0) < 8)
                __nanosleep(100);
        }
        __syncthreads();
    }

    // ---- LN2 ----
    for (int n = warp; n < 64; n += 8) {
        const float* xr = g_x2 + (t0 + n) * Cc;
        float v[6]; float s = 0.f, ss = 0.f;
#pragma unroll
        for (int j = 0; j < 6; j++) { v[j] = xr[lane + 32 * j]; s += v[j]; ss += v[j] * v[j]; }
#pragma unroll
        for (int o = 16; o > 0; o >>= 1) {
            s  += __shfl_xor_sync(0xffffffffu, s,  o);
            ss += __shfl_xor_sync(0xffffffffu, ss, o);
        }
        float mean = s * (1.f / 192.f);
        float rinv = rsqrtf(ss * (1.f / 192.f) - mean * mean + 1e-5f);
#pragma unroll
        for (int j = 0; j < 6; j++) {
            int k = lane + 32 * j;
            xnh[n * XW_STRH + k] = __float2half((v[j] - mean) * rinv * n2w[k] + n2b[k]);
        }
    }

    float4 yacc[2][6];
#pragma unroll
    for (int mf = 0; mf < 2; mf++)
#pragma unroll
        for (int t = 0; t < 6; t++) yacc[mf][t] = make_float4(0.f, 0.f, 0.f, 0.f);

    for (int hc = 0; hc < HIDDEN; hc += 64) {
        __syncthreads();
#pragma unroll
        for (int j = 0; j < 6; j++) {
            *(uint4*)(f1u + f1n[j] * 100 + f1c[j]) = preA[j];
            *(uint4*)(f2u + f2n[j] * 36 + f2c[j]) = preB[j];
        }
        __syncthreads();
        if (hc + 64 < HIDDEN) {
#pragma unroll
            for (int j = 0; j < 6; j++) {
                preA[j] = *(const uint4*)(fc1T_u + (size_t)(hc + 64 + f1n[j]) * 96 + f1c[j]);
                preB[j] = *(const uint4*)(fc2T_u + (size_t)f2n[j] * 384 + ((hc + 64) >> 1) + f2c[j]);
            }
        }

        // fc1: H(64x64) = xn(64x192) @ w1chunk ; warp tile m16 x n32
        float4 acc1[4];
#pragma unroll
        for (int t = 0; t < 4; t++) acc1[t] = make_float4(0.f, 0.f, 0.f, 0.f);
#pragma unroll
        for (int k0 = 0; k0 < 192; k0 += 16) {
            uint32_t a0, a1, a2, a3;
            ldsm4(a0, a1, a2, a3, aBase1 + k0 * 2);
#pragma unroll
            for (int tp = 0; tp < 2; tp++) {
                uint32_t b0, b1, b2, b3;
                ldsm4(b0, b1, b2, b3, b1Base + tp * 6400 + k0 * 2);
                mma16(acc1[2 * tp],     a0, a1, a2, a3, b0, b1);
                mma16(acc1[2 * tp + 1], a0, a1, a2, a3, b2, b3);
            }
        }
#pragma unroll
        for (int t = 0; t < 4; t++) {
            int col = 32 * wn1 + 8 * t + 2 * q;
            float b0v = __ldg(fc1b + hc + col), b1v = __ldg(fc1b + hc + col + 1);
            int wi = 16 * wn1 + 4 * t + q;
            hs2[rowF1 * 36 + wi]       = __floats2half2_rn(gelu_exact(acc1[t].x + b0v),
                                                           gelu_exact(acc1[t].y + b1v));
            hs2[(rowF1 + 8) * 36 + wi] = __floats2half2_rn(gelu_exact(acc1[t].z + b0v),
                                                           gelu_exact(acc1[t].w + b1v));
        }
        __syncthreads();

        // fc2: Y(64x192) += H(64x64) @ w2chunk ; 2m x 4n tiling
#pragma unroll
        for (int k0 = 0; k0 < 64; k0 += 16) {
            uint32_t a[2][4];
            ldsm4(a[0][0], a[0][1], a[0][2], a[0][3], aBase2 + k0 * 2);
            ldsm4(a[1][0], a[1][1], a[1][2], a[1][3], aBase2 + 2304 + k0 * 2);
#pragma unroll
            for (int tp = 0; tp < 3; tp++) {
                uint32_t b0, b1, b2, b3;
                ldsm4(b0, b1, b2, b3, b2Base + tp * 2304 + k0 * 2);
#pragma unroll
                for (int mf = 0; mf < 2; mf++) {
                    mma16(yacc[mf][2 * tp],     a[mf][0], a[mf][1], a[mf][2], a[mf][3], b0, b1);
                    mma16(yacc[mf][2 * tp + 1], a[mf][0], a[mf][1], a[mf][2], a[mf][3], b2, b3);
                }
            }
        }
    }

#pragma unroll
    for (int mf = 0; mf < 2; mf++) {
        int r0 = 32 * wm + 16 * mf + g;
#pragma unroll
        for (int t = 0; t < 6; t++) {
            int col = 48 * wn + 8 * t + 2 * q;
            float b0v = __ldg(fc2b + col), b1v = __ldg(fc2b + col + 1);
            {
                size_t base = (t0 + r0) * Cc + col;
                float2 xv = *(const float2*)(g_x2 + base);
                float2 r; r.x = xv.x + yacc[mf][t].x + b0v; r.y = xv.y + yacc[mf][t].y + b1v;
                *(float2*)(out + base) = r;
            }
            {
                size_t base = (t0 + r0 + 8) * Cc + col;
                float2 xv = *(const float2*)(g_x2 + base);
                float2 r; r.x = xv.x + yacc[mf][t].z + b0v; r.y = xv.y + yacc[mf][t].w + b1v;
                *(float2*)(out + base) = r;
            }
        }
    }
}

__global__ __launch_bounds__(256, 2) void swin_fused_kernel(
    const float* __restrict__ x,
    const float* __restrict__ qkv_b, const float* __restrict__ proj_b,
    const float* __restrict__ n1w, const float* __restrict__ n1b,
    const float* __restrict__ n2w, const float* __restrict__ n2b,
    const float* __restrict__ fc1b, const float* __restrict__ fc2b,
    float* __restrict__ out)
{
    extern __shared__ __half smh[];
    const int bid = blockIdx.x;
    if (bid < ATTN_BLOCKS) {
        attn_body(smh, bid, x, qkv_b, proj_b, n1w, n1b);
    } else {
        mlp_body(smh, bid - ATTN_BLOCKS, n2w, n2b, fc1b, fc2b, out);
    }
}

// ---------------------------------------------------------------------------
extern "C" void kernel_launch(void* const* d_in, const int* in_sizes, int n_in,
                              void* d_out, int out_size)
{
    const float* x      = (const float*)d_in[0];
    const float* mask   = (const float*)d_in[1];
    const float* rel    = (const float*)d_in[2];
    const float* qkv_w  = (const float*)d_in[3];
    const float* qkv_b  = (const float*)d_in[4];
    const float* proj_w = (const float*)d_in[5];
    const float* proj_b = (const float*)d_in[6];
    const float* n1w    = (const float*)d_in[7];
    const float* n1b    = (const float*)d_in[8];
    const float* n2w    = (const float*)d_in[9];
    const float* n2b    = (const float*)d_in[10];
    const float* fc1w   = (const float*)d_in[11];
    const float* fc1b   = (const float*)d_in[12];
    const float* fc2w   = (const float*)d_in[13];
    const float* fc2b   = (const float*)d_in[14];
    float* out = (float*)d_out;

    cudaFuncSetAttribute(swin_fused_kernel, cudaFuncAttributeMaxDynamicSharedMemorySize,
                         FUSED_SM_BYTES);

    convert_w<<<1184, 256>>>(qkv_w, proj_w, fc1w, fc2w, mask, rel);
    swin_fused_kernel<<<ATTN_BLOCKS + MLP_BLOCKS, 256, FUSED_SM_BYTES>>>(
        x, qkv_b, proj_b, n1w, n1b, n2w, n2b, fc1b, fc2b, out);
}

// round 12
// speedup vs baseline: 8.1853x; 1.4125x over previous
#include <cuda_runtime.h>
#include <cuda_fp16.h>
#include <math.h>
#include <stdint.h>

#define Bn 32
#define Cc 192
#define WSZ 7
#define NHEAD 6
#define NT 49
#define HIDDEN 768
#define SCALE 0.17677669529663687f
#define ATTN_BLOCKS 2048
#define MLP_BLOCKS 1568

// scratch for x + attention residual
__device__ float g_x2[(size_t)Bn * 56 * 56 * Cc];
// dependency counters: [batch 32][band 8]
__device__ int g_dep[Bn * 8];

// fragment-packed fp16 weights: per (n8 x k16) tile, 64 u32 = lane*2 -> {b0,b1}
// tile index = (n/8)*(K/16) + k/16
__device__ __align__(16) uint32_t g_qkvF[72 * 12 * 64];    // N=576 K=192
__device__ __align__(16) uint32_t g_projF[24 * 12 * 64];   // N=192 K=192
__device__ __align__(16) uint32_t g_fc1F[96 * 12 * 64];    // N=768 K=192
__device__ __align__(16) uint32_t g_fc2F[24 * 48 * 64];    // N=192 K=768
// fused rel-pos bias + shift mask, padded: [win 64][head 6][row 64][col 56]
__device__ __align__(16) __half g_bias[64 * 6 * 64 * 56];

__device__ __forceinline__ uint32_t packh2(float a, float b) {
    __half2 h = __floats2half2_rn(a, b);
    return *(uint32_t*)&h;
}

__global__ void convert_w(const float* __restrict__ qkv_w, const float* __restrict__ proj_w,
                          const float* __restrict__ fc1w, const float* __restrict__ fc2w,
                          const float* __restrict__ mask, const float* __restrict__ rel_table)
{
    int tid = blockIdx.x * blockDim.x + threadIdx.x;
    int stride = gridDim.x * blockDim.x;
    if (tid < Bn * 8) g_dep[tid] = 0;
    // QKV: src [192 k][576 n]
    for (int j = tid; j < 72 * 12 * 64; j += stride) {
        int tile = j >> 6, r = j & 63, L = r >> 1, hb = r & 1;
        int n = (tile / 12) * 8 + (L >> 2);
        int k = (tile % 12) * 16 + hb * 8 + (L & 3) * 2;
        g_qkvF[j] = packh2(qkv_w[k * 576 + n], qkv_w[(k + 1) * 576 + n]);
    }
    // proj: src [192][192]
    for (int j = tid; j < 24 * 12 * 64; j += stride) {
        int tile = j >> 6, r = j & 63, L = r >> 1, hb = r & 1;
        int n = (tile / 12) * 8 + (L >> 2);
        int k = (tile % 12) * 16 + hb * 8 + (L & 3) * 2;
        g_projF[j] = packh2(proj_w[k * 192 + n], proj_w[(k + 1) * 192 + n]);
    }
    // fc1: src [192 k][768 n]
    for (int j = tid; j < 96 * 12 * 64; j += stride) {
        int tile = j >> 6, r = j & 63, L = r >> 1, hb = r & 1;
        int n = (tile / 12) * 8 + (L >> 2);
        int k = (tile % 12) * 16 + hb * 8 + (L & 3) * 2;
        g_fc1F[j] = packh2(fc1w[k * 768 + n], fc1w[(k + 1) * 768 + n]);
    }
    // fc2: src [768 k][192 n]
    for (int j = tid; j < 24 * 48 * 64; j += stride) {
        int tile = j >> 6, r = j & 63, L = r >> 1, hb = r & 1;
        int n = (tile / 48) * 8 + (L >> 2);
        int k = (tile % 48) * 16 + hb * 8 + (L & 3) * 2;
        g_fc2F[j] = packh2(fc2w[k * 192 + n], fc2w[(k + 1) * 192 + n]);
    }
    for (int j = tid; j < 64 * 6 * 64 * 56; j += stride) {
        int col = j % 56;
        int rest = j / 56;
        int row = rest % 64; rest /= 64;
        int h = rest % 6;
        int w = rest / 6;
        float v;
        if (row >= NT)      v = 0.f;
        else if (col >= NT) v = -30000.f;
        else {
            int rr = row / 7 - col / 7 + 6;
            int cc = row % 7 - col % 7 + 6;
            v = rel_table[(rr * 13 + cc) * NHEAD + h] + mask[w * 2401 + row * 49 + col];
        }
        g_bias[j] = __float2half(v);
    }
}

__device__ __forceinline__ void mma16(float4& c, uint32_t a0, uint32_t a1, uint32_t a2,
                                      uint32_t a3, uint32_t b0, uint32_t b1) {
    asm volatile(
        "mma.sync.aligned.m16n8k16.row.col.f32.f16.f16.f32 "
        "{%0,%1,%2,%3},{%4,%5,%6,%7},{%8,%9},{%0,%1,%2,%3};"
        : "+f"(c.x), "+f"(c.y), "+f"(c.z), "+f"(c.w)
        : "r"(a0), "r"(a1), "r"(a2), "r"(a3), "r"(b0), "r"(b1));
}

__device__ __forceinline__ uint32_t smaddr(const void* p) {
    return (uint32_t)__cvta_generic_to_shared(p);
}

__device__ __forceinline__ void ldsm4(uint32_t& r0, uint32_t& r1, uint32_t& r2,
                                      uint32_t& r3, uint32_t a) {
    asm volatile("ldmatrix.sync.aligned.m8n8.x4.shared.b16 {%0,%1,%2,%3},[%4];"
                 : "=r"(r0), "=r"(r1), "=r"(r2), "=r"(r3) : "r"(a));
}

__device__ __forceinline__ float gelu_exact(float v) {
    return 0.5f * v * (1.0f + erff(v * 0.70710678118654752f));
}

// ---------------------------------------------------------------------------
// Fused kernel: bids [0,2048) attention path, [2048,3616) MLP path
// B operands come straight from gmem (fragment-packed); A via ldsm from smem.
// ---------------------------------------------------------------------------
#define XW_STRH 200
#define QK_STRH 392
#define VT_STRH 72
#define OFF_QK_H 12800        // 64*200
#define OFF_VT_H 34752        // + 56*392
#define FUSED_SM_BYTES (48576 * 2)   // + 192*72 vT
#define OFF_HS_H 12800

__device__ __forceinline__ void attn_body(
    __half* smh, int bid,
    const float* __restrict__ x,
    const float* __restrict__ qkv_b, const float* __restrict__ proj_b,
    const float* __restrict__ n1w, const float* __restrict__ n1b)
{
    __half* xwh = smh;                   // [64][200]  LN1 out / attn out
    __half* qkh = smh + OFF_QK_H;        // [56][392]  Q(0..191) K(192..383)
    __half* vth = smh + OFF_VT_H;        // [192][72]  V transposed
    uint32_t* xwu  = (uint32_t*)xwh;
    uint32_t* vtu  = (uint32_t*)vth;

    const int b    = bid >> 6;
    const int w    = bid & 63;
    const int wh   = w >> 3;
    const int ww   = w & 7;
    const int tid  = threadIdx.x;
    const int warp = tid >> 5;
    const int lane = tid & 31;
    const int g    = lane >> 2;
    const int q    = lane & 3;
    const int wm   = warp & 1;      // m-half (32 rows)
    const int wn   = warp >> 1;     // n-quarter (48 cols)
    const int lr   = lane & 7;
    const int lb8  = (lane >> 3) & 1;
    const int lb16 = lane >> 4;

    const uint32_t aBase = smaddr(xwh + (32 * wm + lr + 8 * lb8) * XW_STRH + 8 * lb16);

    // ---- zero pad regions ----
    for (int idx = tid; idx < 192 * 36; idx += 256) vtu[idx] = 0u;
    for (int idx = tid; idx < 7 * 196; idx += 256)
        ((uint32_t*)qkh)[(49 + idx / 196) * 196 + idx % 196] = 0u;

    // ---- Phase 1: gather (shifted window) + LN1 ----
    for (int n = warp; n < 64; n += 8) {
        if (n < NT) {
            int r  = wh * WSZ + n / WSZ;
            int c  = ww * WSZ + n % WSZ;
            int gr = r + 3; if (gr >= 56) gr -= 56;
            int gc = c + 3; if (gc >= 56) gc -= 56;
            const float* xr = x + ((size_t)b * 3136 + gr * 56 + gc) * Cc;
            float v[6]; float s = 0.f, ss = 0.f;
#pragma unroll
            for (int j = 0; j < 6; j++) { v[j] = xr[lane + 32 * j]; s += v[j]; ss += v[j] * v[j]; }
#pragma unroll
            for (int o = 16; o > 0; o >>= 1) {
                s  += __shfl_xor_sync(0xffffffffu, s,  o);
                ss += __shfl_xor_sync(0xffffffffu, ss, o);
            }
            float mean = s * (1.f / 192.f);
            float rinv = rsqrtf(ss * (1.f / 192.f) - mean * mean + 1e-5f);
#pragma unroll
            for (int j = 0; j < 6; j++) {
                int k = lane + 32 * j;
                xwh[n * XW_STRH + k] = __float2half((v[j] - mean) * rinv * n1w[k] + n1b[k]);
            }
        } else {
#pragma unroll
            for (int j = 0; j < 3; j++) xwu[n * 100 + lane + 32 * j] = 0u;
        }
    }
    __syncthreads();   // LN (and vT/qk zeroing) complete

    // ---- Phase 2: QKV, B-fragments streamed from gmem ----
    for (int p = 0; p < 3; p++) {
        float4 acc[2][6];
#pragma unroll
        for (int mf = 0; mf < 2; mf++)
#pragma unroll
            for (int t = 0; t < 6; t++) acc[mf][t] = make_float4(0.f, 0.f, 0.f, 0.f);

        const int tbase = (24 * p + 6 * wn) * 12;
        uint2 bn[6];
#pragma unroll
        for (int tp = 0; tp < 6; tp++)
            bn[tp] = *(const uint2*)(g_qkvF + (size_t)(tbase + tp * 12) * 64 + 2 * lane);

        for (int ks = 0; ks < 12; ks++) {
            uint2 bc[6];
#pragma unroll
            for (int tp = 0; tp < 6; tp++) bc[tp] = bn[tp];
            if (ks < 11) {
#pragma unroll
                for (int tp = 0; tp < 6; tp++)
                    bn[tp] = *(const uint2*)(g_qkvF + (size_t)(tbase + tp * 12 + ks + 1) * 64 + 2 * lane);
            }
            uint32_t a[2][4];
            ldsm4(a[0][0], a[0][1], a[0][2], a[0][3], aBase + 32 * ks);
            ldsm4(a[1][0], a[1][1], a[1][2], a[1][3], aBase + 6400 + 32 * ks);
#pragma unroll
            for (int tp = 0; tp < 6; tp++)
#pragma unroll
                for (int mf = 0; mf < 2; mf++)
                    mma16(acc[mf][tp], a[mf][0], a[mf][1], a[mf][2], a[mf][3],
                          bc[tp].x, bc[tp].y);
        }
#pragma unroll
        for (int mf = 0; mf < 2; mf++) {
            int r0 = 32 * wm + 16 * mf + g;
            bool u0 = r0 < NT, u1 = (r0 + 8) < NT;
#pragma unroll
            for (int t = 0; t < 6; t++) {
                int col = 48 * wn + 8 * t + 2 * q;
                int j   = 192 * p + col;
                float b0v = __ldg(qkv_b + j), b1v = __ldg(qkv_b + j + 1);
                float o00 = acc[mf][t].x + b0v, o01 = acc[mf][t].y + b1v;
                float o10 = acc[mf][t].z + b0v, o11 = acc[mf][t].w + b1v;
                if (p == 0) { o00 *= SCALE; o01 *= SCALE; o10 *= SCALE; o11 *= SCALE; }
                if (p < 2) {
                    if (u0) *(__half2*)(qkh + r0 * QK_STRH + j)       = __floats2half2_rn(o00, o01);
                    if (u1) *(__half2*)(qkh + (r0 + 8) * QK_STRH + j) = __floats2half2_rn(o10, o11);
                } else {
                    if (u0) {
                        vth[col * VT_STRH + r0]       = __float2half(o00);
                        vth[(col + 1) * VT_STRH + r0] = __float2half(o01);
                    }
                    if (u1) {
                        vth[col * VT_STRH + r0 + 8]       = __float2half(o10);
                        vth[(col + 1) * VT_STRH + r0 + 8] = __float2half(o11);
                    }
                }
            }
        }
    }
    __syncthreads();   // Q/K/V ready

    // ---- Phase 3: mma attention over 24 (head, m-tile) units, 3 per warp ----
    {
#pragma unroll 1
        for (int t = 0; t < 3; t++) {
            const int u = warp * 3 + t;
            const int h = u >> 2;
            const int i = u & 3;
            const __half* bias = g_bias + ((size_t)(w * NHEAD + h)) * 64 * 56;
            const uint32_t kBase = smaddr(qkh + lr * QK_STRH + 192 + h * 32 + 8 * (lane >> 3));
            const uint32_t vBase = smaddr(vth + (h * 32 + lr) * VT_STRH + 8 * (lane >> 3));
            const int r0i = 16 * i + g, r1i = r0i + 8;

            float2 bb0[7], bb1[7];
#pragma unroll
            for (int j = 0; j < 7; j++) {
                bb0[j] = __half22float2(*(const __half2*)(bias + r0i * 56 + 8 * j + 2 * q));
                bb1[j] = __half22float2(*(const __half2*)(bias + r1i * 56 + 8 * j + 2 * q));
            }

            uint32_t qA = smaddr(qkh + (16 * i + lr + 8 * lb8) * QK_STRH + h * 32 + 8 * lb16);
            uint32_t aq[2][4];
            ldsm4(aq[0][0], aq[0][1], aq[0][2], aq[0][3], qA);
            ldsm4(aq[1][0], aq[1][1], aq[1][2], aq[1][3], qA + 32);
            float4 S[7];
#pragma unroll
            for (int j = 0; j < 7; j++) {
                S[j] = make_float4(0.f, 0.f, 0.f, 0.f);
                uint32_t b0, b1, b2, b3;
                ldsm4(b0, b1, b2, b3, kBase + j * (8 * QK_STRH * 2));
                mma16(S[j], aq[0][0], aq[0][1], aq[0][2], aq[0][3], b0, b1);
                mma16(S[j], aq[1][0], aq[1][1], aq[1][2], aq[1][3], b2, b3);
                S[j].x += bb0[j].x; S[j].y += bb0[j].y;
                S[j].z += bb1[j].x; S[j].w += bb1[j].y;
            }
            float mx0 = -1e30f, mx1 = -1e30f;
#pragma unroll
            for (int j = 0; j < 7; j++) {
                mx0 = fmaxf(mx0, fmaxf(S[j].x, S[j].y));
                mx1 = fmaxf(mx1, fmaxf(S[j].z, S[j].w));
            }
#pragma unroll
            for (int o = 1; o < 4; o <<= 1) {
                mx0 = fmaxf(mx0, __shfl_xor_sync(0xffffffffu, mx0, o));
                mx1 = fmaxf(mx1, __shfl_xor_sync(0xffffffffu, mx1, o));
            }
            float sum0 = 0.f, sum1 = 0.f;
#pragma unroll
            for (int j = 0; j < 7; j++) {
                S[j].x = __expf(S[j].x - mx0); S[j].y = __expf(S[j].y - mx0);
                S[j].z = __expf(S[j].z - mx1); S[j].w = __expf(S[j].w - mx1);
                sum0 += S[j].x + S[j].y; sum1 += S[j].z + S[j].w;
            }
#pragma unroll
            for (int o = 1; o < 4; o <<= 1) {
                sum0 += __shfl_xor_sync(0xffffffffu, sum0, o);
                sum1 += __shfl_xor_sync(0xffffffffu, sum1, o);
            }
            float rc0 = 1.f / sum0, rc1 = 1.f / sum1;
            uint32_t pa[4][4];
#pragma unroll
            for (int kk = 0; kk < 3; kk++) {
                pa[kk][0] = packh2(S[2 * kk].x, S[2 * kk].y);
                pa[kk][1] = packh2(S[2 * kk].z, S[2 * kk].w);
                pa[kk][2] = packh2(S[2 * kk + 1].x, S[2 * kk + 1].y);
                pa[kk][3] = packh2(S[2 * kk + 1].z, S[2 * kk + 1].w);
            }
            pa[3][0] = packh2(S[6].x, S[6].y);
            pa[3][1] = packh2(S[6].z, S[6].w);
            pa[3][2] = 0u; pa[3][3] = 0u;
            float4 O[4];
#pragma unroll
            for (int vj = 0; vj < 4; vj++) {
                O[vj] = make_float4(0.f, 0.f, 0.f, 0.f);
                uint32_t va0, va1, va2, va3, vb0, vb1, vb2, vb3;
                ldsm4(va0, va1, va2, va3, vBase + vj * (8 * VT_STRH * 2));
                ldsm4(vb0, vb1, vb2, vb3, vBase + vj * (8 * VT_STRH * 2) + 64);
                mma16(O[vj], pa[0][0], pa[0][1], pa[0][2], pa[0][3], va0, va1);
                mma16(O[vj], pa[1][0], pa[1][1], pa[1][2], pa[1][3], va2, va3);
                mma16(O[vj], pa[2][0], pa[2][1], pa[2][2], pa[2][3], vb0, vb1);
                mma16(O[vj], pa[3][0], pa[3][1], pa[3][2], pa[3][3], vb2, vb3);
            }
#pragma unroll
            for (int vj = 0; vj < 4; vj++) {
                int col = h * 32 + 8 * vj + 2 * q;
                if (r0i < NT)
                    *(__half2*)(xwh + r0i * XW_STRH + col) =
                        __floats2half2_rn(O[vj].x * rc0, O[vj].y * rc0);
                if (r1i < NT)
                    *(__half2*)(xwh + r1i * XW_STRH + col) =
                        __floats2half2_rn(O[vj].z * rc1, O[vj].w * rc1);
            }
        }
    }
    __syncthreads();   // attn out ready in xwh

    // ---- Phase 4: proj, B-fragments from gmem, fused residual scatter ----
    {
        float4 acc[2][6];
#pragma unroll
        for (int mf = 0; mf < 2; mf++)
#pragma unroll
            for (int t = 0; t < 6; t++) acc[mf][t] = make_float4(0.f, 0.f, 0.f, 0.f);

        const int tbase = (6 * wn) * 12;
        uint2 bn[6];
#pragma unroll
        for (int tp = 0; tp < 6; tp++)
            bn[tp] = *(const uint2*)(g_projF + (size_t)(tbase + tp * 12) * 64 + 2 * lane);

        for (int ks = 0; ks < 12; ks++) {
            uint2 bc[6];
#pragma unroll
            for (int tp = 0; tp < 6; tp++) bc[tp] = bn[tp];
            if (ks < 11) {
#pragma unroll
                for (int tp = 0; tp < 6; tp++)
                    bn[tp] = *(const uint2*)(g_projF + (size_t)(tbase + tp * 12 + ks + 1) * 64 + 2 * lane);
            }
            uint32_t a[2][4];
            ldsm4(a[0][0], a[0][1], a[0][2], a[0][3], aBase + 32 * ks);
            ldsm4(a[1][0], a[1][1], a[1][2], a[1][3], aBase + 6400 + 32 * ks);
#pragma unroll
            for (int tp = 0; tp < 6; tp++)
#pragma unroll
                for (int mf = 0; mf < 2; mf++)
                    mma16(acc[mf][tp], a[mf][0], a[mf][1], a[mf][2], a[mf][3],
                          bc[tp].x, bc[tp].y);
        }

#pragma unroll
        for (int mf = 0; mf < 2; mf++) {
            int r0 = 32 * wm + 16 * mf + g;
            bool u0 = r0 < NT, u1 = (r0 + 8) < NT;
            size_t base0 = 0, base1 = 0;
            if (u0) {
                int gr = wh * 7 + r0 / 7 + 3; if (gr >= 56) gr -= 56;
                int gc = ww * 7 + r0 % 7 + 3; if (gc >= 56) gc -= 56;
                base0 = ((size_t)b * 3136 + gr * 56 + gc) * Cc;
            }
            if (u1) {
                int r1 = r0 + 8;
                int gr = wh * 7 + r1 / 7 + 3; if (gr >= 56) gr -= 56;
                int gc = ww * 7 + r1 % 7 + 3; if (gc >= 56) gc -= 56;
                base1 = ((size_t)b * 3136 + gr * 56 + gc) * Cc;
            }
#pragma unroll
            for (int t = 0; t < 6; t++) {
                int col = 48 * wn + 8 * t + 2 * q;
                float pb0 = __ldg(proj_b + col), pb1 = __ldg(proj_b + col + 1);
                if (u0) {
                    float2 xv = *(const float2*)(x + base0 + col);
                    float2 r; r.x = xv.x + acc[mf][t].x + pb0; r.y = xv.y + acc[mf][t].y + pb1;
                    *(float2*)(g_x2 + base0 + col) = r;
                }
                if (u1) {
                    float2 xv = *(const float2*)(x + base1 + col);
                    float2 r; r.x = xv.x + acc[mf][t].z + pb0; r.y = xv.y + acc[mf][t].w + pb1;
                    *(float2*)(g_x2 + base1 + col) = r;
                }
            }
        }
    }

    // ---- release: band (b, wh) progress ----
    __threadfence();
    __syncthreads();
    if (tid == 0) atomicAdd(&g_dep[b * 8 + wh], 1);
}

__device__ __forceinline__ void mlp_body(
    __half* smh, int m,
    const float* __restrict__ n2w, const float* __restrict__ n2b,
    const float* __restrict__ fc1b, const float* __restrict__ fc2b,
    float* __restrict__ out)
{
    __half* xnh = smh;                       // [64][200]
    __half* hsh = smh + OFF_HS_H;            // [64][72]
    __half2* hs2 = (__half2*)hsh;

    const int tid  = threadIdx.x;
    const int warp = tid >> 5;
    const int lane = tid & 31;
    const int g    = lane >> 2;
    const int q    = lane & 3;
    const int wm   = warp & 1;      // fc2 m-half
    const int wn   = warp >> 1;     // fc2 n-quarter
    const int wm1  = warp >> 2;     // fc1 m-half (32 rows)
    const int wn1  = warp & 3;      // fc1 n-sixteenth (16 cols)
    const int lr   = lane & 7;
    const int lb8  = (lane >> 3) & 1;
    const int lb16 = lane >> 4;
    const size_t t0 = (size_t)m * 64;

    const uint32_t aBase1 = smaddr(xnh + (32 * wm1 + lr + 8 * lb8) * XW_STRH + 8 * lb16);
    const uint32_t aBase2 = smaddr(hsh + (32 * wm + lr + 8 * lb8) * 72 + 8 * lb16);

    // ---- acquire: wait for the attn bands covering these 64 tokens ----
    {
        int mm = m % 49;
        int bb = m / 49;
        int gr0 = (mm * 64) / 56;
        int gr1 = (mm * 64 + 63) / 56;
        int i0 = bb * 8 + ((gr0 + 53) % 56) / 7;
        int i1 = bb * 8 + ((gr1 + 53) % 56) / 7;
        if (tid == 0) {
            while (atomicAdd(&g_dep[i0], 0) < 8 || atomicAdd(&g_dep[i1], 0) < 8)
                __nanosleep(100);
        }
        __syncthreads();
    }

    // ---- LN2 ----
    for (int n = warp; n < 64; n += 8) {
        const float* xr = g_x2 + (t0 + n) * Cc;
        float v[6]; float s = 0.f, ss = 0.f;
#pragma unroll
        for (int j = 0; j < 6; j++) { v[j] = xr[lane + 32 * j]; s += v[j]; ss += v[j] * v[j]; }
#pragma unroll
        for (int o = 16; o > 0; o >>= 1) {
            s  += __shfl_xor_sync(0xffffffffu, s,  o);
            ss += __shfl_xor_sync(0xffffffffu, ss, o);
        }
        float mean = s * (1.f / 192.f);
        float rinv = rsqrtf(ss * (1.f / 192.f) - mean * mean + 1e-5f);
#pragma unroll
        for (int j = 0; j < 6; j++) {
            int k = lane + 32 * j;
            xnh[n * XW_STRH + k] = __float2half((v[j] - mean) * rinv * n2w[k] + n2b[k]);
        }
    }
    __syncthreads();   // xn ready

    float4 yacc[2][6];
#pragma unroll
    for (int mf = 0; mf < 2; mf++)
#pragma unroll
        for (int t = 0; t < 6; t++) yacc[mf][t] = make_float4(0.f, 0.f, 0.f, 0.f);

    for (int hc = 0; hc < HIDDEN; hc += 64) {
        // ---- fc1: H(64x64) = xn @ w1chunk ; warp tile m32 x n16 ----
        float4 acc1[2][2];
#pragma unroll
        for (int mf = 0; mf < 2; mf++)
#pragma unroll
            for (int t = 0; t < 2; t++) acc1[mf][t] = make_float4(0.f, 0.f, 0.f, 0.f);

        const int t1base = ((hc >> 3) + 2 * wn1) * 12;
        uint2 b1n[2];
#pragma unroll
        for (int t = 0; t < 2; t++)
            b1n[t] = *(const uint2*)(g_fc1F + (size_t)(t1base + t * 12) * 64 + 2 * lane);

        for (int ks = 0; ks < 12; ks++) {
            uint2 b1c[2];
#pragma unroll
            for (int t = 0; t < 2; t++) b1c[t] = b1n[t];
            if (ks < 11) {
#pragma unroll
                for (int t = 0; t < 2; t++)
                    b1n[t] = *(const uint2*)(g_fc1F + (size_t)(t1base + t * 12 + ks + 1) * 64 + 2 * lane);
            }
            uint32_t a[2][4];
            ldsm4(a[0][0], a[0][1], a[0][2], a[0][3], aBase1 + 32 * ks);
            ldsm4(a[1][0], a[1][1], a[1][2], a[1][3], aBase1 + 6400 + 32 * ks);
#pragma unroll
            for (int t = 0; t < 2; t++)
#pragma unroll
                for (int mf = 0; mf < 2; mf++)
                    mma16(acc1[mf][t], a[mf][0], a[mf][1], a[mf][2], a[mf][3],
                          b1c[t].x, b1c[t].y);
        }

        // prefetch fc2 chunk-0 fragments (latency hidden behind barriers/gelu)
        const int t2k = hc >> 4;
        uint2 b2n[6];
#pragma unroll
        for (int tp = 0; tp < 6; tp++)
            b2n[tp] = *(const uint2*)(g_fc2F + (size_t)((6 * wn + tp) * 48 + t2k) * 64 + 2 * lane);

        __syncthreads();   // previous fc2 finished reading hs
        // bias + gelu -> hs
#pragma unroll
        for (int mf = 0; mf < 2; mf++) {
            int rF = 32 * wm1 + 16 * mf + g;
#pragma unroll
            for (int t = 0; t < 2; t++) {
                int col = 16 * wn1 + 8 * t + 2 * q;
                float b0v = __ldg(fc1b + hc + col), b1v = __ldg(fc1b + hc + col + 1);
                int wi = 8 * wn1 + 4 * t + q;
                hs2[rF * 36 + wi]       = __floats2half2_rn(gelu_exact(acc1[mf][t].x + b0v),
                                                            gelu_exact(acc1[mf][t].y + b1v));
                hs2[(rF + 8) * 36 + wi] = __floats2half2_rn(gelu_exact(acc1[mf][t].z + b0v),
                                                            gelu_exact(acc1[mf][t].w + b1v));
            }
        }
        __syncthreads();   // hs ready

        // ---- fc2: Y += H @ w2chunk ; warp tile m32 x n48, 4 k-steps ----
        for (int ks = 0; ks < 4; ks++) {
            uint2 b2c[6];
#pragma unroll
            for (int tp = 0; tp < 6; tp++) b2c[tp] = b2n[tp];
            if (ks < 3) {
#pragma unroll
                for (int tp = 0; tp < 6; tp++)
                    b2n[tp] = *(const uint2*)(g_fc2F + (size_t)((6 * wn + tp) * 48 + t2k + ks + 1) * 64 + 2 * lane);
            }
            uint32_t a[2][4];
            ldsm4(a[0][0], a[0][1], a[0][2], a[0][3], aBase2 + 32 * ks);
            ldsm4(a[1][0], a[1][1], a[1][2], a[1][3], aBase2 + 2304 + 32 * ks);
#pragma unroll
            for (int tp = 0; tp < 6; tp++)
#pragma unroll
                for (int mf = 0; mf < 2; mf++)
                    mma16(yacc[mf][tp], a[mf][0], a[mf][1], a[mf][2], a[mf][3],
                          b2c[tp].x, b2c[tp].y);
        }
    }

#pragma unroll
    for (int mf = 0; mf < 2; mf++) {
        int r0 = 32 * wm + 16 * mf + g;
#pragma unroll
        for (int t = 0; t < 6; t++) {
            int col = 48 * wn + 8 * t + 2 * q;
            float b0v = __ldg(fc2b + col), b1v = __ldg(fc2b + col + 1);
            {
                size_t base = (t0 + r0) * Cc + col;
                float2 xv = *(const float2*)(g_x2 + base);
                float2 r; r.x = xv.x + yacc[mf][t].x + b0v; r.y = xv.y + yacc[mf][t].y + b1v;
                *(float2*)(out + base) = r;
            }
            {
                size_t base = (t0 + r0 + 8) * Cc + col;
                float2 xv = *(const float2*)(g_x2 + base);
                float2 r; r.x = xv.x + yacc[mf][t].z + b0v; r.y = xv.y + yacc[mf][t].w + b1v;
                *(float2*)(out + base) = r;
            }
        }
    }
}

__global__ __launch_bounds__(256, 2) void swin_fused_kernel(
    const float* __restrict__ x,
    const float* __restrict__ qkv_b, const float* __restrict__ proj_b,
    const float* __restrict__ n1w, const float* __restrict__ n1b,
    const float* __restrict__ n2w, const float* __restrict__ n2b,
    const float* __restrict__ fc1b, const float* __restrict__ fc2b,
    float* __restrict__ out)
{
    extern __shared__ __half smh[];
    const int bid = blockIdx.x;
    if (bid < ATTN_BLOCKS) {
        attn_body(smh, bid, x, qkv_b, proj_b, n1w, n1b);
    } else {
        mlp_body(smh, bid - ATTN_BLOCKS, n2w, n2b, fc1b, fc2b, out);
    }
}

// ---------------------------------------------------------------------------
extern "C" void kernel_launch(void* const* d_in, const int* in_sizes, int n_in,
                              void* d_out, int out_size)
{
    const float* x      = (const float*)d_in[0];
    const float* mask   = (const float*)d_in[1];
    const float* rel    = (const float*)d_in[2];
    const float* qkv_w  = (const float*)d_in[3];
    const float* qkv_b  = (const float*)d_in[4];
    const float* proj_w = (const float*)d_in[5];
    const float* proj_b = (const float*)d_in[6];
    const float* n1w    = (const float*)d_in[7];
    const float* n1b    = (const float*)d_in[8];
    const float* n2w    = (const float*)d_in[9];
    const float* n2b    = (const float*)d_in[10];
    const float* fc1w   = (const float*)d_in[11];
    const float* fc1b   = (const float*)d_in[12];
    const float* fc2w   = (const float*)d_in[13];
    const float* fc2b   = (const float*)d_in[14];
    float* out = (float*)d_out;

    cudaFuncSetAttribute(swin_fused_kernel, cudaFuncAttributeMaxDynamicSharedMemorySize,
                         FUSED_SM_BYTES);

    convert_w<<<1184, 256>>>(qkv_w, proj_w, fc1w, fc2w, mask, rel);
    swin_fused_kernel<<<ATTN_BLOCKS + MLP_BLOCKS, 256, FUSED_SM_BYTES>>>(
        x, qkv_b, proj_b, n1w, n1b, n2w, n2b, fc1b, fc2b, out);
}

// round 13
// speedup vs baseline: 8.6399x; 1.0555x over previous
#include <cuda_runtime.h>
#include <cuda_fp16.h>
#include <math.h>
#include <stdint.h>

#define Bn 32
#define Cc 192
#define WSZ 7
#define NHEAD 6
#define NT 49
#define HIDDEN 768
#define SCALE 0.17677669529663687f
#define ATTN_BLOCKS 2048
#define MLP_BLOCKS 1568

// scratch for x + attention residual
__device__ float g_x2[(size_t)Bn * 56 * 56 * Cc];
// dependency counters: [batch 32][band 8]
__device__ int g_dep[Bn * 8];

// fragment-packed fp16 weights, (n8 x k32) super-tiles of 128 u32:
// lane L holds 4 consecutive u32 at 4*L = {k16#0 b0,b1, k16#1 b0,b1}
// stile index = (n/8)*(K/32) + k/32
__device__ __align__(16) uint32_t g_qkvF[72 * 6 * 128];    // N=576 K=192
__device__ __align__(16) uint32_t g_projF[24 * 6 * 128];   // N=192 K=192
__device__ __align__(16) uint32_t g_fc1F[96 * 6 * 128];    // N=768 K=192
__device__ __align__(16) uint32_t g_fc2F[24 * 24 * 128];   // N=192 K=768
// fused rel-pos bias + shift mask, padded: [win 64][head 6][row 64][col 56]
__device__ __align__(16) __half g_bias[64 * 6 * 64 * 56];

__device__ __forceinline__ uint32_t packh2(float a, float b) {
    __half2 h = __floats2half2_rn(a, b);
    return *(uint32_t*)&h;
}

__global__ void convert_w(const float* __restrict__ qkv_w, const float* __restrict__ proj_w,
                          const float* __restrict__ fc1w, const float* __restrict__ fc2w,
                          const float* __restrict__ mask, const float* __restrict__ rel_table)
{
    int tid = blockIdx.x * blockDim.x + threadIdx.x;
    int stride = gridDim.x * blockDim.x;
    if (tid < Bn * 8) g_dep[tid] = 0;
    // QKV: src [192 k][576 n]
    for (int j = tid; j < 72 * 6 * 128; j += stride) {
        int st = j >> 7, r = j & 127, L = r >> 2, c = r & 3;
        int n = (st / 6) * 8 + (L >> 2);
        int k = (st % 6) * 32 + (c >> 1) * 16 + (c & 1) * 8 + (L & 3) * 2;
        g_qkvF[j] = packh2(qkv_w[k * 576 + n], qkv_w[(k + 1) * 576 + n]);
    }
    // proj: src [192][192]
    for (int j = tid; j < 24 * 6 * 128; j += stride) {
        int st = j >> 7, r = j & 127, L = r >> 2, c = r & 3;
        int n = (st / 6) * 8 + (L >> 2);
        int k = (st % 6) * 32 + (c >> 1) * 16 + (c & 1) * 8 + (L & 3) * 2;
        g_projF[j] = packh2(proj_w[k * 192 + n], proj_w[(k + 1) * 192 + n]);
    }
    // fc1: src [192 k][768 n]
    for (int j = tid; j < 96 * 6 * 128; j += stride) {
        int st = j >> 7, r = j & 127, L = r >> 2, c = r & 3;
        int n = (st / 6) * 8 + (L >> 2);
        int k = (st % 6) * 32 + (c >> 1) * 16 + (c & 1) * 8 + (L & 3) * 2;
        g_fc1F[j] = packh2(fc1w[k * 768 + n], fc1w[(k + 1) * 768 + n]);
    }
    // fc2: src [768 k][192 n]
    for (int j = tid; j < 24 * 24 * 128; j += stride) {
        int st = j >> 7, r = j & 127, L = r >> 2, c = r & 3;
        int n = (st / 24) * 8 + (L >> 2);
        int k = (st % 24) * 32 + (c >> 1) * 16 + (c & 1) * 8 + (L & 3) * 2;
        g_fc2F[j] = packh2(fc2w[k * 192 + n], fc2w[(k + 1) * 192 + n]);
    }
    for (int j = tid; j < 64 * 6 * 64 * 56; j += stride) {
        int col = j % 56;
        int rest = j / 56;
        int row = rest % 64; rest /= 64;
        int h = rest % 6;
        int w = rest / 6;
        float v;
        if (row >= NT)      v = 0.f;
        else if (col >= NT) v = -30000.f;
        else {
            int rr = row / 7 - col / 7 + 6;
            int cc = row % 7 - col % 7 + 6;
            v = rel_table[(rr * 13 + cc) * NHEAD + h] + mask[w * 2401 + row * 49 + col];
        }
        g_bias[j] = __float2half(v);
    }
}

__device__ __forceinline__ void mma16(float4& c, uint32_t a0, uint32_t a1, uint32_t a2,
                                      uint32_t a3, uint32_t b0, uint32_t b1) {
    asm volatile(
        "mma.sync.aligned.m16n8k16.row.col.f32.f16.f16.f32 "
        "{%0,%1,%2,%3},{%4,%5,%6,%7},{%8,%9},{%0,%1,%2,%3};"
        : "+f"(c.x), "+f"(c.y), "+f"(c.z), "+f"(c.w)
        : "r"(a0), "r"(a1), "r"(a2), "r"(a3), "r"(b0), "r"(b1));
}

__device__ __forceinline__ uint32_t smaddr(const void* p) {
    return (uint32_t)__cvta_generic_to_shared(p);
}

__device__ __forceinline__ void ldsm4(uint32_t& r0, uint32_t& r1, uint32_t& r2,
                                      uint32_t& r3, uint32_t a) {
    asm volatile("ldmatrix.sync.aligned.m8n8.x4.shared.b16 {%0,%1,%2,%3},[%4];"
                 : "=r"(r0), "=r"(r1), "=r"(r2), "=r"(r3) : "r"(a));
}

__device__ __forceinline__ float gelu_exact(float v) {
    return 0.5f * v * (1.0f + erff(v * 0.70710678118654752f));
}

// ---------------------------------------------------------------------------
#define XW_STRH 200
#define QK_STRH 392
#define VT_STRH 72
#define HS_STRH 136
#define OFF_QK_H 12800        // 64*200
#define OFF_VT_H 34752        // + 56*392
#define FUSED_SM_BYTES (48576 * 2)
#define OFF_HS_H 12800

__device__ __forceinline__ void attn_body(
    __half* smh, int bid,
    const float* __restrict__ x,
    const float* __restrict__ qkv_b, const float* __restrict__ proj_b,
    const float* __restrict__ n1w, const float* __restrict__ n1b)
{
    __half* xwh = smh;                   // [64][200]
    __half* qkh = smh + OFF_QK_H;        // [56][392]
    __half* vth = smh + OFF_VT_H;        // [192][72]
    uint32_t* xwu  = (uint32_t*)xwh;
    uint32_t* vtu  = (uint32_t*)vth;

    const int b    = bid >> 6;
    const int w    = bid & 63;
    const int wh   = w >> 3;
    const int ww   = w & 7;
    const int tid  = threadIdx.x;
    const int warp = tid >> 5;
    const int lane = tid & 31;
    const int g    = lane >> 2;
    const int q    = lane & 3;
    const int wm   = warp & 1;
    const int wn   = warp >> 1;
    const int lr   = lane & 7;
    const int lb8  = (lane >> 3) & 1;
    const int lb16 = lane >> 4;

    const uint32_t aBase = smaddr(xwh + (32 * wm + lr + 8 * lb8) * XW_STRH + 8 * lb16);

    for (int idx = tid; idx < 192 * 36; idx += 256) vtu[idx] = 0u;
    for (int idx = tid; idx < 7 * 196; idx += 256)
        ((uint32_t*)qkh)[(49 + idx / 196) * 196 + idx % 196] = 0u;

    // ---- Phase 1: gather + LN1 ----
    for (int n = warp; n < 64; n += 8) {
        if (n < NT) {
            int r  = wh * WSZ + n / WSZ;
            int c  = ww * WSZ + n % WSZ;
            int gr = r + 3; if (gr >= 56) gr -= 56;
            int gc = c + 3; if (gc >= 56) gc -= 56;
            const float* xr = x + ((size_t)b * 3136 + gr * 56 + gc) * Cc;
            float v[6]; float s = 0.f, ss = 0.f;
#pragma unroll
            for (int j = 0; j < 6; j++) { v[j] = xr[lane + 32 * j]; s += v[j]; ss += v[j] * v[j]; }
#pragma unroll
            for (int o = 16; o > 0; o >>= 1) {
                s  += __shfl_xor_sync(0xffffffffu, s,  o);
                ss += __shfl_xor_sync(0xffffffffu, ss, o);
            }
            float mean = s * (1.f / 192.f);
            float rinv = rsqrtf(ss * (1.f / 192.f) - mean * mean + 1e-5f);
#pragma unroll
            for (int j = 0; j < 6; j++) {
                int k = lane + 32 * j;
                xwh[n * XW_STRH + k] = __float2half((v[j] - mean) * rinv * n1w[k] + n1b[k]);
            }
        } else {
#pragma unroll
            for (int j = 0; j < 3; j++) xwu[n * 100 + lane + 32 * j] = 0u;
        }
    }
    __syncthreads();

    // ---- Phase 2: QKV, uint4 B-fragments from gmem ----
    for (int p = 0; p < 3; p++) {
        float4 acc[2][6];
#pragma unroll
        for (int mf = 0; mf < 2; mf++)
#pragma unroll
            for (int t = 0; t < 6; t++) acc[mf][t] = make_float4(0.f, 0.f, 0.f, 0.f);

        const int sb = (24 * p + 6 * wn) * 6;
        uint4 bn[6];
#pragma unroll
        for (int tp = 0; tp < 6; tp++)
            bn[tp] = *(const uint4*)(g_qkvF + (size_t)(sb + tp * 6) * 128 + 4 * lane);

#pragma unroll
        for (int kc = 0; kc < 6; kc++) {
            uint4 bc[6];
#pragma unroll
            for (int tp = 0; tp < 6; tp++) bc[tp] = bn[tp];
            if (kc < 5) {
#pragma unroll
                for (int tp = 0; tp < 6; tp++)
                    bn[tp] = *(const uint4*)(g_qkvF + (size_t)(sb + tp * 6 + kc + 1) * 128 + 4 * lane);
            } else if (p < 2) {
                const int sb2 = (24 * (p + 1) + 6 * wn) * 6;
#pragma unroll
                for (int tp = 0; tp < 6; tp++)
                    bn[tp] = *(const uint4*)(g_qkvF + (size_t)(sb2 + tp * 6) * 128 + 4 * lane);
            }
#pragma unroll
            for (int ss = 0; ss < 2; ss++) {
                uint32_t a[2][4];
                ldsm4(a[0][0], a[0][1], a[0][2], a[0][3], aBase + 64 * kc + 32 * ss);
                ldsm4(a[1][0], a[1][1], a[1][2], a[1][3], aBase + 6400 + 64 * kc + 32 * ss);
#pragma unroll
                for (int tp = 0; tp < 6; tp++) {
                    uint32_t b0 = ss ? bc[tp].z : bc[tp].x;
                    uint32_t b1 = ss ? bc[tp].w : bc[tp].y;
#pragma unroll
                    for (int mf = 0; mf < 2; mf++)
                        mma16(acc[mf][tp], a[mf][0], a[mf][1], a[mf][2], a[mf][3], b0, b1);
                }
            }
        }
#pragma unroll
        for (int mf = 0; mf < 2; mf++) {
            int r0 = 32 * wm + 16 * mf + g;
            bool u0 = r0 < NT, u1 = (r0 + 8) < NT;
#pragma unroll
            for (int t = 0; t < 6; t++) {
                int col = 48 * wn + 8 * t + 2 * q;
                int j   = 192 * p + col;
                float b0v = __ldg(qkv_b + j), b1v = __ldg(qkv_b + j + 1);
                float o00 = acc[mf][t].x + b0v, o01 = acc[mf][t].y + b1v;
                float o10 = acc[mf][t].z + b0v, o11 = acc[mf][t].w + b1v;
                if (p == 0) { o00 *= SCALE; o01 *= SCALE; o10 *= SCALE; o11 *= SCALE; }
                if (p < 2) {
                    if (u0) *(__half2*)(qkh + r0 * QK_STRH + j)       = __floats2half2_rn(o00, o01);
                    if (u1) *(__half2*)(qkh + (r0 + 8) * QK_STRH + j) = __floats2half2_rn(o10, o11);
                } else {
                    if (u0) {
                        vth[col * VT_STRH + r0]       = __float2half(o00);
                        vth[(col + 1) * VT_STRH + r0] = __float2half(o01);
                    }
                    if (u1) {
                        vth[col * VT_STRH + r0 + 8]       = __float2half(o10);
                        vth[(col + 1) * VT_STRH + r0 + 8] = __float2half(o11);
                    }
                }
            }
        }
    }
    __syncthreads();

    // ---- Phase 3: mma attention, 24 units, 3 per warp ----
    {
#pragma unroll 1
        for (int t = 0; t < 3; t++) {
            const int u = warp * 3 + t;
            const int h = u >> 2;
            const int i = u & 3;
            const __half* bias = g_bias + ((size_t)(w * NHEAD + h)) * 64 * 56;
            const uint32_t kBase = smaddr(qkh + lr * QK_STRH + 192 + h * 32 + 8 * (lane >> 3));
            const uint32_t vBase = smaddr(vth + (h * 32 + lr) * VT_STRH + 8 * (lane >> 3));
            const int r0i = 16 * i + g, r1i = r0i + 8;

            float2 bb0[7], bb1[7];
#pragma unroll
            for (int j = 0; j < 7; j++) {
                bb0[j] = __half22float2(*(const __half2*)(bias + r0i * 56 + 8 * j + 2 * q));
                bb1[j] = __half22float2(*(const __half2*)(bias + r1i * 56 + 8 * j + 2 * q));
            }

            uint32_t qA = smaddr(qkh + (16 * i + lr + 8 * lb8) * QK_STRH + h * 32 + 8 * lb16);
            uint32_t aq[2][4];
            ldsm4(aq[0][0], aq[0][1], aq[0][2], aq[0][3], qA);
            ldsm4(aq[1][0], aq[1][1], aq[1][2], aq[1][3], qA + 32);
            float4 S[7];
#pragma unroll
            for (int j = 0; j < 7; j++) {
                S[j] = make_float4(0.f, 0.f, 0.f, 0.f);
                uint32_t b0, b1, b2, b3;
                ldsm4(b0, b1, b2, b3, kBase + j * (8 * QK_STRH * 2));
                mma16(S[j], aq[0][0], aq[0][1], aq[0][2], aq[0][3], b0, b1);
                mma16(S[j], aq[1][0], aq[1][1], aq[1][2], aq[1][3], b2, b3);
                S[j].x += bb0[j].x; S[j].y += bb0[j].y;
                S[j].z += bb1[j].x; S[j].w += bb1[j].y;
            }
            float mx0 = -1e30f, mx1 = -1e30f;
#pragma unroll
            for (int j = 0; j < 7; j++) {
                mx0 = fmaxf(mx0, fmaxf(S[j].x, S[j].y));
                mx1 = fmaxf(mx1, fmaxf(S[j].z, S[j].w));
            }
#pragma unroll
            for (int o = 1; o < 4; o <<= 1) {
                mx0 = fmaxf(mx0, __shfl_xor_sync(0xffffffffu, mx0, o));
                mx1 = fmaxf(mx1, __shfl_xor_sync(0xffffffffu, mx1, o));
            }
            float sum0 = 0.f, sum1 = 0.f;
#pragma unroll
            for (int j = 0; j < 7; j++) {
                S[j].x = __expf(S[j].x - mx0); S[j].y = __expf(S[j].y - mx0);
                S[j].z = __expf(S[j].z - mx1); S[j].w = __expf(S[j].w - mx1);
                sum0 += S[j].x + S[j].y; sum1 += S[j].z + S[j].w;
            }
#pragma unroll
            for (int o = 1; o < 4; o <<= 1) {
                sum0 += __shfl_xor_sync(0xffffffffu, sum0, o);
                sum1 += __shfl_xor_sync(0xffffffffu, sum1, o);
            }
            float rc0 = 1.f / sum0, rc1 = 1.f / sum1;
            uint32_t pa[4][4];
#pragma unroll
            for (int kk = 0; kk < 3; kk++) {
                pa[kk][0] = packh2(S[2 * kk].x, S[2 * kk].y);
                pa[kk][1] = packh2(S[2 * kk].z, S[2 * kk].w);
                pa[kk][2] = packh2(S[2 * kk + 1].x, S[2 * kk + 1].y);
                pa[kk][3] = packh2(S[2 * kk + 1].z, S[2 * kk + 1].w);
            }
            pa[3][0] = packh2(S[6].x, S[6].y);
            pa[3][1] = packh2(S[6].z, S[6].w);
            pa[3][2] = 0u; pa[3][3] = 0u;
            float4 O[4];
#pragma unroll
            for (int vj = 0; vj < 4; vj++) {
                O[vj] = make_float4(0.f, 0.f, 0.f, 0.f);
                uint32_t va0, va1, va2, va3, vb0, vb1, vb2, vb3;
                ldsm4(va0, va1, va2, va3, vBase + vj * (8 * VT_STRH * 2));
                ldsm4(vb0, vb1, vb2, vb3, vBase + vj * (8 * VT_STRH * 2) + 64);
                mma16(O[vj], pa[0][0], pa[0][1], pa[0][2], pa[0][3], va0, va1);
                mma16(O[vj], pa[1][0], pa[1][1], pa[1][2], pa[1][3], va2, va3);
                mma16(O[vj], pa[2][0], pa[2][1], pa[2][2], pa[2][3], vb0, vb1);
                mma16(O[vj], pa[3][0], pa[3][1], pa[3][2], pa[3][3], vb2, vb3);
            }
#pragma unroll
            for (int vj = 0; vj < 4; vj++) {
                int col = h * 32 + 8 * vj + 2 * q;
                if (r0i < NT)
                    *(__half2*)(xwh + r0i * XW_STRH + col) =
                        __floats2half2_rn(O[vj].x * rc0, O[vj].y * rc0);
                if (r1i < NT)
                    *(__half2*)(xwh + r1i * XW_STRH + col) =
                        __floats2half2_rn(O[vj].z * rc1, O[vj].w * rc1);
            }
        }
    }
    __syncthreads();

    // ---- Phase 4: proj, uint4 B-fragments, fused residual scatter ----
    {
        float4 acc[2][6];
#pragma unroll
        for (int mf = 0; mf < 2; mf++)
#pragma unroll
            for (int t = 0; t < 6; t++) acc[mf][t] = make_float4(0.f, 0.f, 0.f, 0.f);

        const int sb = (6 * wn) * 6;
        uint4 bn[6];
#pragma unroll
        for (int tp = 0; tp < 6; tp++)
            bn[tp] = *(const uint4*)(g_projF + (size_t)(sb + tp * 6) * 128 + 4 * lane);

#pragma unroll
        for (int kc = 0; kc < 6; kc++) {
            uint4 bc[6];
#pragma unroll
            for (int tp = 0; tp < 6; tp++) bc[tp] = bn[tp];
            if (kc < 5) {
#pragma unroll
                for (int tp = 0; tp < 6; tp++)
                    bn[tp] = *(const uint4*)(g_projF + (size_t)(sb + tp * 6 + kc + 1) * 128 + 4 * lane);
            }
#pragma unroll
            for (int ss = 0; ss < 2; ss++) {
                uint32_t a[2][4];
                ldsm4(a[0][0], a[0][1], a[0][2], a[0][3], aBase + 64 * kc + 32 * ss);
                ldsm4(a[1][0], a[1][1], a[1][2], a[1][3], aBase + 6400 + 64 * kc + 32 * ss);
#pragma unroll
                for (int tp = 0; tp < 6; tp++) {
                    uint32_t b0 = ss ? bc[tp].z : bc[tp].x;
                    uint32_t b1 = ss ? bc[tp].w : bc[tp].y;
#pragma unroll
                    for (int mf = 0; mf < 2; mf++)
                        mma16(acc[mf][tp], a[mf][0], a[mf][1], a[mf][2], a[mf][3], b0, b1);
                }
            }
        }

#pragma unroll
        for (int mf = 0; mf < 2; mf++) {
            int r0 = 32 * wm + 16 * mf + g;
            bool u0 = r0 < NT, u1 = (r0 + 8) < NT;
            size_t base0 = 0, base1 = 0;
            if (u0) {
                int gr = wh * 7 + r0 / 7 + 3; if (gr >= 56) gr -= 56;
                int gc = ww * 7 + r0 % 7 + 3; if (gc >= 56) gc -= 56;
                base0 = ((size_t)b * 3136 + gr * 56 + gc) * Cc;
            }
            if (u1) {
                int r1 = r0 + 8;
                int gr = wh * 7 + r1 / 7 + 3; if (gr >= 56) gr -= 56;
                int gc = ww * 7 + r1 % 7 + 3; if (gc >= 56) gc -= 56;
                base1 = ((size_t)b * 3136 + gr * 56 + gc) * Cc;
            }
#pragma unroll
            for (int t = 0; t < 6; t++) {
                int col = 48 * wn + 8 * t + 2 * q;
                float pb0 = __ldg(proj_b + col), pb1 = __ldg(proj_b + col + 1);
                if (u0) {
                    float2 xv = *(const float2*)(x + base0 + col);
                    float2 r; r.x = xv.x + acc[mf][t].x + pb0; r.y = xv.y + acc[mf][t].y + pb1;
                    *(float2*)(g_x2 + base0 + col) = r;
                }
                if (u1) {
                    float2 xv = *(const float2*)(x + base1 + col);
                    float2 r; r.x = xv.x + acc[mf][t].z + pb0; r.y = xv.y + acc[mf][t].w + pb1;
                    *(float2*)(g_x2 + base1 + col) = r;
                }
            }
        }
    }

    __threadfence();
    __syncthreads();
    if (tid == 0) atomicAdd(&g_dep[b * 8 + wh], 1);
}

__device__ __forceinline__ void mlp_body(
    __half* smh, int m,
    const float* __restrict__ n2w, const float* __restrict__ n2b,
    const float* __restrict__ fc1b, const float* __restrict__ fc2b,
    float* __restrict__ out)
{
    __half* xnh = smh;                       // [64][200]
    __half* hsh = smh + OFF_HS_H;            // [64][136]
    __half2* hs2 = (__half2*)hsh;

    const int tid  = threadIdx.x;
    const int warp = tid >> 5;
    const int lane = tid & 31;
    const int g    = lane >> 2;
    const int q    = lane & 3;
    const int wm   = warp & 1;      // fc2 m-half
    const int wn   = warp >> 1;     // fc2 n-quarter (48 cols)
    const int wm1  = warp >> 2;     // fc1 m-half (32 rows)
    const int wn1  = warp & 3;      // fc1 n-32 block within 128-chunk
    const int lr   = lane & 7;
    const int lb8  = (lane >> 3) & 1;
    const int lb16 = lane >> 4;
    const size_t t0 = (size_t)m * 64;

    const uint32_t aBase1 = smaddr(xnh + (32 * wm1 + lr + 8 * lb8) * XW_STRH + 8 * lb16);
    const uint32_t aBase2 = smaddr(hsh + (32 * wm + lr + 8 * lb8) * HS_STRH + 8 * lb16);

    // ---- acquire ----
    {
        int mm = m % 49;
        int bb = m / 49;
        int gr0 = (mm * 64) / 56;
        int gr1 = (mm * 64 + 63) / 56;
        int i0 = bb * 8 + ((gr0 + 53) % 56) / 7;
        int i1 = bb * 8 + ((gr1 + 53) % 56) / 7;
        if (tid == 0) {
            while (atomicAdd(&g_dep[i0], 0) < 8 || atomicAdd(&g_dep[i1], 0) < 8)
                __nanosleep(100);
        }
        __syncthreads();
    }

    // ---- LN2 ----
    for (int n = warp; n < 64; n += 8) {
        const float* xr = g_x2 + (t0 + n) * Cc;
        float v[6]; float s = 0.f, ss = 0.f;
#pragma unroll
        for (int j = 0; j < 6; j++) { v[j] = xr[lane + 32 * j]; s += v[j]; ss += v[j] * v[j]; }
#pragma unroll
        for (int o = 16; o > 0; o >>= 1) {
            s  += __shfl_xor_sync(0xffffffffu, s,  o);
            ss += __shfl_xor_sync(0xffffffffu, ss, o);
        }
        float mean = s * (1.f / 192.f);
        float rinv = rsqrtf(ss * (1.f / 192.f) - mean * mean + 1e-5f);
#pragma unroll
        for (int j = 0; j < 6; j++) {
            int k = lane + 32 * j;
            xnh[n * XW_STRH + k] = __float2half((v[j] - mean) * rinv * n2w[k] + n2b[k]);
        }
    }
    __syncthreads();

    float4 yacc[2][6];
#pragma unroll
    for (int mf = 0; mf < 2; mf++)
#pragma unroll
        for (int t = 0; t < 6; t++) yacc[mf][t] = make_float4(0.f, 0.f, 0.f, 0.f);

    for (int hc = 0; hc < HIDDEN; hc += 128) {
        // ---- fc1: H(64x128) = xn @ w1chunk ; warp tile m32 x n32 ----
        float4 acc1[2][4];
#pragma unroll
        for (int mf = 0; mf < 2; mf++)
#pragma unroll
            for (int t = 0; t < 4; t++) acc1[mf][t] = make_float4(0.f, 0.f, 0.f, 0.f);

        const int sb1 = ((hc >> 3) + 4 * wn1) * 6;
        uint4 b1n[4];
#pragma unroll
        for (int t = 0; t < 4; t++)
            b1n[t] = *(const uint4*)(g_fc1F + (size_t)(sb1 + t * 6) * 128 + 4 * lane);

#pragma unroll
        for (int kc = 0; kc < 6; kc++) {
            uint4 b1c[4];
#pragma unroll
            for (int t = 0; t < 4; t++) b1c[t] = b1n[t];
            if (kc < 5) {
#pragma unroll
                for (int t = 0; t < 4; t++)
                    b1n[t] = *(const uint4*)(g_fc1F + (size_t)(sb1 + t * 6 + kc + 1) * 128 + 4 * lane);
            }
#pragma unroll
            for (int ss = 0; ss < 2; ss++) {
                uint32_t a[2][4];
                ldsm4(a[0][0], a[0][1], a[0][2], a[0][3], aBase1 + 64 * kc + 32 * ss);
                ldsm4(a[1][0], a[1][1], a[1][2], a[1][3], aBase1 + 6400 + 64 * kc + 32 * ss);
#pragma unroll
                for (int t = 0; t < 4; t++) {
                    uint32_t b0 = ss ? b1c[t].z : b1c[t].x;
                    uint32_t b1 = ss ? b1c[t].w : b1c[t].y;
#pragma unroll
                    for (int mf = 0; mf < 2; mf++)
                        mma16(acc1[mf][t], a[mf][0], a[mf][1], a[mf][2], a[mf][3], b0, b1);
                }
            }
        }

        // prefetch fc2 first k32 of this chunk
        const int t2k = hc >> 5;
        uint4 b2n[6];
#pragma unroll
        for (int tp = 0; tp < 6; tp++)
            b2n[tp] = *(const uint4*)(g_fc2F + (size_t)((6 * wn + tp) * 24 + t2k) * 128 + 4 * lane);

        __syncthreads();   // previous fc2 done reading hs
        // bias + gelu -> hs
#pragma unroll
        for (int mf = 0; mf < 2; mf++) {
            int rF = 32 * wm1 + 16 * mf + g;
#pragma unroll
            for (int t = 0; t < 4; t++) {
                int col = 32 * wn1 + 8 * t + 2 * q;
                float b0v = __ldg(fc1b + hc + col), b1v = __ldg(fc1b + hc + col + 1);
                int wi = 16 * wn1 + 4 * t + q;
                hs2[rF * 68 + wi]       = __floats2half2_rn(gelu_exact(acc1[mf][t].x + b0v),
                                                            gelu_exact(acc1[mf][t].y + b1v));
                hs2[(rF + 8) * 68 + wi] = __floats2half2_rn(gelu_exact(acc1[mf][t].z + b0v),
                                                            gelu_exact(acc1[mf][t].w + b1v));
            }
        }
        __syncthreads();   // hs ready

        // ---- fc2: Y += H @ w2chunk ; warp tile m32 x n48, 4 k32 steps ----
#pragma unroll
        for (int kc = 0; kc < 4; kc++) {
            uint4 b2c[6];
#pragma unroll
            for (int tp = 0; tp < 6; tp++) b2c[tp] = b2n[tp];
            if (kc < 3) {
#pragma unroll
                for (int tp = 0; tp < 6; tp++)
                    b2n[tp] = *(const uint4*)(g_fc2F + (size_t)((6 * wn + tp) * 24 + t2k + kc + 1) * 128 + 4 * lane);
            }
#pragma unroll
            for (int ss = 0; ss < 2; ss++) {
                uint32_t a[2][4];
                ldsm4(a[0][0], a[0][1], a[0][2], a[0][3], aBase2 + 64 * kc + 32 * ss);
                ldsm4(a[1][0], a[1][1], a[1][2], a[1][3], aBase2 + 4352 + 64 * kc + 32 * ss);
#pragma unroll
                for (int tp = 0; tp < 6; tp++) {
                    uint32_t b0 = ss ? b2c[tp].z : b2c[tp].x;
                    uint32_t b1 = ss ? b2c[tp].w : b2c[tp].y;
#pragma unroll
                    for (int mf = 0; mf < 2; mf++)
                        mma16(yacc[mf][tp], a[mf][0], a[mf][1], a[mf][2], a[mf][3], b0, b1);
                }
            }
        }
    }

#pragma unroll
    for (int mf = 0; mf < 2; mf++) {
        int r0 = 32 * wm + 16 * mf + g;
#pragma unroll
        for (int t = 0; t < 6; t++) {
            int col = 48 * wn + 8 * t + 2 * q;
            float b0v = __ldg(fc2b + col), b1v = __ldg(fc2b + col + 1);
            {
                size_t base = (t0 + r0) * Cc + col;
                float2 xv = *(const float2*)(g_x2 + base);
                float2 r; r.x = xv.x + yacc[mf][t].x + b0v; r.y = xv.y + yacc[mf][t].y + b1v;
                *(float2*)(out + base) = r;
            }
            {
                size_t base = (t0 + r0 + 8) * Cc + col;
                float2 xv = *(const float2*)(g_x2 + base);
                float2 r; r.x = xv.x + yacc[mf][t].z + b0v; r.y = xv.y + yacc[mf][t].w + b1v;
                *(float2*)(out + base) = r;
            }
        }
    }
}

__global__ __launch_bounds__(256, 2) void swin_fused_kernel(
    const float* __restrict__ x,
    const float* __restrict__ qkv_b, const float* __restrict__ proj_b,
    const float* __restrict__ n1w, const float* __restrict__ n1b,
    const float* __restrict__ n2w, const float* __restrict__ n2b,
    const float* __restrict__ fc1b, const float* __restrict__ fc2b,
    float* __restrict__ out)
{
    extern __shared__ __half smh[];
    const int bid = blockIdx.x;
    if (bid < ATTN_BLOCKS) {
        attn_body(smh, bid, x, qkv_b, proj_b, n1w, n1b);
    } else {
        mlp_body(smh, bid - ATTN_BLOCKS, n2w, n2b, fc1b, fc2b, out);
    }
}

// ---------------------------------------------------------------------------
extern "C" void kernel_launch(void* const* d_in, const int* in_sizes, int n_in,
                              void* d_out, int out_size)
{
    const float* x      = (const float*)d_in[0];
    const float* mask   = (const float*)d_in[1];
    const float* rel    = (const float*)d_in[2];
    const float* qkv_w  = (const float*)d_in[3];
    const float* qkv_b  = (const float*)d_in[4];
    const float* proj_w = (const float*)d_in[5];
    const float* proj_b = (const float*)d_in[6];
    const float* n1w    = (const float*)d_in[7];
    const float* n1b    = (const float*)d_in[8];
    const float* n2w    = (const float*)d_in[9];
    const float* n2b    = (const float*)d_in[10];
    const float* fc1w   = (const float*)d_in[11];
    const float* fc1b   = (const float*)d_in[12];
    const float* fc2w   = (const float*)d_in[13];
    const float* fc2b   = (const float*)d_in[14];
    float* out = (float*)d_out;

    cudaFuncSetAttribute(swin_fused_kernel, cudaFuncAttributeMaxDynamicSharedMemorySize,
                         FUSED_SM_BYTES);

    convert_w<<<1184, 256>>>(qkv_w, proj_w, fc1w, fc2w, mask, rel);
    swin_fused_kernel<<<ATTN_BLOCKS + MLP_BLOCKS, 256, FUSED_SM_BYTES>>>(
        x, qkv_b, proj_b, n1w, n1b, n2w, n2b, fc1b, fc2b, out);
}